// round 2
// baseline (speedup 1.0000x reference)
#include <cuda_runtime.h>
#include <math.h>

#define S_    1024
#define H_    1024
#define NH_   16
#define KVH_  4
#define HD_   64
#define REP_  4
#define E_    64
#define TOPK_ 8
#define ID_   1408
#define CAP_  256
#define EPS_  1e-6f

// ---------------- scratch (device globals; no allocations allowed) ----------
__device__ float g_xn1 [S_ * H_];
__device__ float g_qbuf[S_ * NH_ * HD_];
__device__ float g_kbuf[S_ * KVH_ * HD_];
__device__ float g_vbuf[S_ * KVH_ * HD_];
__device__ float g_qr  [NH_ * S_ * HD_];
__device__ float g_kr  [KVH_ * S_ * HD_];
__device__ float g_vr  [KVH_ * S_ * HD_];
__device__ float g_sc  [(long)NH_ * S_ * S_];     // 64 MB scores/probs
__device__ float g_aoh [NH_ * S_ * HD_];
__device__ float g_ao  [S_ * H_];
__device__ float g_hres[S_ * H_];
__device__ float g_xn2 [S_ * H_];
__device__ float g_logits[S_ * E_];
__device__ int   g_topi[S_ * TOPK_];
__device__ float g_coef[S_ * TOPK_];
__device__ int   g_pos [S_ * TOPK_];
__device__ float g_buf [(long)E_ * CAP_ * H_];    // 64 MB
__device__ float g_gg  [(long)E_ * CAP_ * ID_];   // 92 MB
__device__ float g_uu  [(long)E_ * CAP_ * ID_];   // 92 MB
__device__ float g_yy  [(long)E_ * CAP_ * H_];    // 64 MB
__device__ float g_sg  [S_ * ID_];
__device__ float g_su  [S_ * ID_];
__device__ float g_shb [S_ * H_];

// ---------------- reductions ----------------
__device__ __forceinline__ float warpSum(float v) {
    #pragma unroll
    for (int o = 16; o; o >>= 1) v += __shfl_xor_sync(0xffffffffu, v, o);
    return v;
}
__device__ __forceinline__ float warpMax(float v) {
    #pragma unroll
    for (int o = 16; o; o >>= 1) v = fmaxf(v, __shfl_xor_sync(0xffffffffu, v, o));
    return v;
}
__device__ float blockSum(float v) {
    __shared__ float sh[32];
    __shared__ float tot;
    int lane = threadIdx.x & 31, wid = threadIdx.x >> 5;
    v = warpSum(v);
    if (lane == 0) sh[wid] = v;
    __syncthreads();
    int nw = (blockDim.x + 31) >> 5;
    float w = (threadIdx.x < nw) ? sh[threadIdx.x] : 0.f;
    if (wid == 0) {
        w = warpSum(w);
        if (lane == 0) tot = w;
    }
    __syncthreads();
    float r = tot;
    __syncthreads();
    return r;
}
__device__ float blockMax(float v) {
    __shared__ float sh[32];
    __shared__ float tot;
    int lane = threadIdx.x & 31, wid = threadIdx.x >> 5;
    v = warpMax(v);
    if (lane == 0) sh[wid] = v;
    __syncthreads();
    int nw = (blockDim.x + 31) >> 5;
    float w = (threadIdx.x < nw) ? sh[threadIdx.x] : -1e30f;
    if (wid == 0) {
        w = warpMax(w);
        if (lane == 0) tot = w;
    }
    __syncthreads();
    float r = tot;
    __syncthreads();
    return r;
}

// ---------------- generic tiled SGEMM (batched, optional B-transpose) -------
template<int BM, int BN, int BK, int TM, int TN, bool TB>
__global__ void sgemm_k(const float* __restrict__ A, const float* __restrict__ B,
                        float* __restrict__ C, int M, int N, int K,
                        long sA, long sB, long sC, int bDiv)
{
    const int tid = threadIdx.x;
    const int bz  = blockIdx.z;
    A += (long)bz * sA;
    B += (long)(bz / bDiv) * sB;
    C += (long)bz * sC;
    const int row0 = blockIdx.y * BM;
    const int col0 = blockIdx.x * BN;

    __shared__ float As[BK][BM + 4];
    __shared__ float Bs[BK][BN + 4];

    float acc[TM][TN];
    #pragma unroll
    for (int i = 0; i < TM; i++)
        #pragma unroll
        for (int j = 0; j < TN; j++) acc[i][j] = 0.f;

    const int tRow = (tid / (BN / TN)) * TM;
    const int tCol = (tid % (BN / TN)) * TN;

    const int aRow = tid / (BK / 4);
    const int aK   = (tid % (BK / 4)) * 4;

    int bR, bC;
    if (TB) { bR = tid / (BK / 4); bC = (tid % (BK / 4)) * 4; }   // bR = n, bC = k
    else    { bR = tid / (BN / 4); bC = (tid % (BN / 4)) * 4; }   // bR = k, bC = n

    for (int k0 = 0; k0 < K; k0 += BK) {
        // ---- A tile ----
        {
            int gr = row0 + aRow;
            int gk = k0 + aK;
            float4 v = make_float4(0.f, 0.f, 0.f, 0.f);
            if (gr < M) {
                if (gk + 3 < K) v = *reinterpret_cast<const float4*>(A + (long)gr * K + gk);
                else {
                    float* pv = (float*)&v;
                    for (int j = 0; j < 4; j++) if (gk + j < K) pv[j] = A[(long)gr * K + gk + j];
                }
            }
            As[aK + 0][aRow] = v.x; As[aK + 1][aRow] = v.y;
            As[aK + 2][aRow] = v.z; As[aK + 3][aRow] = v.w;
        }
        // ---- B tile ----
        if (TB) {
            int gn = col0 + bR;
            int gk = k0 + bC;
            float4 v = make_float4(0.f, 0.f, 0.f, 0.f);
            if (gn < N) {
                if (gk + 3 < K) v = *reinterpret_cast<const float4*>(B + (long)gn * K + gk);
                else {
                    float* pv = (float*)&v;
                    for (int j = 0; j < 4; j++) if (gk + j < K) pv[j] = B[(long)gn * K + gk + j];
                }
            }
            Bs[bC + 0][bR] = v.x; Bs[bC + 1][bR] = v.y;
            Bs[bC + 2][bR] = v.z; Bs[bC + 3][bR] = v.w;
        } else {
            int gk = k0 + bR;
            int gn = col0 + bC;
            float4 v = make_float4(0.f, 0.f, 0.f, 0.f);
            if (gk < K) {
                if (gn + 3 < N) v = *reinterpret_cast<const float4*>(B + (long)gk * N + gn);
                else {
                    float* pv = (float*)&v;
                    for (int j = 0; j < 4; j++) if (gn + j < N) pv[j] = B[(long)gk * N + gn + j];
                }
            }
            *reinterpret_cast<float4*>(&Bs[bR][bC]) = v;
        }
        __syncthreads();
        #pragma unroll
        for (int k = 0; k < BK; k++) {
            float rA[TM], rB[TN];
            #pragma unroll
            for (int m = 0; m < TM; m++) rA[m] = As[k][tRow + m];
            #pragma unroll
            for (int n = 0; n < TN; n++) rB[n] = Bs[k][tCol + n];
            #pragma unroll
            for (int m = 0; m < TM; m++)
                #pragma unroll
                for (int n = 0; n < TN; n++) acc[m][n] += rA[m] * rB[n];
        }
        __syncthreads();
    }
    #pragma unroll
    for (int m = 0; m < TM; m++) {
        int gr = row0 + tRow + m;
        if (gr >= M) continue;
        #pragma unroll
        for (int n = 0; n < TN; n++) {
            int gc = col0 + tCol + n;
            if (gc < N) C[(long)gr * N + gc] = acc[m][n];
        }
    }
}

// ---------------- elementwise / small kernels ----------------
__global__ void rmsnorm_k(const float* __restrict__ x, const float* __restrict__ w,
                          float* __restrict__ y)
{
    int t = blockIdx.x;
    const float* xr = x + (long)t * H_;
    float s = 0.f;
    for (int i = threadIdx.x; i < H_; i += blockDim.x) { float v = xr[i]; s += v * v; }
    s = blockSum(s);
    float inv = rsqrtf(s / (float)H_ + EPS_);
    for (int i = threadIdx.x; i < H_; i += blockDim.x)
        y[(long)t * H_ + i] = xr[i] * inv * w[i];
}

// src (S, nh*HD) row-major -> dst (nh, S, HD) with RoPE applied
__global__ void rope_k(const float* __restrict__ src, float* __restrict__ dst, int nh)
{
    int idx = blockIdx.x * blockDim.x + threadIdx.x;
    int total = nh * S_ * HD_;
    if (idx >= total) return;
    int d = idx % HD_;
    int s = (idx / HD_) % S_;
    int h = idx / (HD_ * S_);
    const float* p = src + (long)s * (nh * HD_) + h * HD_;
    float v  = p[d];
    float pr = (d < HD_ / 2) ? -p[d + HD_ / 2] : p[d - HD_ / 2];
    int i = d & (HD_ / 2 - 1);
    float inv = expf(-(float)i * (9.210340371976184f / (HD_ / 2)));  // 10000^(-i/32)
    float ang = (float)s * inv;
    float sn, cs;
    sincosf(ang, &sn, &cs);
    dst[((long)h * S_ + s) * HD_ + d] = v * cs + pr * sn;
}

// src (S, nh*HD) -> dst (nh, S, HD) (no rope, for V)
__global__ void transpose_heads_k(const float* __restrict__ src, float* __restrict__ dst, int nh)
{
    int idx = blockIdx.x * blockDim.x + threadIdx.x;
    int total = nh * S_ * HD_;
    if (idx >= total) return;
    int d = idx % HD_;
    int s = (idx / HD_) % S_;
    int h = idx / (HD_ * S_);
    dst[((long)h * S_ + s) * HD_ + d] = src[(long)s * nh * HD_ + h * HD_ + d];
}

// dst (S, nh*HD) <- src (nh, S, HD)
__global__ void merge_heads_k(const float* __restrict__ src, float* __restrict__ dst)
{
    int idx = blockIdx.x * blockDim.x + threadIdx.x;
    int total = NH_ * S_ * HD_;
    if (idx >= total) return;
    int d = idx % HD_;
    int s = (idx / HD_) % S_;
    int h = idx / (HD_ * S_);
    dst[(long)s * H_ + h * HD_ + d] = src[((long)h * S_ + s) * HD_ + d];
}

__global__ void softmax_k(float* __restrict__ sc, const float* __restrict__ mask)
{
    int r = blockIdx.x, h = blockIdx.y;
    float* row = sc + ((long)h * S_ + r) * S_;
    const float* mr = mask + (long)r * S_;
    float mx = -1e30f;
    for (int j = threadIdx.x; j < S_; j += blockDim.x) {
        float v = row[j] * 0.125f + mr[j];  // 1/sqrt(64)
        row[j] = v;
        mx = fmaxf(mx, v);
    }
    mx = blockMax(mx);
    float sum = 0.f;
    for (int j = threadIdx.x; j < S_; j += blockDim.x) {
        float e = expf(row[j] - mx);
        row[j] = e;
        sum += e;
    }
    sum = blockSum(sum);
    float inv = 1.f / sum;
    for (int j = threadIdx.x; j < S_; j += blockDim.x) row[j] *= inv;
}

__global__ void add_k(const float* __restrict__ a, const float* __restrict__ b,
                      float* __restrict__ c, long n)
{
    long i = (long)blockIdx.x * blockDim.x + threadIdx.x;
    if (i < n) c[i] = a[i] + b[i];
}

__global__ void zero_k(float* __restrict__ p, long n4)
{
    long i = (long)blockIdx.x * blockDim.x + threadIdx.x;
    if (i < n4) reinterpret_cast<float4*>(p)[i] = make_float4(0.f, 0.f, 0.f, 0.f);
}

__global__ void topk_k(const float* __restrict__ logits, int* __restrict__ topi,
                       float* __restrict__ coef)
{
    int t = blockIdx.x * blockDim.x + threadIdx.x;
    if (t >= S_) return;
    const float* lr = logits + (long)t * E_;
    unsigned long long sel = 0ull;
    float tv[TOPK_];
    int   ti[TOPK_];
    for (int k = 0; k < TOPK_; k++) {
        float best = -1e30f; int bi = 0;
        for (int e = 0; e < E_; e++) {
            if ((sel >> e) & 1ull) continue;
            float v = lr[e];
            if (v > best) { best = v; bi = e; }
        }
        sel |= 1ull << bi;
        tv[k] = best; ti[k] = bi;
    }
    float mx = tv[0];
    float ex[TOPK_]; float sum = 0.f;
    for (int k = 0; k < TOPK_; k++) { ex[k] = expf(tv[k] - mx); sum += ex[k]; }
    float inv = 1.f / sum;
    for (int k = 0; k < TOPK_; k++) { topi[t * TOPK_ + k] = ti[k]; coef[t * TOPK_ + k] = ex[k] * inv; }
}

// per-expert occurrence-order position assignment (matches cumsum-of-one-hot)
__global__ void assign_k(const int* __restrict__ topi, int* __restrict__ pos)
{
    const int e = blockIdx.x;           // expert
    const int NTOT = S_ * TOPK_;        // 8192
    __shared__ int sdata[256];
    int base = 0;
    for (int chunk = 0; chunk < NTOT; chunk += 256) {
        int i = chunk + threadIdx.x;
        int p = (topi[i] == e) ? 1 : 0;
        sdata[threadIdx.x] = p;
        __syncthreads();
        #pragma unroll
        for (int off = 1; off < 256; off <<= 1) {
            int v = (threadIdx.x >= off) ? sdata[threadIdx.x - off] : 0;
            __syncthreads();
            sdata[threadIdx.x] += v;
            __syncthreads();
        }
        if (p) pos[i] = base + sdata[threadIdx.x] - 1;
        base += sdata[255];
        __syncthreads();
    }
}

__global__ void scatter_k(const float* __restrict__ xn2, const int* __restrict__ topi,
                          const int* __restrict__ pos, float* __restrict__ buf)
{
    int i = blockIdx.x;                 // 0..8191
    int p = pos[i];
    if (p >= CAP_) return;
    int e = topi[i];
    int t = i >> 3;
    const float4* src = reinterpret_cast<const float4*>(xn2 + (long)t * H_);
    float4* dst = reinterpret_cast<float4*>(buf + ((long)e * CAP_ + p) * H_);
    dst[threadIdx.x] = src[threadIdx.x];   // 256 threads x float4 = 1024 floats
}

__global__ void act_k(float* __restrict__ g, const float* __restrict__ u, long n)
{
    long i = (long)blockIdx.x * blockDim.x + threadIdx.x;
    if (i < n) {
        float x = g[i];
        g[i] = (x / (1.f + expf(-x))) * u[i];
    }
}

__global__ void final_k(const float* __restrict__ hres, const float* __restrict__ shb,
                        const float* __restrict__ y, const int* __restrict__ topi,
                        const int* __restrict__ pos, const float* __restrict__ coef,
                        float* __restrict__ out)
{
    int t = blockIdx.x;
    int j = threadIdx.x;                // 256 float4 lanes per token
    float4 a = reinterpret_cast<const float4*>(hres)[(long)t * 256 + j];
    float4 b = reinterpret_cast<const float4*>(shb)[(long)t * 256 + j];
    a.x += b.x; a.y += b.y; a.z += b.z; a.w += b.w;
    #pragma unroll
    for (int k = 0; k < TOPK_; k++) {
        int idx = t * TOPK_ + k;
        int p = pos[idx];
        if (p < CAP_) {
            int e = topi[idx];
            float c = coef[idx];
            float4 v = reinterpret_cast<const float4*>(y)[((long)e * CAP_ + p) * 256 + j];
            a.x += c * v.x; a.y += c * v.y; a.z += c * v.z; a.w += c * v.w;
        }
    }
    reinterpret_cast<float4*>(out)[(long)t * 256 + j] = a;
}

// ---------------- host-side launchers ----------------
static void gemmA(const float* A, const float* B, float* C, int M, int N, int K,
                  int batch, long sA, long sB, long sC, int bDiv, cudaStream_t st)
{
    dim3 grid((N + 127) / 128, (M + 127) / 128, batch);
    sgemm_k<128, 128, 8, 8, 8, false><<<grid, 256, 0, st>>>(A, B, C, M, N, K, sA, sB, sC, bDiv);
}
static void gemmB_nn(const float* A, const float* B, float* C, int M, int N, int K,
                     int batch, long sA, long sB, long sC, int bDiv, cudaStream_t st)
{
    dim3 grid((N + 63) / 64, (M + 63) / 64, batch);
    sgemm_k<64, 64, 16, 4, 4, false><<<grid, 256, 0, st>>>(A, B, C, M, N, K, sA, sB, sC, bDiv);
}
static void gemmB_nt(const float* A, const float* B, float* C, int M, int N, int K,
                     int batch, long sA, long sB, long sC, int bDiv, cudaStream_t st)
{
    dim3 grid((N + 63) / 64, (M + 63) / 64, batch);
    sgemm_k<64, 64, 16, 4, 4, true><<<grid, 256, 0, st>>>(A, B, C, M, N, K, sA, sB, sC, bDiv);
}

extern "C" void kernel_launch(void* const* d_in, const int* in_sizes, int n_in,
                              void* d_out, int out_size)
{
    (void)in_sizes; (void)n_in; (void)out_size;
    cudaStream_t st = 0;

    const float* x     = (const float*)d_in[0];   // hidden_states (1,1024,1024)
    const float* mask  = (const float*)d_in[1];   // (1,1,1024,1024)
    const float* wln1  = (const float*)d_in[2];
    const float* wln2  = (const float*)d_in[3];
    const float* Wq    = (const float*)d_in[4];
    const float* Wk    = (const float*)d_in[5];
    const float* Wv    = (const float*)d_in[6];
    const float* Wo    = (const float*)d_in[7];
    const float* Wgate = (const float*)d_in[8];
    const float* Weg   = (const float*)d_in[9];
    const float* Weu   = (const float*)d_in[10];
    const float* Wed   = (const float*)d_in[11];
    const float* Wsg   = (const float*)d_in[12];
    const float* Wsu   = (const float*)d_in[13];
    const float* Wsd   = (const float*)d_in[14];
    float* out = (float*)d_out;

    void *p;
    #define GET(sym, var) cudaGetSymbolAddress(&p, sym); float* var = (float*)p;
    #define GETI(sym, var) cudaGetSymbolAddress(&p, sym); int* var = (int*)p;
    GET(g_xn1, xn1)  GET(g_qbuf, qbuf) GET(g_kbuf, kbuf) GET(g_vbuf, vbuf)
    GET(g_qr, qr)    GET(g_kr, kr)     GET(g_vr, vr)     GET(g_sc, sc)
    GET(g_aoh, aoh)  GET(g_ao, ao)     GET(g_hres, hres) GET(g_xn2, xn2)
    GET(g_logits, logits) GET(g_coef, coef)
    GET(g_buf, buf)  GET(g_gg, gg)     GET(g_uu, uu)     GET(g_yy, yy)
    GET(g_sg, sg)    GET(g_su, su)     GET(g_shb, shb)
    GETI(g_topi, topi) GETI(g_pos, pos)
    #undef GET
    #undef GETI

    // ===== attention =====
    rmsnorm_k<<<S_, 256, 0, st>>>(x, wln1, xn1);

    gemmA(xn1, Wq, qbuf, S_, NH_ * HD_, H_, 1, 0, 0, 0, 1, st);
    gemmA(xn1, Wk, kbuf, S_, KVH_ * HD_, H_, 1, 0, 0, 0, 1, st);
    gemmA(xn1, Wv, vbuf, S_, KVH_ * HD_, H_, 1, 0, 0, 0, 1, st);

    {
        int totq = NH_ * S_ * HD_, totk = KVH_ * S_ * HD_;
        rope_k<<<(totq + 255) / 256, 256, 0, st>>>(qbuf, qr, NH_);
        rope_k<<<(totk + 255) / 256, 256, 0, st>>>(kbuf, kr, KVH_);
        transpose_heads_k<<<(totk + 255) / 256, 256, 0, st>>>(vbuf, vr, KVH_);
    }

    // scores[h] = qr[h] @ kr[h/4]^T    (16 x 1024x1024, K=64)
    gemmB_nt(qr, kr, sc, S_, S_, HD_, NH_,
             (long)S_ * HD_, (long)S_ * HD_, (long)S_ * S_, REP_, st);

    softmax_k<<<dim3(S_, NH_), 256, 0, st>>>(sc, mask);

    // aoh[h] = probs[h] @ vr[h/4]      (16 x 1024x64, K=1024)
    gemmB_nn(sc, vr, aoh, S_, HD_, S_, NH_,
             (long)S_ * S_, (long)S_ * HD_, (long)S_ * HD_, REP_, st);

    merge_heads_k<<<(NH_ * S_ * HD_ + 255) / 256, 256, 0, st>>>(aoh, ao);

    gemmA(ao, Wo, xn1 /*reuse as attn_proj*/, S_, H_, H_, 1, 0, 0, 0, 1, st);
    add_k<<<(S_ * H_ + 255) / 256, 256, 0, st>>>(x, xn1, hres, (long)S_ * H_);

    // ===== MoE =====
    rmsnorm_k<<<S_, 256, 0, st>>>(hres, wln2, xn2);

    gemmB_nn(xn2, Wgate, logits, S_, E_, H_, 1, 0, 0, 0, 1, st);
    topk_k<<<(S_ + 255) / 256, 256, 0, st>>>(logits, topi, coef);
    assign_k<<<E_, 256, 0, st>>>(topi, pos);

    zero_k<<<(int)(((long)E_ * CAP_ * H_ / 4 + 255) / 256), 256, 0, st>>>(buf, (long)E_ * CAP_ * H_ / 4);
    scatter_k<<<S_ * TOPK_, 256, 0, st>>>(xn2, topi, pos, buf);

    // expert up/gate: 64 x (256x1408, K=1024)
    gemmA(buf, Weg, gg, CAP_, ID_, H_, E_,
          (long)CAP_ * H_, (long)H_ * ID_, (long)CAP_ * ID_, 1, st);
    gemmA(buf, Weu, uu, CAP_, ID_, H_, E_,
          (long)CAP_ * H_, (long)H_ * ID_, (long)CAP_ * ID_, 1, st);

    {
        long n = (long)E_ * CAP_ * ID_;
        act_k<<<(int)((n + 255) / 256), 256, 0, st>>>(gg, uu, n);
    }

    // expert down: 64 x (256x1024, K=1408)
    gemmA(gg, Wed, yy, CAP_, H_, ID_, E_,
          (long)CAP_ * ID_, (long)ID_ * H_, (long)CAP_ * H_, 1, st);

    // shared expert
    gemmA(xn2, Wsg, sg, S_, ID_, H_, 1, 0, 0, 0, 1, st);
    gemmA(xn2, Wsu, su, S_, ID_, H_, 1, 0, 0, 0, 1, st);
    {
        long n = (long)S_ * ID_;
        act_k<<<(int)((n + 255) / 256), 256, 0, st>>>(sg, su, n);
    }
    gemmA(sg, Wsd, shb, S_, H_, ID_, 1, 0, 0, 0, 1, st);

    // gather + residuals
    final_k<<<S_, 256, 0, st>>>(hres, shb, yy, topi, pos, coef, out);
}

// round 4
// speedup vs baseline: 3.4857x; 3.4857x over previous
#include <cuda_runtime.h>
#include <math.h>
#include <stdint.h>

#define S_    1024
#define H_    1024
#define NH_   16
#define KVH_  4
#define HD_   64
#define REP_  4
#define E_    64
#define TOPK_ 8
#define ID_   1408
#define CAP_  256
#define EPS_  1e-6f

__device__ float g_xn1 [S_ * H_];
__device__ float g_qbuf[S_ * NH_ * HD_];
__device__ float g_kbuf[S_ * KVH_ * HD_];
__device__ float g_vbuf[S_ * KVH_ * HD_];
__device__ float g_qr  [NH_ * S_ * HD_];
__device__ float g_kr  [KVH_ * S_ * HD_];
__device__ float g_vr  [KVH_ * S_ * HD_];
__device__ float g_sc  [(long)NH_ * S_ * S_];
__device__ float g_aoh [NH_ * S_ * HD_];
__device__ float g_ao  [S_ * H_];
__device__ float g_hres[S_ * H_];
__device__ float g_xn2 [S_ * H_];
__device__ float g_logits[S_ * E_];
__device__ int   g_topi[S_ * TOPK_];
__device__ float g_coef[S_ * TOPK_];
__device__ int   g_pos [S_ * TOPK_];
__device__ float g_buf [(long)E_ * CAP_ * H_];
__device__ float g_gg  [(long)E_ * CAP_ * ID_];
__device__ float g_uu  [(long)E_ * CAP_ * ID_];
__device__ float g_yy  [(long)E_ * CAP_ * H_];
__device__ float g_sg  [S_ * ID_];
__device__ float g_su  [S_ * ID_];
__device__ float g_shb [S_ * H_];

// ---------- helpers ----------
__device__ __forceinline__ uint32_t smem_u32(const void* p) {
    uint32_t a;
    asm("{ .reg .u64 t; cvta.to.shared.u64 t, %1; cvt.u32.u64 %0, t; }" : "=r"(a) : "l"(p));
    return a;
}
__device__ __forceinline__ float rtf(float x) {
    uint32_t r;
    asm("cvt.rna.tf32.f32 %0, %1;" : "=r"(r) : "f"(x));
    return __uint_as_float(r);
}
__device__ __forceinline__ uint32_t rtf_u(float x) {
    uint32_t r;
    asm("cvt.rna.tf32.f32 %0, %1;" : "=r"(r) : "f"(x));
    return r;
}
__device__ __forceinline__ void cp16(uint32_t dst, const void* src) {
    asm volatile("cp.async.cg.shared.global [%0], [%1], 16;" :: "r"(dst), "l"(src));
}
__device__ __forceinline__ void cp_commit() { asm volatile("cp.async.commit_group;" ::: "memory"); }
__device__ __forceinline__ void cp_wait(int n) {
    if (n <= 0)      asm volatile("cp.async.wait_group 0;" ::: "memory");
    else if (n == 1) asm volatile("cp.async.wait_group 1;" ::: "memory");
    else             asm volatile("cp.async.wait_group 2;" ::: "memory");
}
__device__ __forceinline__ void mma1688(float* d, const uint32_t* a, const uint32_t* b) {
    asm volatile("mma.sync.aligned.m16n8k8.row.col.f32.tf32.tf32.f32 "
        "{%0,%1,%2,%3}, {%4,%5,%6,%7}, {%8,%9}, {%0,%1,%2,%3};"
        : "+f"(d[0]), "+f"(d[1]), "+f"(d[2]), "+f"(d[3])
        : "r"(a[0]), "r"(a[1]), "r"(a[2]), "r"(a[3]), "r"(b[0]), "r"(b[1]));
}

// ---------- tf32 mma.sync GEMM ----------
// C[M,N] = A[M,K] @ B ; batched by blockIdx.z (strides sA,sB,sC; B index z/bDiv).
// BKMAJ=true : B gmem [K,N] row-major.  BKMAJ=false: B gmem [N,K] row-major (B^T).
// M mult of 128, N mult of BN, K mult of 32. All leading dims mult of 4.
template<int BN, bool BKMAJ, bool CVTA, bool CVTB>
__global__ void __launch_bounds__(256, 1) mmagemm_k(
    const float* __restrict__ A, const float* __restrict__ B, float* __restrict__ C,
    int K, int lda, int ldb, int ldc, long sA, long sB, long sC, int bDiv)
{
    constexpr int BM = 128, BK = 32;
    constexpr int LDA  = BK + 4;                       // 36 floats, 144B rows (16B-aligned)
    constexpr int LDBK = BN + 4;                       // k-major B row stride
    constexpr int A_FL = BM * LDA;                     // 4608 floats
    constexpr int B_FL = BKMAJ ? BK * LDBK : BN * LDA;
    constexpr int STG_FL = A_FL + B_FL;
    constexpr int WGN = BN / 32, WGM = 8 / WGN;        // warp grid
    constexpr int WM  = BM / WGM, MT = WM / 16, NT = 4;

    extern __shared__ float sm[];
    const int tid = threadIdx.x, wid = tid >> 5, lane = tid & 31;
    const int qrw = lane >> 2, qc = lane & 3;
    A += (long)blockIdx.z * sA;
    B += (long)(blockIdx.z / bDiv) * sB;
    C += (long)blockIdx.z * sC;
    const int row0 = blockIdx.y * BM;
    const int col0 = blockIdx.x * BN;
    const int wm0 = (wid / WGN) * WM;
    const int wn0 = (wid % WGN) * 32;
    const int nch = K / BK;

    auto fill = [&](int c) {
        float* As = sm + (c % 3) * STG_FL;
        float* Bs = As + A_FL;
        const int k0 = c * BK;
        const float* Ag = A + (long)row0 * lda + k0;
        #pragma unroll
        for (int i = 0; i < 4; i++) {
            int idx = i * 256 + tid;
            int r = idx >> 3, sg = idx & 7;
            cp16(smem_u32(As + r * LDA + sg * 4), Ag + (long)r * lda + sg * 4);
        }
        if (BKMAJ) {
            const float* Bg = B + (long)k0 * ldb + col0;
            #pragma unroll
            for (int i = 0; i < BN / 32; i++) {
                int idx = i * 256 + tid;
                int r = idx / (BN / 4), sg = idx % (BN / 4);
                cp16(smem_u32(Bs + r * LDBK + sg * 4), Bg + (long)r * ldb + sg * 4);
            }
        } else {
            const float* Bg = B + (long)col0 * ldb + k0;
            #pragma unroll
            for (int i = 0; i < BN / 32; i++) {
                int idx = i * 256 + tid;
                int r = idx >> 3, sg = idx & 7;
                cp16(smem_u32(Bs + r * LDA + sg * 4), Bg + (long)r * ldb + sg * 4);
            }
        }
        cp_commit();
    };

    float acc[MT][NT][4];
    #pragma unroll
    for (int m = 0; m < MT; m++)
        #pragma unroll
        for (int n = 0; n < NT; n++)
            #pragma unroll
            for (int j = 0; j < 4; j++) acc[m][n][j] = 0.f;

    const int F0 = (nch < 2) ? nch : 2;
    for (int c = 0; c < F0; c++) fill(c);
    int g = F0;

    for (int c = 0; c < nch; c++) {
        cp_wait(g - (c + 1));
        __syncthreads();
        if (c + 2 < nch) { fill(c + 2); g++; }

        const float* As = sm + (c % 3) * STG_FL;
        const float* Bs = As + A_FL;
        #pragma unroll
        for (int ks = 0; ks < 4; ks++) {
            const int kk = ks * 8;
            uint32_t af[MT][4], bf[NT][2];
            #pragma unroll
            for (int mt = 0; mt < MT; mt++) {
                const float* ap = As + (wm0 + mt * 16 + qrw) * LDA + kk + qc;
                float a0 = ap[0], a1 = ap[8 * LDA], a2 = ap[4], a3 = ap[8 * LDA + 4];
                af[mt][0] = CVTA ? rtf_u(a0) : __float_as_uint(a0);
                af[mt][1] = CVTA ? rtf_u(a1) : __float_as_uint(a1);
                af[mt][2] = CVTA ? rtf_u(a2) : __float_as_uint(a2);
                af[mt][3] = CVTA ? rtf_u(a3) : __float_as_uint(a3);
            }
            #pragma unroll
            for (int nt = 0; nt < NT; nt++) {
                float b0, b1;
                if (BKMAJ) {
                    const float* bp = Bs + (kk + qc) * LDBK + wn0 + nt * 8 + qrw;
                    b0 = bp[0]; b1 = bp[4 * LDBK];
                } else {
                    const float* bp = Bs + (wn0 + nt * 8 + qrw) * LDA + kk + qc;
                    b0 = bp[0]; b1 = bp[4];
                }
                bf[nt][0] = CVTB ? rtf_u(b0) : __float_as_uint(b0);
                bf[nt][1] = CVTB ? rtf_u(b1) : __float_as_uint(b1);
            }
            #pragma unroll
            for (int mt = 0; mt < MT; mt++)
                #pragma unroll
                for (int nt = 0; nt < NT; nt++)
                    mma1688(acc[mt][nt], af[mt], bf[nt]);
        }
    }

    #pragma unroll
    for (int mt = 0; mt < MT; mt++) {
        const int r = row0 + wm0 + mt * 16 + qrw;
        #pragma unroll
        for (int nt = 0; nt < NT; nt++) {
            const int cc = col0 + wn0 + nt * 8 + qc * 2;
            *reinterpret_cast<float2*>(C + (long)r * ldc + cc) =
                make_float2(acc[mt][nt][0], acc[mt][nt][1]);
            *reinterpret_cast<float2*>(C + (long)(r + 8) * ldc + cc) =
                make_float2(acc[mt][nt][2], acc[mt][nt][3]);
        }
    }
}

// ---------- exact fp32 gemm for gate logits ----------
__global__ void sgemm64_k(const float* __restrict__ A, const float* __restrict__ B,
                          float* __restrict__ C, int M, int N, int K)
{
    const int tid = threadIdx.x;
    const int row0 = blockIdx.y * 64, col0 = blockIdx.x * 64;
    __shared__ float As[16][68];
    __shared__ float Bs[16][68];
    float acc[4][4] = {};
    const int tRow = (tid / 16) * 4, tCol = (tid % 16) * 4;
    const int aRow = tid / 4, aK = (tid % 4) * 4;
    const int bR = tid / 16, bC = (tid % 16) * 4;
    for (int k0 = 0; k0 < K; k0 += 16) {
        {
            int gr = row0 + aRow, gk = k0 + aK;
            float4 v = make_float4(0,0,0,0);
            if (gr < M && gk + 3 < K) v = *reinterpret_cast<const float4*>(A + (long)gr*K + gk);
            As[aK+0][aRow]=v.x; As[aK+1][aRow]=v.y; As[aK+2][aRow]=v.z; As[aK+3][aRow]=v.w;
        }
        {
            int gk = k0 + bR, gn = col0 + bC;
            float4 v = make_float4(0,0,0,0);
            if (gk < K && gn + 3 < N) v = *reinterpret_cast<const float4*>(B + (long)gk*N + gn);
            *reinterpret_cast<float4*>(&Bs[bR][bC]) = v;
        }
        __syncthreads();
        #pragma unroll
        for (int k = 0; k < 16; k++) {
            float rA[4], rB[4];
            #pragma unroll
            for (int m = 0; m < 4; m++) rA[m] = As[k][tRow+m];
            #pragma unroll
            for (int n = 0; n < 4; n++) rB[n] = Bs[k][tCol+n];
            #pragma unroll
            for (int m = 0; m < 4; m++)
                #pragma unroll
                for (int n = 0; n < 4; n++) acc[m][n] += rA[m]*rB[n];
        }
        __syncthreads();
    }
    #pragma unroll
    for (int m = 0; m < 4; m++) {
        int gr = row0 + tRow + m;
        if (gr >= M) continue;
        #pragma unroll
        for (int n = 0; n < 4; n++) {
            int gc = col0 + tCol + n;
            if (gc < N) C[(long)gr*N + gc] = acc[m][n];
        }
    }
}

// ---------- reductions ----------
__device__ __forceinline__ float warpSum(float v) {
    #pragma unroll
    for (int o = 16; o; o >>= 1) v += __shfl_xor_sync(0xffffffffu, v, o);
    return v;
}
__device__ __forceinline__ float warpMax(float v) {
    #pragma unroll
    for (int o = 16; o; o >>= 1) v = fmaxf(v, __shfl_xor_sync(0xffffffffu, v, o));
    return v;
}
__device__ float blockSum(float v) {
    __shared__ float sh[32]; __shared__ float tot;
    int lane = threadIdx.x & 31, wid = threadIdx.x >> 5;
    v = warpSum(v);
    if (lane == 0) sh[wid] = v;
    __syncthreads();
    int nw = (blockDim.x + 31) >> 5;
    float w = (threadIdx.x < nw) ? sh[threadIdx.x] : 0.f;
    if (wid == 0) { w = warpSum(w); if (lane == 0) tot = w; }
    __syncthreads();
    float r = tot; __syncthreads(); return r;
}
__device__ float blockMax(float v) {
    __shared__ float sh[32]; __shared__ float tot;
    int lane = threadIdx.x & 31, wid = threadIdx.x >> 5;
    v = warpMax(v);
    if (lane == 0) sh[wid] = v;
    __syncthreads();
    int nw = (blockDim.x + 31) >> 5;
    float w = (threadIdx.x < nw) ? sh[threadIdx.x] : -1e30f;
    if (wid == 0) { w = warpMax(w); if (lane == 0) tot = w; }
    __syncthreads();
    float r = tot; __syncthreads(); return r;
}

// ---------- small kernels ----------
__global__ void rmsnorm_k(const float* __restrict__ x, const float* __restrict__ w,
                          float* __restrict__ y, int rnd)
{
    int t = blockIdx.x;
    const float* xr = x + (long)t * H_;
    float s = 0.f;
    for (int i = threadIdx.x; i < H_; i += blockDim.x) { float v = xr[i]; s += v * v; }
    s = blockSum(s);
    float inv = rsqrtf(s / (float)H_ + EPS_);
    for (int i = threadIdx.x; i < H_; i += blockDim.x) {
        float v = xr[i] * inv * w[i];
        y[(long)t * H_ + i] = rnd ? rtf(v) : v;
    }
}

__global__ void rope_k(const float* __restrict__ src, float* __restrict__ dst, int nh)
{
    int idx = blockIdx.x * blockDim.x + threadIdx.x;
    if (idx >= nh * S_ * HD_) return;
    int d = idx % HD_;
    int s = (idx / HD_) % S_;
    int h = idx / (HD_ * S_);
    const float* p = src + (long)s * (nh * HD_) + h * HD_;
    float v  = p[d];
    float pr = (d < HD_/2) ? -p[d + HD_/2] : p[d - HD_/2];
    int i = d & (HD_/2 - 1);
    float inv = expf(-(float)i * (9.210340371976184f / (HD_/2)));
    float ang = (float)s * inv, sn, cs;
    sincosf(ang, &sn, &cs);
    dst[((long)h * S_ + s) * HD_ + d] = rtf(v * cs + pr * sn);
}

__global__ void transpose_heads_k(const float* __restrict__ src, float* __restrict__ dst, int nh)
{
    int idx = blockIdx.x * blockDim.x + threadIdx.x;
    if (idx >= nh * S_ * HD_) return;
    int d = idx % HD_;
    int s = (idx / HD_) % S_;
    int h = idx / (HD_ * S_);
    dst[((long)h * S_ + s) * HD_ + d] = rtf(src[(long)s * nh * HD_ + h * HD_ + d]);
}

__global__ void merge_heads_k(const float* __restrict__ src, float* __restrict__ dst)
{
    int idx = blockIdx.x * blockDim.x + threadIdx.x;
    if (idx >= NH_ * S_ * HD_) return;
    int d = idx % HD_;
    int s = (idx / HD_) % S_;
    int h = idx / (HD_ * S_);
    dst[(long)s * H_ + h * HD_ + d] = rtf(src[((long)h * S_ + s) * HD_ + d]);
}

__global__ void softmax_k(float* __restrict__ sc, const float* __restrict__ mask)
{
    int r = blockIdx.x, h = blockIdx.y;
    float* row = sc + ((long)h * S_ + r) * S_;
    const float* mr = mask + (long)r * S_;
    float mx = -1e30f;
    for (int j = threadIdx.x; j < S_; j += blockDim.x) {
        float v = row[j] * 0.125f + mr[j];
        row[j] = v;
        mx = fmaxf(mx, v);
    }
    mx = blockMax(mx);
    float sum = 0.f;
    for (int j = threadIdx.x; j < S_; j += blockDim.x) {
        float e = expf(row[j] - mx);
        row[j] = e;
        sum += e;
    }
    sum = blockSum(sum);
    float inv = 1.f / sum;
    for (int j = threadIdx.x; j < S_; j += blockDim.x) row[j] = rtf(row[j] * inv);
}

__global__ void add_k(const float* __restrict__ a, const float* __restrict__ b,
                      float* __restrict__ c, long n)
{
    long i = (long)blockIdx.x * blockDim.x + threadIdx.x;
    if (i < n) c[i] = a[i] + b[i];
}

__global__ void zero_k(float* __restrict__ p, long n4)
{
    long i = (long)blockIdx.x * blockDim.x + threadIdx.x;
    if (i < n4) reinterpret_cast<float4*>(p)[i] = make_float4(0,0,0,0);
}

__global__ void topk_k(const float* __restrict__ logits, int* __restrict__ topi,
                       float* __restrict__ coef)
{
    int t = blockIdx.x * blockDim.x + threadIdx.x;
    if (t >= S_) return;
    const float* lr = logits + (long)t * E_;
    unsigned long long sel = 0ull;
    float tv[TOPK_]; int ti[TOPK_];
    for (int k = 0; k < TOPK_; k++) {
        float best = -1e30f; int bi = 0;
        for (int e = 0; e < E_; e++) {
            if ((sel >> e) & 1ull) continue;
            float v = lr[e];
            if (v > best) { best = v; bi = e; }
        }
        sel |= 1ull << bi;
        tv[k] = best; ti[k] = bi;
    }
    float mx = tv[0], ex[TOPK_], sum = 0.f;
    for (int k = 0; k < TOPK_; k++) { ex[k] = expf(tv[k] - mx); sum += ex[k]; }
    float inv = 1.f / sum;
    for (int k = 0; k < TOPK_; k++) { topi[t*TOPK_+k] = ti[k]; coef[t*TOPK_+k] = ex[k]*inv; }
}

__global__ void assign_k(const int* __restrict__ topi, int* __restrict__ pos)
{
    const int e = blockIdx.x;
    __shared__ int sdata[256];
    int base = 0;
    for (int chunk = 0; chunk < S_ * TOPK_; chunk += 256) {
        int i = chunk + threadIdx.x;
        int p = (topi[i] == e) ? 1 : 0;
        sdata[threadIdx.x] = p;
        __syncthreads();
        #pragma unroll
        for (int off = 1; off < 256; off <<= 1) {
            int v = (threadIdx.x >= off) ? sdata[threadIdx.x - off] : 0;
            __syncthreads();
            sdata[threadIdx.x] += v;
            __syncthreads();
        }
        if (p) pos[i] = base + sdata[threadIdx.x] - 1;
        base += sdata[255];
        __syncthreads();
    }
}

__global__ void scatter_k(const float* __restrict__ xn2, const int* __restrict__ topi,
                          const int* __restrict__ pos, float* __restrict__ buf)
{
    int i = blockIdx.x;
    int p = pos[i];
    if (p >= CAP_) return;
    int e = topi[i];
    int t = i >> 3;
    const float* src = xn2 + (long)t * H_;
    float* dst = buf + ((long)e * CAP_ + p) * H_;
    for (int j = threadIdx.x; j < H_; j += blockDim.x) dst[j] = rtf(src[j]);
}

__global__ void act_k(float* __restrict__ g, const float* __restrict__ u, long n)
{
    long i = (long)blockIdx.x * blockDim.x + threadIdx.x;
    if (i < n) {
        float x = g[i];
        g[i] = rtf((x / (1.f + expf(-x))) * u[i]);
    }
}

__global__ void final_k(const float* __restrict__ hres, const float* __restrict__ shb,
                        const float* __restrict__ y, const int* __restrict__ topi,
                        const int* __restrict__ pos, const float* __restrict__ coef,
                        float* __restrict__ out)
{
    int t = blockIdx.x, j = threadIdx.x;
    float4 a = reinterpret_cast<const float4*>(hres)[(long)t*256 + j];
    float4 b = reinterpret_cast<const float4*>(shb)[(long)t*256 + j];
    a.x += b.x; a.y += b.y; a.z += b.z; a.w += b.w;
    #pragma unroll
    for (int k = 0; k < TOPK_; k++) {
        int idx = t * TOPK_ + k;
        int p = pos[idx];
        if (p < CAP_) {
            float c = coef[idx];
            float4 v = reinterpret_cast<const float4*>(y)[((long)topi[idx]*CAP_ + p)*256 + j];
            a.x += c*v.x; a.y += c*v.y; a.z += c*v.z; a.w += c*v.w;
        }
    }
    reinterpret_cast<float4*>(out)[(long)t*256 + j] = a;
}

// ---------- host-side smem sizes (mirror of kernel constexpr) ----------
static int smemBytes(int BN, bool bkmaj) {
    int A_FL = 128 * 36;
    int B_FL = bkmaj ? 32 * (BN + 4) : BN * 36;
    return 3 * (A_FL + B_FL) * 4;
}

extern "C" void kernel_launch(void* const* d_in, const int* in_sizes, int n_in,
                              void* d_out, int out_size)
{
    (void)in_sizes; (void)n_in; (void)out_size;
    cudaStream_t st = 0;

    const int SM_W   = smemBytes(128, true);    // weight GEMMs (B [K,N])
    const int SM_SCR = smemBytes(128, false);   // scores (B = K^T, [N,K])
    const int SM_PV  = smemBytes(64, true);     // probs@V  (B [K,64])
    cudaFuncSetAttribute(mmagemm_k<128, true,  false, true >, cudaFuncAttributeMaxDynamicSharedMemorySize, SM_W);
    cudaFuncSetAttribute(mmagemm_k<128, true,  true,  true >, cudaFuncAttributeMaxDynamicSharedMemorySize, SM_W);
    cudaFuncSetAttribute(mmagemm_k<128, false, false, false>, cudaFuncAttributeMaxDynamicSharedMemorySize, SM_SCR);
    cudaFuncSetAttribute(mmagemm_k<64,  true,  false, false>, cudaFuncAttributeMaxDynamicSharedMemorySize, SM_PV);

    const float* x     = (const float*)d_in[0];
    const float* mask  = (const float*)d_in[1];
    const float* wln1  = (const float*)d_in[2];
    const float* wln2  = (const float*)d_in[3];
    const float* Wq    = (const float*)d_in[4];
    const float* Wk    = (const float*)d_in[5];
    const float* Wv    = (const float*)d_in[6];
    const float* Wo    = (const float*)d_in[7];
    const float* Wgate = (const float*)d_in[8];
    const float* Weg   = (const float*)d_in[9];
    const float* Weu   = (const float*)d_in[10];
    const float* Wed   = (const float*)d_in[11];
    const float* Wsg   = (const float*)d_in[12];
    const float* Wsu   = (const float*)d_in[13];
    const float* Wsd   = (const float*)d_in[14];
    float* out = (float*)d_out;

    void *p;
    #define GET(sym, var) cudaGetSymbolAddress(&p, sym); float* var = (float*)p;
    #define GETI(sym, var) cudaGetSymbolAddress(&p, sym); int* var = (int*)p;
    GET(g_xn1, xn1)  GET(g_qbuf, qbuf) GET(g_kbuf, kbuf) GET(g_vbuf, vbuf)
    GET(g_qr, qr)    GET(g_kr, kr)     GET(g_vr, vr)     GET(g_sc, sc)
    GET(g_aoh, aoh)  GET(g_ao, ao)     GET(g_hres, hres) GET(g_xn2, xn2)
    GET(g_logits, logits) GET(g_coef, coef)
    GET(g_buf, buf)  GET(g_gg, gg)     GET(g_uu, uu)     GET(g_yy, yy)
    GET(g_sg, sg)    GET(g_su, su)     GET(g_shb, shb)
    GETI(g_topi, topi) GETI(g_pos, pos)
    #undef GET
    #undef GETI

    // weight GEMM: A pre-rounded, B = [K,N] weights (cvt in-register)
    auto gw = [&](const float* A, const float* B, float* C, int M, int N, int K,
                  int lda, int ldb, int ldc, long sA, long sB, long sC, int bDiv, int batch) {
        dim3 grid(N / 128, M / 128, batch);
        mmagemm_k<128, true, false, true><<<grid, 256, SM_W, st>>>(A, B, C, K, lda, ldb, ldc, sA, sB, sC, bDiv);
    };

    // ===== attention =====
    rmsnorm_k<<<S_, 256, 0, st>>>(x, wln1, xn1, 1);

    gw(xn1, Wq, qbuf, S_, H_,       H_, H_, H_,       H_,       0,0,0, 1, 1);
    gw(xn1, Wk, kbuf, S_, KVH_*HD_, H_, H_, KVH_*HD_, KVH_*HD_, 0,0,0, 1, 1);
    gw(xn1, Wv, vbuf, S_, KVH_*HD_, H_, H_, KVH_*HD_, KVH_*HD_, 0,0,0, 1, 1);

    rope_k<<<(NH_*S_*HD_ + 255)/256, 256, 0, st>>>(qbuf, qr, NH_);
    rope_k<<<(KVH_*S_*HD_ + 255)/256, 256, 0, st>>>(kbuf, kr, KVH_);
    transpose_heads_k<<<(KVH_*S_*HD_ + 255)/256, 256, 0, st>>>(vbuf, vr, KVH_);

    // scores[h] = qr[h] @ kr[h/4]^T : B = kr ([N,K] row-major)
    {
        dim3 grid(S_/128, S_/128, NH_);
        mmagemm_k<128, false, false, false><<<grid, 256, SM_SCR, st>>>(
            qr, kr, sc, HD_, HD_, HD_, S_,
            (long)S_*HD_, (long)S_*HD_, (long)S_*S_, REP_);
    }

    softmax_k<<<dim3(S_, NH_), 256, 0, st>>>(sc, mask);

    // aoh[h] = probs[h] @ vr[h/4] : B = vr ([K,N]=[S,HD] row-major), N=64
    {
        dim3 grid(1, S_/128, NH_);
        mmagemm_k<64, true, false, false><<<grid, 256, SM_PV, st>>>(
            sc, vr, aoh, S_, S_, HD_, HD_,
            (long)S_*S_, (long)S_*HD_, (long)S_*HD_, REP_);
    }

    merge_heads_k<<<(NH_*S_*HD_ + 255)/256, 256, 0, st>>>(aoh, ao);

    gw(ao, Wo, xn1, S_, H_, H_, H_, H_, H_, 0,0,0, 1, 1);
    add_k<<<(S_*H_ + 255)/256, 256, 0, st>>>(x, xn1, hres, (long)S_*H_);

    // ===== MoE =====
    rmsnorm_k<<<S_, 256, 0, st>>>(hres, wln2, xn2, 0);   // exact for routing

    sgemm64_k<<<dim3(1, S_/64), 256, 0, st>>>(xn2, Wgate, logits, S_, E_, H_);
    topk_k<<<(S_ + 255)/256, 256, 0, st>>>(logits, topi, coef);
    assign_k<<<E_, 256, 0, st>>>(topi, pos);

    zero_k<<<(int)(((long)E_*CAP_*H_/4 + 255)/256), 256, 0, st>>>(buf, (long)E_*CAP_*H_/4);
    scatter_k<<<S_*TOPK_, 256, 0, st>>>(xn2, topi, pos, buf);

    gw(buf, Weg, gg, CAP_, ID_, H_, H_, ID_, ID_,
       (long)CAP_*H_, (long)H_*ID_, (long)CAP_*ID_, 1, E_);
    gw(buf, Weu, uu, CAP_, ID_, H_, H_, ID_, ID_,
       (long)CAP_*H_, (long)H_*ID_, (long)CAP_*ID_, 1, E_);

    { long n = (long)E_*CAP_*ID_;
      act_k<<<(int)((n + 255)/256), 256, 0, st>>>(gg, uu, n); }

    gw(gg, Wed, yy, CAP_, H_, ID_, ID_, H_, H_,
       (long)CAP_*ID_, (long)ID_*H_, (long)CAP_*H_, 1, E_);

    // shared expert (A = xn2 unrounded -> cvt A in-register)
    {
        dim3 grid(ID_/128, S_/128, 1);
        mmagemm_k<128, true, true, true><<<grid, 256, SM_W, st>>>(
            xn2, Wsg, sg, H_, H_, ID_, ID_, 0, 0, 0, 1);
        mmagemm_k<128, true, true, true><<<grid, 256, SM_W, st>>>(
            xn2, Wsu, su, H_, H_, ID_, ID_, 0, 0, 0, 1);
    }
    { long n = (long)S_*ID_;
      act_k<<<(int)((n + 255)/256), 256, 0, st>>>(sg, su, n); }
    gw(sg, Wsd, shb, S_, H_, ID_, ID_, H_, H_, 0,0,0, 1, 1);

    final_k<<<S_, 256, 0, st>>>(hres, shb, yy, topi, pos, coef, out);
}

// round 5
// speedup vs baseline: 4.4896x; 1.2880x over previous
#include <cuda_runtime.h>
#include <math.h>
#include <stdint.h>

#define S_    1024
#define H_    1024
#define NH_   16
#define KVH_  4
#define HD_   64
#define REP_  4
#define E_    64
#define TOPK_ 8
#define ID_   1408
#define CAP_  256
#define EPS_  1e-6f
#define QKVN_ (H_ + 2 * KVH_ * HD_)   // 1536

__device__ float g_xn1 [S_ * H_];
__device__ float g_wqkv[H_ * QKVN_];
__device__ float g_qkv [S_ * QKVN_];
__device__ float g_qr  [NH_ * S_ * HD_];
__device__ float g_kr  [KVH_ * S_ * HD_];
__device__ float g_vr  [KVH_ * S_ * HD_];
__device__ float g_sc  [(long)NH_ * S_ * S_];
__device__ float g_aoh [NH_ * S_ * HD_];
__device__ float g_ao  [S_ * H_];
__device__ float g_hres[S_ * H_];
__device__ float g_xn2 [S_ * H_];
__device__ float g_logits[S_ * E_];
__device__ int   g_topi[S_ * TOPK_];
__device__ float g_coef[S_ * TOPK_];
__device__ int   g_pos [S_ * TOPK_];
__device__ float g_buf [(long)E_ * CAP_ * H_];
__device__ float g_gg  [(long)E_ * CAP_ * ID_];
__device__ float g_uu  [(long)E_ * CAP_ * ID_];
__device__ float g_yy  [(long)E_ * CAP_ * H_];
__device__ float g_sg  [S_ * ID_];
__device__ float g_su  [S_ * ID_];
__device__ float g_shb [S_ * H_];

// ---------- helpers ----------
__device__ __forceinline__ uint32_t smem_u32(const void* p) {
    uint32_t a;
    asm("{ .reg .u64 t; cvta.to.shared.u64 t, %1; cvt.u32.u64 %0, t; }" : "=r"(a) : "l"(p));
    return a;
}
__device__ __forceinline__ float rtf(float x) {
    uint32_t r;
    asm("cvt.rna.tf32.f32 %0, %1;" : "=r"(r) : "f"(x));
    return __uint_as_float(r);
}
__device__ __forceinline__ uint32_t rtf_u(float x) {
    uint32_t r;
    asm("cvt.rna.tf32.f32 %0, %1;" : "=r"(r) : "f"(x));
    return r;
}
__device__ __forceinline__ void cp16(uint32_t dst, const void* src) {
    asm volatile("cp.async.cg.shared.global [%0], [%1], 16;" :: "r"(dst), "l"(src));
}
__device__ __forceinline__ void cp_commit() { asm volatile("cp.async.commit_group;" ::: "memory"); }
__device__ __forceinline__ void cp_wait(int n) {
    if (n <= 0)      asm volatile("cp.async.wait_group 0;" ::: "memory");
    else if (n == 1) asm volatile("cp.async.wait_group 1;" ::: "memory");
    else             asm volatile("cp.async.wait_group 2;" ::: "memory");
}
__device__ __forceinline__ void mma1688(float* d, const uint32_t* a, const uint32_t* b) {
    asm volatile("mma.sync.aligned.m16n8k8.row.col.f32.tf32.tf32.f32 "
        "{%0,%1,%2,%3}, {%4,%5,%6,%7}, {%8,%9}, {%0,%1,%2,%3};"
        : "+f"(d[0]), "+f"(d[1]), "+f"(d[2]), "+f"(d[3])
        : "r"(a[0]), "r"(a[1]), "r"(a[2]), "r"(a[3]), "r"(b[0]), "r"(b[1]));
}

// ---------- tf32 mma.sync GEMM ----------
// C[M,N] = A[M,K] @ B ; batched by blockIdx.z (strides sA,sB,sC; B index z/bDiv).
// BKMAJ=true : B gmem [K,N] row-major.  BKMAJ=false: B gmem [N,K] row-major (B^T).
// M mult of 128, N mult of BN, K mult of 32. Leading dims mult of 4.
template<int BN, bool BKMAJ, bool CVTA, bool CVTB>
__global__ void __launch_bounds__(256, 2) mmagemm_k(
    const float* __restrict__ A, const float* __restrict__ B, float* __restrict__ C,
    int K, int lda, int ldb, int ldc, long sA, long sB, long sC, int bDiv)
{
    constexpr int BM = 128, BK = 32;
    constexpr int LDA  = BK + 4;                       // bank = 4*qrw + qc (conflict-free)
    constexpr int LDBK = BN + 8;                       // bank = 8*qc + qrw (conflict-free)
    constexpr int A_FL = BM * LDA;
    constexpr int B_FL = BKMAJ ? BK * LDBK : BN * LDA;
    constexpr int STG_FL = A_FL + B_FL;
    constexpr int WGN = BN / 32, WGM = 8 / WGN;
    constexpr int WM  = BM / WGM, MT = WM / 16, NT = 4;

    extern __shared__ float sm[];
    const int tid = threadIdx.x, wid = tid >> 5, lane = tid & 31;
    const int qrw = lane >> 2, qc = lane & 3;
    A += (long)blockIdx.z * sA;
    B += (long)(blockIdx.z / bDiv) * sB;
    C += (long)blockIdx.z * sC;
    const int row0 = blockIdx.y * BM;
    const int col0 = blockIdx.x * BN;
    const int wm0 = (wid / WGN) * WM;
    const int wn0 = (wid % WGN) * 32;
    const int nch = K / BK;

    auto fill = [&](int c) {
        float* As = sm + (c % 3) * STG_FL;
        float* Bs = As + A_FL;
        const int k0 = c * BK;
        const float* Ag = A + (long)row0 * lda + k0;
        #pragma unroll
        for (int i = 0; i < 4; i++) {
            int idx = i * 256 + tid;
            int r = idx >> 3, sg = idx & 7;
            cp16(smem_u32(As + r * LDA + sg * 4), Ag + (long)r * lda + sg * 4);
        }
        if (BKMAJ) {
            const float* Bg = B + (long)k0 * ldb + col0;
            #pragma unroll
            for (int i = 0; i < BN / 32; i++) {
                int idx = i * 256 + tid;
                int r = idx / (BN / 4), sg = idx % (BN / 4);
                cp16(smem_u32(Bs + r * LDBK + sg * 4), Bg + (long)r * ldb + sg * 4);
            }
        } else {
            const float* Bg = B + (long)col0 * ldb + k0;
            #pragma unroll
            for (int i = 0; i < BN / 32; i++) {
                int idx = i * 256 + tid;
                int r = idx >> 3, sg = idx & 7;
                cp16(smem_u32(Bs + r * LDA + sg * 4), Bg + (long)r * ldb + sg * 4);
            }
        }
        cp_commit();
    };

    float acc[MT][NT][4];
    #pragma unroll
    for (int m = 0; m < MT; m++)
        #pragma unroll
        for (int n = 0; n < NT; n++)
            #pragma unroll
            for (int j = 0; j < 4; j++) acc[m][n][j] = 0.f;

    const int F0 = (nch < 2) ? nch : 2;
    for (int c = 0; c < F0; c++) fill(c);
    int g = F0;

    for (int c = 0; c < nch; c++) {
        cp_wait(g - (c + 1));
        __syncthreads();
        if (c + 2 < nch) { fill(c + 2); g++; }

        const float* As = sm + (c % 3) * STG_FL;
        const float* Bs = As + A_FL;
        #pragma unroll
        for (int ks = 0; ks < 4; ks++) {
            const int kk = ks * 8;
            uint32_t af[MT][4], bf[NT][2];
            #pragma unroll
            for (int mt = 0; mt < MT; mt++) {
                const float* ap = As + (wm0 + mt * 16 + qrw) * LDA + kk + qc;
                float a0 = ap[0], a1 = ap[8 * LDA], a2 = ap[4], a3 = ap[8 * LDA + 4];
                af[mt][0] = CVTA ? rtf_u(a0) : __float_as_uint(a0);
                af[mt][1] = CVTA ? rtf_u(a1) : __float_as_uint(a1);
                af[mt][2] = CVTA ? rtf_u(a2) : __float_as_uint(a2);
                af[mt][3] = CVTA ? rtf_u(a3) : __float_as_uint(a3);
            }
            #pragma unroll
            for (int nt = 0; nt < NT; nt++) {
                float b0, b1;
                if (BKMAJ) {
                    const float* bp = Bs + (kk + qc) * LDBK + wn0 + nt * 8 + qrw;
                    b0 = bp[0]; b1 = bp[4 * LDBK];
                } else {
                    const float* bp = Bs + (wn0 + nt * 8 + qrw) * LDA + kk + qc;
                    b0 = bp[0]; b1 = bp[4];
                }
                bf[nt][0] = CVTB ? rtf_u(b0) : __float_as_uint(b0);
                bf[nt][1] = CVTB ? rtf_u(b1) : __float_as_uint(b1);
            }
            #pragma unroll
            for (int mt = 0; mt < MT; mt++)
                #pragma unroll
                for (int nt = 0; nt < NT; nt++)
                    mma1688(acc[mt][nt], af[mt], bf[nt]);
        }
    }

    #pragma unroll
    for (int mt = 0; mt < MT; mt++) {
        const int r = row0 + wm0 + mt * 16 + qrw;
        #pragma unroll
        for (int nt = 0; nt < NT; nt++) {
            const int cc = col0 + wn0 + nt * 8 + qc * 2;
            *reinterpret_cast<float2*>(C + (long)r * ldc + cc) =
                make_float2(acc[mt][nt][0], acc[mt][nt][1]);
            *reinterpret_cast<float2*>(C + (long)(r + 8) * ldc + cc) =
                make_float2(acc[mt][nt][2], acc[mt][nt][3]);
        }
    }
}

// ---------- exact fp32 gemm for gate logits ----------
__global__ void sgemm64_k(const float* __restrict__ A, const float* __restrict__ B,
                          float* __restrict__ C, int M, int N, int K)
{
    const int tid = threadIdx.x;
    const int row0 = blockIdx.y * 64, col0 = blockIdx.x * 64;
    __shared__ float As[16][68];
    __shared__ float Bs[16][68];
    float acc[4][4] = {};
    const int tRow = (tid / 16) * 4, tCol = (tid % 16) * 4;
    const int aRow = tid / 4, aK = (tid % 4) * 4;
    const int bR = tid / 16, bC = (tid % 16) * 4;
    for (int k0 = 0; k0 < K; k0 += 16) {
        {
            int gr = row0 + aRow, gk = k0 + aK;
            float4 v = make_float4(0,0,0,0);
            if (gr < M && gk + 3 < K) v = *reinterpret_cast<const float4*>(A + (long)gr*K + gk);
            As[aK+0][aRow]=v.x; As[aK+1][aRow]=v.y; As[aK+2][aRow]=v.z; As[aK+3][aRow]=v.w;
        }
        {
            int gk = k0 + bR, gn = col0 + bC;
            float4 v = make_float4(0,0,0,0);
            if (gk < K && gn + 3 < N) v = *reinterpret_cast<const float4*>(B + (long)gk*N + gn);
            *reinterpret_cast<float4*>(&Bs[bR][bC]) = v;
        }
        __syncthreads();
        #pragma unroll
        for (int k = 0; k < 16; k++) {
            float rA[4], rB[4];
            #pragma unroll
            for (int m = 0; m < 4; m++) rA[m] = As[k][tRow+m];
            #pragma unroll
            for (int n = 0; n < 4; n++) rB[n] = Bs[k][tCol+n];
            #pragma unroll
            for (int m = 0; m < 4; m++)
                #pragma unroll
                for (int n = 0; n < 4; n++) acc[m][n] += rA[m]*rB[n];
        }
        __syncthreads();
    }
    #pragma unroll
    for (int m = 0; m < 4; m++) {
        int gr = row0 + tRow + m;
        if (gr >= M) continue;
        #pragma unroll
        for (int n = 0; n < 4; n++) {
            int gc = col0 + tCol + n;
            if (gc < N) C[(long)gr*N + gc] = acc[m][n];
        }
    }
}

// ---------- reductions ----------
__device__ __forceinline__ float warpSum(float v) {
    #pragma unroll
    for (int o = 16; o; o >>= 1) v += __shfl_xor_sync(0xffffffffu, v, o);
    return v;
}
__device__ __forceinline__ float warpMax(float v) {
    #pragma unroll
    for (int o = 16; o; o >>= 1) v = fmaxf(v, __shfl_xor_sync(0xffffffffu, v, o));
    return v;
}
__device__ float blockSum(float v) {
    __shared__ float sh[32]; __shared__ float tot;
    int lane = threadIdx.x & 31, wid = threadIdx.x >> 5;
    v = warpSum(v);
    if (lane == 0) sh[wid] = v;
    __syncthreads();
    int nw = (blockDim.x + 31) >> 5;
    float w = (threadIdx.x < nw) ? sh[threadIdx.x] : 0.f;
    if (wid == 0) { w = warpSum(w); if (lane == 0) tot = w; }
    __syncthreads();
    float r = tot; __syncthreads(); return r;
}
__device__ float blockMax(float v) {
    __shared__ float sh[32]; __shared__ float tot;
    int lane = threadIdx.x & 31, wid = threadIdx.x >> 5;
    v = warpMax(v);
    if (lane == 0) sh[wid] = v;
    __syncthreads();
    int nw = (blockDim.x + 31) >> 5;
    float w = (threadIdx.x < nw) ? sh[threadIdx.x] : -1e30f;
    if (wid == 0) { w = warpMax(w); if (lane == 0) tot = w; }
    __syncthreads();
    float r = tot; __syncthreads(); return r;
}

// ---------- small kernels ----------
__global__ void concat_qkv_w(const float* __restrict__ Wq, const float* __restrict__ Wk,
                             const float* __restrict__ Wv, float* __restrict__ W)
{
    int idx = blockIdx.x * blockDim.x + threadIdx.x;
    if (idx >= H_ * QKVN_) return;
    int r = idx / QKVN_, c = idx % QKVN_;
    float v;
    if (c < H_)                 v = Wq[(long)r * H_ + c];
    else if (c < H_ + KVH_*HD_) v = Wk[(long)r * (KVH_*HD_) + (c - H_)];
    else                        v = Wv[(long)r * (KVH_*HD_) + (c - H_ - KVH_*HD_)];
    W[idx] = v;
}

__global__ void rmsnorm_k(const float* __restrict__ x, const float* __restrict__ w,
                          float* __restrict__ y, int rnd)
{
    int t = blockIdx.x;
    const float* xr = x + (long)t * H_;
    float s = 0.f;
    for (int i = threadIdx.x; i < H_; i += blockDim.x) { float v = xr[i]; s += v * v; }
    s = blockSum(s);
    float inv = rsqrtf(s / (float)H_ + EPS_);
    for (int i = threadIdx.x; i < H_; i += blockDim.x) {
        float v = xr[i] * inv * w[i];
        y[(long)t * H_ + i] = rnd ? rtf(v) : v;
    }
}

// src (S, ld) with column offset -> dst (nh, S, HD) with RoPE
__global__ void rope_k(const float* __restrict__ src, float* __restrict__ dst,
                       int nh, int ld, int off)
{
    int idx = blockIdx.x * blockDim.x + threadIdx.x;
    if (idx >= nh * S_ * HD_) return;
    int d = idx % HD_;
    int s = (idx / HD_) % S_;
    int h = idx / (HD_ * S_);
    const float* p = src + (long)s * ld + off + h * HD_;
    float v  = p[d];
    float pr = (d < HD_/2) ? -p[d + HD_/2] : p[d - HD_/2];
    int i = d & (HD_/2 - 1);
    float inv = expf(-(float)i * (9.210340371976184f / (HD_/2)));
    float ang = (float)s * inv, sn, cs;
    sincosf(ang, &sn, &cs);
    dst[((long)h * S_ + s) * HD_ + d] = rtf(v * cs + pr * sn);
}

__global__ void transpose_heads_k(const float* __restrict__ src, float* __restrict__ dst,
                                  int nh, int ld, int off)
{
    int idx = blockIdx.x * blockDim.x + threadIdx.x;
    if (idx >= nh * S_ * HD_) return;
    int d = idx % HD_;
    int s = (idx / HD_) % S_;
    int h = idx / (HD_ * S_);
    dst[((long)h * S_ + s) * HD_ + d] = rtf(src[(long)s * ld + off + h * HD_ + d]);
}

__global__ void merge_heads_k(const float* __restrict__ src, float* __restrict__ dst)
{
    int idx = blockIdx.x * blockDim.x + threadIdx.x;
    if (idx >= NH_ * S_ * HD_) return;
    int d = idx % HD_;
    int s = (idx / HD_) % S_;
    int h = idx / (HD_ * S_);
    dst[(long)s * H_ + h * HD_ + d] = rtf(src[((long)h * S_ + s) * HD_ + d]);
}

__global__ void softmax_k(float* __restrict__ sc, const float* __restrict__ mask)
{
    int r = blockIdx.x, h = blockIdx.y;
    float* row = sc + ((long)h * S_ + r) * S_;
    const float* mr = mask + (long)r * S_;
    float mx = -1e30f;
    for (int j = threadIdx.x; j < S_; j += blockDim.x) {
        float v = row[j] * 0.125f + mr[j];
        row[j] = v;
        mx = fmaxf(mx, v);
    }
    mx = blockMax(mx);
    float sum = 0.f;
    for (int j = threadIdx.x; j < S_; j += blockDim.x) {
        float e = expf(row[j] - mx);
        row[j] = e;
        sum += e;
    }
    sum = blockSum(sum);
    float inv = 1.f / sum;
    for (int j = threadIdx.x; j < S_; j += blockDim.x) row[j] = rtf(row[j] * inv);
}

__global__ void add_k(const float* __restrict__ a, const float* __restrict__ b,
                      float* __restrict__ c, long n)
{
    long i = (long)blockIdx.x * blockDim.x + threadIdx.x;
    if (i < n) c[i] = a[i] + b[i];
}

__global__ void zero_k(float* __restrict__ p, long n4)
{
    long i = (long)blockIdx.x * blockDim.x + threadIdx.x;
    if (i < n4) reinterpret_cast<float4*>(p)[i] = make_float4(0,0,0,0);
}

__global__ void topk_k(const float* __restrict__ logits, int* __restrict__ topi,
                       float* __restrict__ coef)
{
    int t = blockIdx.x * blockDim.x + threadIdx.x;
    if (t >= S_) return;
    const float* lr = logits + (long)t * E_;
    unsigned long long sel = 0ull;
    float tv[TOPK_]; int ti[TOPK_];
    for (int k = 0; k < TOPK_; k++) {
        float best = -1e30f; int bi = 0;
        for (int e = 0; e < E_; e++) {
            if ((sel >> e) & 1ull) continue;
            float v = lr[e];
            if (v > best) { best = v; bi = e; }
        }
        sel |= 1ull << bi;
        tv[k] = best; ti[k] = bi;
    }
    float mx = tv[0], ex[TOPK_], sum = 0.f;
    for (int k = 0; k < TOPK_; k++) { ex[k] = expf(tv[k] - mx); sum += ex[k]; }
    float inv = 1.f / sum;
    for (int k = 0; k < TOPK_; k++) { topi[t*TOPK_+k] = ti[k]; coef[t*TOPK_+k] = ex[k]*inv; }
}

__global__ void assign_k(const int* __restrict__ topi, int* __restrict__ pos)
{
    const int e = blockIdx.x;
    __shared__ int sdata[256];
    int base = 0;
    for (int chunk = 0; chunk < S_ * TOPK_; chunk += 256) {
        int i = chunk + threadIdx.x;
        int p = (topi[i] == e) ? 1 : 0;
        sdata[threadIdx.x] = p;
        __syncthreads();
        #pragma unroll
        for (int off = 1; off < 256; off <<= 1) {
            int v = (threadIdx.x >= off) ? sdata[threadIdx.x - off] : 0;
            __syncthreads();
            sdata[threadIdx.x] += v;
            __syncthreads();
        }
        if (p) pos[i] = base + sdata[threadIdx.x] - 1;
        base += sdata[255];
        __syncthreads();
    }
}

__global__ void scatter_k(const float* __restrict__ xn2, const int* __restrict__ topi,
                          const int* __restrict__ pos, float* __restrict__ buf)
{
    int i = blockIdx.x;
    int p = pos[i];
    if (p >= CAP_) return;
    int e = topi[i];
    int t = i >> 3;
    const float* src = xn2 + (long)t * H_;
    float* dst = buf + ((long)e * CAP_ + p) * H_;
    for (int j = threadIdx.x; j < H_; j += blockDim.x) dst[j] = rtf(src[j]);
}

__global__ void act_k(float* __restrict__ g, const float* __restrict__ u, long n)
{
    long i = (long)blockIdx.x * blockDim.x + threadIdx.x;
    if (i < n) {
        float x = g[i];
        g[i] = rtf((x / (1.f + expf(-x))) * u[i]);
    }
}

__global__ void final_k(const float* __restrict__ hres, const float* __restrict__ shb,
                        const float* __restrict__ y, const int* __restrict__ topi,
                        const int* __restrict__ pos, const float* __restrict__ coef,
                        float* __restrict__ out)
{
    int t = blockIdx.x, j = threadIdx.x;
    float4 a = reinterpret_cast<const float4*>(hres)[(long)t*256 + j];
    float4 b = reinterpret_cast<const float4*>(shb)[(long)t*256 + j];
    a.x += b.x; a.y += b.y; a.z += b.z; a.w += b.w;
    #pragma unroll
    for (int k = 0; k < TOPK_; k++) {
        int idx = t * TOPK_ + k;
        int p = pos[idx];
        if (p < CAP_) {
            float c = coef[idx];
            float4 v = reinterpret_cast<const float4*>(y)[((long)topi[idx]*CAP_ + p)*256 + j];
            a.x += c*v.x; a.y += c*v.y; a.z += c*v.z; a.w += c*v.w;
        }
    }
    reinterpret_cast<float4*>(out)[(long)t*256 + j] = a;
}

// ---------- host-side smem size (mirror of kernel constexpr) ----------
static int smemBytes(int BN, bool bkmaj) {
    int A_FL = 128 * 36;
    int B_FL = bkmaj ? 32 * (BN + 8) : BN * 36;
    return 3 * (A_FL + B_FL) * 4;
}

extern "C" void kernel_launch(void* const* d_in, const int* in_sizes, int n_in,
                              void* d_out, int out_size)
{
    (void)in_sizes; (void)n_in; (void)out_size;
    cudaStream_t st = 0;

    const int SM_W   = smemBytes(128, true);
    const int SM_SCR = smemBytes(128, false);
    const int SM_PV  = smemBytes(64, true);
    cudaFuncSetAttribute(mmagemm_k<128, true,  false, true >, cudaFuncAttributeMaxDynamicSharedMemorySize, SM_W);
    cudaFuncSetAttribute(mmagemm_k<128, true,  true,  true >, cudaFuncAttributeMaxDynamicSharedMemorySize, SM_W);
    cudaFuncSetAttribute(mmagemm_k<128, false, false, false>, cudaFuncAttributeMaxDynamicSharedMemorySize, SM_SCR);
    cudaFuncSetAttribute(mmagemm_k<64,  true,  false, false>, cudaFuncAttributeMaxDynamicSharedMemorySize, SM_PV);

    const float* x     = (const float*)d_in[0];
    const float* mask  = (const float*)d_in[1];
    const float* wln1  = (const float*)d_in[2];
    const float* wln2  = (const float*)d_in[3];
    const float* Wq    = (const float*)d_in[4];
    const float* Wk    = (const float*)d_in[5];
    const float* Wv    = (const float*)d_in[6];
    const float* Wo    = (const float*)d_in[7];
    const float* Wgate = (const float*)d_in[8];
    const float* Weg   = (const float*)d_in[9];
    const float* Weu   = (const float*)d_in[10];
    const float* Wed   = (const float*)d_in[11];
    const float* Wsg   = (const float*)d_in[12];
    const float* Wsu   = (const float*)d_in[13];
    const float* Wsd   = (const float*)d_in[14];
    float* out = (float*)d_out;

    void *p;
    #define GET(sym, var) cudaGetSymbolAddress(&p, sym); float* var = (float*)p;
    #define GETI(sym, var) cudaGetSymbolAddress(&p, sym); int* var = (int*)p;
    GET(g_xn1, xn1)  GET(g_wqkv, wqkv) GET(g_qkv, qkv)
    GET(g_qr, qr)    GET(g_kr, kr)     GET(g_vr, vr)     GET(g_sc, sc)
    GET(g_aoh, aoh)  GET(g_ao, ao)     GET(g_hres, hres) GET(g_xn2, xn2)
    GET(g_logits, logits) GET(g_coef, coef)
    GET(g_buf, buf)  GET(g_gg, gg)     GET(g_uu, uu)     GET(g_yy, yy)
    GET(g_sg, sg)    GET(g_su, su)     GET(g_shb, shb)
    GETI(g_topi, topi) GETI(g_pos, pos)
    #undef GET
    #undef GETI

    auto gw = [&](const float* A, const float* B, float* C, int M, int N, int K,
                  int lda, int ldb, int ldc, long sA, long sB, long sC, int bDiv, int batch) {
        dim3 grid(N / 128, M / 128, batch);
        mmagemm_k<128, true, false, true><<<grid, 256, SM_W, st>>>(A, B, C, K, lda, ldb, ldc, sA, sB, sC, bDiv);
    };

    // ===== attention =====
    rmsnorm_k<<<S_, 256, 0, st>>>(x, wln1, xn1, 1);

    concat_qkv_w<<<(H_ * QKVN_ + 255)/256, 256, 0, st>>>(Wq, Wk, Wv, wqkv);
    gw(xn1, wqkv, qkv, S_, QKVN_, H_, H_, QKVN_, QKVN_, 0,0,0, 1, 1);

    rope_k<<<(NH_*S_*HD_ + 255)/256, 256, 0, st>>>(qkv, qr, NH_, QKVN_, 0);
    rope_k<<<(KVH_*S_*HD_ + 255)/256, 256, 0, st>>>(qkv, kr, KVH_, QKVN_, H_);
    transpose_heads_k<<<(KVH_*S_*HD_ + 255)/256, 256, 0, st>>>(qkv, vr, KVH_, QKVN_, H_ + KVH_*HD_);

    // scores[h] = qr[h] @ kr[h/4]^T : B = kr ([N,K] row-major)
    {
        dim3 grid(S_/128, S_/128, NH_);
        mmagemm_k<128, false, false, false><<<grid, 256, SM_SCR, st>>>(
            qr, kr, sc, HD_, HD_, HD_, S_,
            (long)S_*HD_, (long)S_*HD_, (long)S_*S_, REP_);
    }

    softmax_k<<<dim3(S_, NH_), 256, 0, st>>>(sc, mask);

    // aoh[h] = probs[h] @ vr[h/4] : B = vr ([K,N]=[S,HD] row-major), N=64
    {
        dim3 grid(1, S_/128, NH_);
        mmagemm_k<64, true, false, false><<<grid, 256, SM_PV, st>>>(
            sc, vr, aoh, S_, S_, HD_, HD_,
            (long)S_*S_, (long)S_*HD_, (long)S_*HD_, REP_);
    }

    merge_heads_k<<<(NH_*S_*HD_ + 255)/256, 256, 0, st>>>(aoh, ao);

    gw(ao, Wo, xn1, S_, H_, H_, H_, H_, H_, 0,0,0, 1, 1);
    add_k<<<(S_*H_ + 255)/256, 256, 0, st>>>(x, xn1, hres, (long)S_*H_);

    // ===== MoE =====
    rmsnorm_k<<<S_, 256, 0, st>>>(hres, wln2, xn2, 0);   // exact for routing

    sgemm64_k<<<dim3(1, S_/64), 256, 0, st>>>(xn2, Wgate, logits, S_, E_, H_);
    topk_k<<<(S_ + 255)/256, 256, 0, st>>>(logits, topi, coef);
    assign_k<<<E_, 256, 0, st>>>(topi, pos);

    zero_k<<<(int)(((long)E_*CAP_*H_/4 + 255)/256), 256, 0, st>>>(buf, (long)E_*CAP_*H_/4);
    scatter_k<<<S_*TOPK_, 256, 0, st>>>(xn2, topi, pos, buf);

    gw(buf, Weg, gg, CAP_, ID_, H_, H_, ID_, ID_,
       (long)CAP_*H_, (long)H_*ID_, (long)CAP_*ID_, 1, E_);
    gw(buf, Weu, uu, CAP_, ID_, H_, H_, ID_, ID_,
       (long)CAP_*H_, (long)H_*ID_, (long)CAP_*ID_, 1, E_);

    { long n = (long)E_*CAP_*ID_;
      act_k<<<(int)((n + 255)/256), 256, 0, st>>>(gg, uu, n); }

    gw(gg, Wed, yy, CAP_, H_, ID_, ID_, H_, H_,
       (long)CAP_*ID_, (long)ID_*H_, (long)CAP_*H_, 1, E_);

    // shared expert (A = xn2 unrounded -> cvt A in-register)
    {
        dim3 grid(ID_/128, S_/128, 1);
        mmagemm_k<128, true, true, true><<<grid, 256, SM_W, st>>>(
            xn2, Wsg, sg, H_, H_, ID_, ID_, 0, 0, 0, 1);
        mmagemm_k<128, true, true, true><<<grid, 256, SM_W, st>>>(
            xn2, Wsu, su, H_, H_, ID_, ID_, 0, 0, 0, 1);
    }
    { long n = (long)S_*ID_;
      act_k<<<(int)((n + 255)/256), 256, 0, st>>>(sg, su, n); }
    gw(sg, Wsd, shb, S_, H_, ID_, ID_, H_, H_, 0,0,0, 1, 1);

    final_k<<<S_, 256, 0, st>>>(hres, shb, yy, topi, pos, coef, out);
}

// round 6
// speedup vs baseline: 5.3565x; 1.1931x over previous
#include <cuda_runtime.h>
#include <math.h>
#include <stdint.h>

#define S_    1024
#define H_    1024
#define NH_   16
#define KVH_  4
#define HD_   64
#define REP_  4
#define E_    64
#define TOPK_ 8
#define ID_   1408
#define CAP_  256
#define EPS_  1e-6f
#define QKVN_ (H_ + 2 * KVH_ * HD_)   // 1536

__device__ float g_xn1 [S_ * H_];
__device__ float g_wqkv[H_ * QKVN_];
__device__ float g_qkv [S_ * QKVN_];
__device__ float g_qr  [NH_ * S_ * HD_];
__device__ float g_kr  [KVH_ * S_ * HD_];
__device__ float g_vr  [KVH_ * S_ * HD_];
__device__ float g_sc  [(long)NH_ * S_ * S_];
__device__ float g_aoh [NH_ * S_ * HD_];
__device__ float g_ao  [S_ * H_];
__device__ float g_hres[S_ * H_];
__device__ float g_xn2 [S_ * H_];
__device__ float g_logits[S_ * E_];
__device__ int   g_topi[S_ * TOPK_];
__device__ float g_coef[S_ * TOPK_];
__device__ int   g_pos [S_ * TOPK_];
__device__ int   g_cnt [E_];
__device__ float g_buf [(long)E_ * CAP_ * H_];
__device__ float g_gg  [(long)E_ * CAP_ * ID_];
__device__ float g_uu  [(long)E_ * CAP_ * ID_];
__device__ float g_yy  [(long)E_ * CAP_ * H_];
__device__ float g_sg  [S_ * ID_];
__device__ float g_su  [S_ * ID_];
__device__ float g_shb [S_ * H_];

// ---------- helpers ----------
__device__ __forceinline__ uint32_t smem_u32(const void* p) {
    uint32_t a;
    asm("{ .reg .u64 t; cvta.to.shared.u64 t, %1; cvt.u32.u64 %0, t; }" : "=r"(a) : "l"(p));
    return a;
}
__device__ __forceinline__ float rtf(float x) {
    uint32_t r;
    asm("cvt.rna.tf32.f32 %0, %1;" : "=r"(r) : "f"(x));
    return __uint_as_float(r);
}
__device__ __forceinline__ uint32_t rtf_u(float x) {
    uint32_t r;
    asm("cvt.rna.tf32.f32 %0, %1;" : "=r"(r) : "f"(x));
    return r;
}
__device__ __forceinline__ void cp16(uint32_t dst, const void* src) {
    asm volatile("cp.async.cg.shared.global [%0], [%1], 16;" :: "r"(dst), "l"(src));
}
__device__ __forceinline__ void cp_commit() { asm volatile("cp.async.commit_group;" ::: "memory"); }
__device__ __forceinline__ void cp_wait(int n) {
    if (n <= 0)      asm volatile("cp.async.wait_group 0;" ::: "memory");
    else if (n == 1) asm volatile("cp.async.wait_group 1;" ::: "memory");
    else             asm volatile("cp.async.wait_group 2;" ::: "memory");
}
__device__ __forceinline__ void mma1688(float* d, const uint32_t* a, const uint32_t* b) {
    asm volatile("mma.sync.aligned.m16n8k8.row.col.f32.tf32.tf32.f32 "
        "{%0,%1,%2,%3}, {%4,%5,%6,%7}, {%8,%9}, {%0,%1,%2,%3};"
        : "+f"(d[0]), "+f"(d[1]), "+f"(d[2]), "+f"(d[3])
        : "r"(a[0]), "r"(a[1]), "r"(a[2]), "r"(a[3]), "r"(b[0]), "r"(b[1]));
}

// ---------- tf32 mma.sync GEMM ----------
// C[M,N] = A[M,K] @ B ; batched by blockIdx.z (strides sA,sB,sC; B index z/bDiv).
// BKMAJ=true : B gmem [K,N] row-major.  BKMAJ=false: B gmem [N,K] row-major (B^T).
// cnt != nullptr: per-batch valid row count; CTAs whose whole M-tile is >= cnt[z] exit.
template<int BN, bool BKMAJ, bool CVTA, bool CVTB>
__global__ void __launch_bounds__(256, 2) mmagemm_k(
    const float* __restrict__ A, const float* __restrict__ B, float* __restrict__ C,
    int K, int lda, int ldb, int ldc, long sA, long sB, long sC, int bDiv,
    const int* __restrict__ cnt)
{
    constexpr int BM = 128, BK = 32;
    constexpr int LDA  = BK + 4;
    constexpr int LDBK = BN + 8;
    constexpr int A_FL = BM * LDA;
    constexpr int B_FL = BKMAJ ? BK * LDBK : BN * LDA;
    constexpr int STG_FL = A_FL + B_FL;
    constexpr int WGN = BN / 32, WGM = 8 / WGN;
    constexpr int WM  = BM / WGM, MT = WM / 16, NT = 4;

    const int row0 = blockIdx.y * BM;
    if (cnt != nullptr && row0 >= cnt[blockIdx.z]) return;

    extern __shared__ float sm[];
    const int tid = threadIdx.x, wid = tid >> 5, lane = tid & 31;
    const int qrw = lane >> 2, qc = lane & 3;
    A += (long)blockIdx.z * sA;
    B += (long)(blockIdx.z / bDiv) * sB;
    C += (long)blockIdx.z * sC;
    const int col0 = blockIdx.x * BN;
    const int wm0 = (wid / WGN) * WM;
    const int wn0 = (wid % WGN) * 32;
    const int nch = K / BK;

    auto fill = [&](int c) {
        float* As = sm + (c % 3) * STG_FL;
        float* Bs = As + A_FL;
        const int k0 = c * BK;
        const float* Ag = A + (long)row0 * lda + k0;
        #pragma unroll
        for (int i = 0; i < 4; i++) {
            int idx = i * 256 + tid;
            int r = idx >> 3, sg = idx & 7;
            cp16(smem_u32(As + r * LDA + sg * 4), Ag + (long)r * lda + sg * 4);
        }
        if (BKMAJ) {
            const float* Bg = B + (long)k0 * ldb + col0;
            #pragma unroll
            for (int i = 0; i < BN / 32; i++) {
                int idx = i * 256 + tid;
                int r = idx / (BN / 4), sg = idx % (BN / 4);
                cp16(smem_u32(Bs + r * LDBK + sg * 4), Bg + (long)r * ldb + sg * 4);
            }
        } else {
            const float* Bg = B + (long)col0 * ldb + k0;
            #pragma unroll
            for (int i = 0; i < BN / 32; i++) {
                int idx = i * 256 + tid;
                int r = idx >> 3, sg = idx & 7;
                cp16(smem_u32(Bs + r * LDA + sg * 4), Bg + (long)r * ldb + sg * 4);
            }
        }
        cp_commit();
    };

    float acc[MT][NT][4];
    #pragma unroll
    for (int m = 0; m < MT; m++)
        #pragma unroll
        for (int n = 0; n < NT; n++)
            #pragma unroll
            for (int j = 0; j < 4; j++) acc[m][n][j] = 0.f;

    const int F0 = (nch < 2) ? nch : 2;
    for (int c = 0; c < F0; c++) fill(c);
    int g = F0;

    for (int c = 0; c < nch; c++) {
        cp_wait(g - (c + 1));
        __syncthreads();
        if (c + 2 < nch) { fill(c + 2); g++; }

        const float* As = sm + (c % 3) * STG_FL;
        const float* Bs = As + A_FL;
        #pragma unroll
        for (int ks = 0; ks < 4; ks++) {
            const int kk = ks * 8;
            uint32_t af[MT][4], bf[NT][2];
            #pragma unroll
            for (int mt = 0; mt < MT; mt++) {
                const float* ap = As + (wm0 + mt * 16 + qrw) * LDA + kk + qc;
                float a0 = ap[0], a1 = ap[8 * LDA], a2 = ap[4], a3 = ap[8 * LDA + 4];
                af[mt][0] = CVTA ? rtf_u(a0) : __float_as_uint(a0);
                af[mt][1] = CVTA ? rtf_u(a1) : __float_as_uint(a1);
                af[mt][2] = CVTA ? rtf_u(a2) : __float_as_uint(a2);
                af[mt][3] = CVTA ? rtf_u(a3) : __float_as_uint(a3);
            }
            #pragma unroll
            for (int nt = 0; nt < NT; nt++) {
                float b0, b1;
                if (BKMAJ) {
                    const float* bp = Bs + (kk + qc) * LDBK + wn0 + nt * 8 + qrw;
                    b0 = bp[0]; b1 = bp[4 * LDBK];
                } else {
                    const float* bp = Bs + (wn0 + nt * 8 + qrw) * LDA + kk + qc;
                    b0 = bp[0]; b1 = bp[4];
                }
                bf[nt][0] = CVTB ? rtf_u(b0) : __float_as_uint(b0);
                bf[nt][1] = CVTB ? rtf_u(b1) : __float_as_uint(b1);
            }
            #pragma unroll
            for (int mt = 0; mt < MT; mt++)
                #pragma unroll
                for (int nt = 0; nt < NT; nt++)
                    mma1688(acc[mt][nt], af[mt], bf[nt]);
        }
    }

    #pragma unroll
    for (int mt = 0; mt < MT; mt++) {
        const int r = row0 + wm0 + mt * 16 + qrw;
        #pragma unroll
        for (int nt = 0; nt < NT; nt++) {
            const int cc = col0 + wn0 + nt * 8 + qc * 2;
            *reinterpret_cast<float2*>(C + (long)r * ldc + cc) =
                make_float2(acc[mt][nt][0], acc[mt][nt][1]);
            *reinterpret_cast<float2*>(C + (long)(r + 8) * ldc + cc) =
                make_float2(acc[mt][nt][2], acc[mt][nt][3]);
        }
    }
}

// ---------- exact fp32 gemm for gate logits ----------
__global__ void sgemm64_k(const float* __restrict__ A, const float* __restrict__ B,
                          float* __restrict__ C, int M, int N, int K)
{
    const int tid = threadIdx.x;
    const int row0 = blockIdx.y * 64, col0 = blockIdx.x * 64;
    __shared__ float As[16][68];
    __shared__ float Bs[16][68];
    float acc[4][4] = {};
    const int tRow = (tid / 16) * 4, tCol = (tid % 16) * 4;
    const int aRow = tid / 4, aK = (tid % 4) * 4;
    const int bR = tid / 16, bC = (tid % 16) * 4;
    for (int k0 = 0; k0 < K; k0 += 16) {
        {
            int gr = row0 + aRow, gk = k0 + aK;
            float4 v = make_float4(0,0,0,0);
            if (gr < M && gk + 3 < K) v = *reinterpret_cast<const float4*>(A + (long)gr*K + gk);
            As[aK+0][aRow]=v.x; As[aK+1][aRow]=v.y; As[aK+2][aRow]=v.z; As[aK+3][aRow]=v.w;
        }
        {
            int gk = k0 + bR, gn = col0 + bC;
            float4 v = make_float4(0,0,0,0);
            if (gk < K && gn + 3 < N) v = *reinterpret_cast<const float4*>(B + (long)gk*N + gn);
            *reinterpret_cast<float4*>(&Bs[bR][bC]) = v;
        }
        __syncthreads();
        #pragma unroll
        for (int k = 0; k < 16; k++) {
            float rA[4], rB[4];
            #pragma unroll
            for (int m = 0; m < 4; m++) rA[m] = As[k][tRow+m];
            #pragma unroll
            for (int n = 0; n < 4; n++) rB[n] = Bs[k][tCol+n];
            #pragma unroll
            for (int m = 0; m < 4; m++)
                #pragma unroll
                for (int n = 0; n < 4; n++) acc[m][n] += rA[m]*rB[n];
        }
        __syncthreads();
    }
    #pragma unroll
    for (int m = 0; m < 4; m++) {
        int gr = row0 + tRow + m;
        if (gr >= M) continue;
        #pragma unroll
        for (int n = 0; n < 4; n++) {
            int gc = col0 + tCol + n;
            if (gc < N) C[(long)gr*N + gc] = acc[m][n];
        }
    }
}

// ---------- reductions ----------
__device__ __forceinline__ float warpSum(float v) {
    #pragma unroll
    for (int o = 16; o; o >>= 1) v += __shfl_xor_sync(0xffffffffu, v, o);
    return v;
}
__device__ __forceinline__ float warpMax(float v) {
    #pragma unroll
    for (int o = 16; o; o >>= 1) v = fmaxf(v, __shfl_xor_sync(0xffffffffu, v, o));
    return v;
}
__device__ float blockSum(float v) {
    __shared__ float sh[32]; __shared__ float tot;
    int lane = threadIdx.x & 31, wid = threadIdx.x >> 5;
    v = warpSum(v);
    if (lane == 0) sh[wid] = v;
    __syncthreads();
    int nw = (blockDim.x + 31) >> 5;
    float w = (threadIdx.x < nw) ? sh[threadIdx.x] : 0.f;
    if (wid == 0) { w = warpSum(w); if (lane == 0) tot = w; }
    __syncthreads();
    float r = tot; __syncthreads(); return r;
}
__device__ float blockMax(float v) {
    __shared__ float sh[32]; __shared__ float tot;
    int lane = threadIdx.x & 31, wid = threadIdx.x >> 5;
    v = warpMax(v);
    if (lane == 0) sh[wid] = v;
    __syncthreads();
    int nw = (blockDim.x + 31) >> 5;
    float w = (threadIdx.x < nw) ? sh[threadIdx.x] : -1e30f;
    if (wid == 0) { w = warpMax(w); if (lane == 0) tot = w; }
    __syncthreads();
    float r = tot; __syncthreads(); return r;
}

// ---------- small kernels ----------
__global__ void concat_qkv_w(const float* __restrict__ Wq, const float* __restrict__ Wk,
                             const float* __restrict__ Wv, float* __restrict__ W)
{
    int idx = blockIdx.x * blockDim.x + threadIdx.x;
    if (idx >= H_ * QKVN_) return;
    int r = idx / QKVN_, c = idx % QKVN_;
    float v;
    if (c < H_)                 v = Wq[(long)r * H_ + c];
    else if (c < H_ + KVH_*HD_) v = Wk[(long)r * (KVH_*HD_) + (c - H_)];
    else                        v = Wv[(long)r * (KVH_*HD_) + (c - H_ - KVH_*HD_)];
    W[idx] = v;
}

__global__ void rmsnorm_k(const float* __restrict__ x, const float* __restrict__ w,
                          float* __restrict__ y, int rnd)
{
    int t = blockIdx.x;
    const float* xr = x + (long)t * H_;
    float s = 0.f;
    for (int i = threadIdx.x; i < H_; i += blockDim.x) { float v = xr[i]; s += v * v; }
    s = blockSum(s);
    float inv = rsqrtf(s / (float)H_ + EPS_);
    for (int i = threadIdx.x; i < H_; i += blockDim.x) {
        float v = xr[i] * inv * w[i];
        y[(long)t * H_ + i] = rnd ? rtf(v) : v;
    }
}

__global__ void rope_k(const float* __restrict__ src, float* __restrict__ dst,
                       int nh, int ld, int off)
{
    int idx = blockIdx.x * blockDim.x + threadIdx.x;
    if (idx >= nh * S_ * HD_) return;
    int d = idx % HD_;
    int s = (idx / HD_) % S_;
    int h = idx / (HD_ * S_);
    const float* p = src + (long)s * ld + off + h * HD_;
    float v  = p[d];
    float pr = (d < HD_/2) ? -p[d + HD_/2] : p[d - HD_/2];
    int i = d & (HD_/2 - 1);
    float inv = expf(-(float)i * (9.210340371976184f / (HD_/2)));
    float ang = (float)s * inv, sn, cs;
    sincosf(ang, &sn, &cs);
    dst[((long)h * S_ + s) * HD_ + d] = rtf(v * cs + pr * sn);
}

__global__ void transpose_heads_k(const float* __restrict__ src, float* __restrict__ dst,
                                  int nh, int ld, int off)
{
    int idx = blockIdx.x * blockDim.x + threadIdx.x;
    if (idx >= nh * S_ * HD_) return;
    int d = idx % HD_;
    int s = (idx / HD_) % S_;
    int h = idx / (HD_ * S_);
    dst[((long)h * S_ + s) * HD_ + d] = rtf(src[(long)s * ld + off + h * HD_ + d]);
}

__global__ void merge_heads_k(const float* __restrict__ src, float* __restrict__ dst)
{
    int idx = blockIdx.x * blockDim.x + threadIdx.x;
    if (idx >= NH_ * S_ * HD_) return;
    int d = idx % HD_;
    int s = (idx / HD_) % S_;
    int h = idx / (HD_ * S_);
    dst[(long)s * H_ + h * HD_ + d] = rtf(src[((long)h * S_ + s) * HD_ + d]);
}

// single-pass masked softmax: row cached in 4 float4 registers
__global__ void softmax_k(float* __restrict__ sc, const float* __restrict__ mask)
{
    int r = blockIdx.x, h = blockIdx.y;
    float4* row = reinterpret_cast<float4*>(sc + ((long)h * S_ + r) * S_);
    const float4* mr = reinterpret_cast<const float4*>(mask + (long)r * S_);
    int j = threadIdx.x;             // 256 threads x float4 = 1024
    float4 v = row[j], m = mr[j];
    v.x = v.x * 0.125f + m.x;
    v.y = v.y * 0.125f + m.y;
    v.z = v.z * 0.125f + m.z;
    v.w = v.w * 0.125f + m.w;
    float mx = fmaxf(fmaxf(v.x, v.y), fmaxf(v.z, v.w));
    mx = blockMax(mx);
    v.x = expf(v.x - mx); v.y = expf(v.y - mx);
    v.z = expf(v.z - mx); v.w = expf(v.w - mx);
    float sum = v.x + v.y + v.z + v.w;
    sum = blockSum(sum);
    float inv = 1.f / sum;
    v.x = rtf(v.x * inv); v.y = rtf(v.y * inv);
    v.z = rtf(v.z * inv); v.w = rtf(v.w * inv);
    row[j] = v;
}

__global__ void add_k(const float* __restrict__ a, const float* __restrict__ b,
                      float* __restrict__ c, long n)
{
    long i = (long)blockIdx.x * blockDim.x + threadIdx.x;
    if (i < n) c[i] = a[i] + b[i];
}

__global__ void topk_k(const float* __restrict__ logits, int* __restrict__ topi,
                       float* __restrict__ coef)
{
    int t = blockIdx.x * blockDim.x + threadIdx.x;
    if (t >= S_) return;
    const float* lr = logits + (long)t * E_;
    unsigned long long sel = 0ull;
    float tv[TOPK_]; int ti[TOPK_];
    for (int k = 0; k < TOPK_; k++) {
        float best = -1e30f; int bi = 0;
        for (int e = 0; e < E_; e++) {
            if ((sel >> e) & 1ull) continue;
            float v = lr[e];
            if (v > best) { best = v; bi = e; }
        }
        sel |= 1ull << bi;
        tv[k] = best; ti[k] = bi;
    }
    float mx = tv[0], ex[TOPK_], sum = 0.f;
    for (int k = 0; k < TOPK_; k++) { ex[k] = expf(tv[k] - mx); sum += ex[k]; }
    float inv = 1.f / sum;
    for (int k = 0; k < TOPK_; k++) { topi[t*TOPK_+k] = ti[k]; coef[t*TOPK_+k] = ex[k]*inv; }
}

__global__ void assign_k(const int* __restrict__ topi, int* __restrict__ pos,
                         int* __restrict__ cnt)
{
    const int e = blockIdx.x;
    __shared__ int sdata[256];
    int base = 0;
    for (int chunk = 0; chunk < S_ * TOPK_; chunk += 256) {
        int i = chunk + threadIdx.x;
        int p = (topi[i] == e) ? 1 : 0;
        sdata[threadIdx.x] = p;
        __syncthreads();
        #pragma unroll
        for (int off = 1; off < 256; off <<= 1) {
            int v = (threadIdx.x >= off) ? sdata[threadIdx.x - off] : 0;
            __syncthreads();
            sdata[threadIdx.x] += v;
            __syncthreads();
        }
        if (p) pos[i] = base + sdata[threadIdx.x] - 1;
        base += sdata[255];
        __syncthreads();
    }
    if (threadIdx.x == 0) cnt[e] = (base < CAP_) ? base : CAP_;
}

__global__ void scatter_k(const float* __restrict__ xn2, const int* __restrict__ topi,
                          const int* __restrict__ pos, float* __restrict__ buf)
{
    int i = blockIdx.x;
    int p = pos[i];
    if (p >= CAP_) return;
    int e = topi[i];
    int t = i >> 3;
    const float* src = xn2 + (long)t * H_;
    float* dst = buf + ((long)e * CAP_ + p) * H_;
    for (int j = threadIdx.x; j < H_; j += blockDim.x) dst[j] = rtf(src[j]);
}

// expert activation: one block per (expert, cap-row); skip rows >= cnt[e]
__global__ void act_expert_k(float* __restrict__ g, const float* __restrict__ u,
                             const int* __restrict__ cnt)
{
    int e = blockIdx.x >> 8, c = blockIdx.x & 255;
    if (c >= cnt[e]) return;
    long base = ((long)e * CAP_ + c) * ID_;
    for (int j = threadIdx.x; j < ID_; j += blockDim.x) {
        float x = g[base + j];
        g[base + j] = rtf((x / (1.f + expf(-x))) * u[base + j]);
    }
}

__global__ void act_k(float* __restrict__ g, const float* __restrict__ u, long n)
{
    long i = (long)blockIdx.x * blockDim.x + threadIdx.x;
    if (i < n) {
        float x = g[i];
        g[i] = rtf((x / (1.f + expf(-x))) * u[i]);
    }
}

__global__ void final_k(const float* __restrict__ hres, const float* __restrict__ shb,
                        const float* __restrict__ y, const int* __restrict__ topi,
                        const int* __restrict__ pos, const float* __restrict__ coef,
                        float* __restrict__ out)
{
    int t = blockIdx.x, j = threadIdx.x;
    float4 a = reinterpret_cast<const float4*>(hres)[(long)t*256 + j];
    float4 b = reinterpret_cast<const float4*>(shb)[(long)t*256 + j];
    a.x += b.x; a.y += b.y; a.z += b.z; a.w += b.w;
    #pragma unroll
    for (int k = 0; k < TOPK_; k++) {
        int idx = t * TOPK_ + k;
        int p = pos[idx];
        if (p < CAP_) {
            float c = coef[idx];
            float4 v = reinterpret_cast<const float4*>(y)[((long)topi[idx]*CAP_ + p)*256 + j];
            a.x += c*v.x; a.y += c*v.y; a.z += c*v.z; a.w += c*v.w;
        }
    }
    reinterpret_cast<float4*>(out)[(long)t*256 + j] = a;
}

// ---------- host-side smem size ----------
static int smemBytes(int BN, bool bkmaj) {
    int A_FL = 128 * 36;
    int B_FL = bkmaj ? 32 * (BN + 8) : BN * 36;
    return 3 * (A_FL + B_FL) * 4;
}

extern "C" void kernel_launch(void* const* d_in, const int* in_sizes, int n_in,
                              void* d_out, int out_size)
{
    (void)in_sizes; (void)n_in; (void)out_size;
    cudaStream_t st = 0;

    const int SM_W   = smemBytes(128, true);
    const int SM_SCR = smemBytes(128, false);
    const int SM_PV  = smemBytes(64, true);
    cudaFuncSetAttribute(mmagemm_k<128, true,  false, true >, cudaFuncAttributeMaxDynamicSharedMemorySize, SM_W);
    cudaFuncSetAttribute(mmagemm_k<128, true,  true,  true >, cudaFuncAttributeMaxDynamicSharedMemorySize, SM_W);
    cudaFuncSetAttribute(mmagemm_k<128, false, false, false>, cudaFuncAttributeMaxDynamicSharedMemorySize, SM_SCR);
    cudaFuncSetAttribute(mmagemm_k<64,  true,  false, false>, cudaFuncAttributeMaxDynamicSharedMemorySize, SM_PV);

    const float* x     = (const float*)d_in[0];
    const float* mask  = (const float*)d_in[1];
    const float* wln1  = (const float*)d_in[2];
    const float* wln2  = (const float*)d_in[3];
    const float* Wq    = (const float*)d_in[4];
    const float* Wk    = (const float*)d_in[5];
    const float* Wv    = (const float*)d_in[6];
    const float* Wo    = (const float*)d_in[7];
    const float* Wgate = (const float*)d_in[8];
    const float* Weg   = (const float*)d_in[9];
    const float* Weu   = (const float*)d_in[10];
    const float* Wed   = (const float*)d_in[11];
    const float* Wsg   = (const float*)d_in[12];
    const float* Wsu   = (const float*)d_in[13];
    const float* Wsd   = (const float*)d_in[14];
    float* out = (float*)d_out;

    void *p;
    #define GET(sym, var) cudaGetSymbolAddress(&p, sym); float* var = (float*)p;
    #define GETI(sym, var) cudaGetSymbolAddress(&p, sym); int* var = (int*)p;
    GET(g_xn1, xn1)  GET(g_wqkv, wqkv) GET(g_qkv, qkv)
    GET(g_qr, qr)    GET(g_kr, kr)     GET(g_vr, vr)     GET(g_sc, sc)
    GET(g_aoh, aoh)  GET(g_ao, ao)     GET(g_hres, hres) GET(g_xn2, xn2)
    GET(g_logits, logits) GET(g_coef, coef)
    GET(g_buf, buf)  GET(g_gg, gg)     GET(g_uu, uu)     GET(g_yy, yy)
    GET(g_sg, sg)    GET(g_su, su)     GET(g_shb, shb)
    GETI(g_topi, topi) GETI(g_pos, pos) GETI(g_cnt, cnt)
    #undef GET
    #undef GETI

    auto gw = [&](const float* A, const float* B, float* C, int M, int N, int K,
                  int lda, int ldb, int ldc, long sA, long sB, long sC, int bDiv,
                  int batch, const int* cc) {
        dim3 grid(N / 128, M / 128, batch);
        mmagemm_k<128, true, false, true><<<grid, 256, SM_W, st>>>(
            A, B, C, K, lda, ldb, ldc, sA, sB, sC, bDiv, cc);
    };

    // ===== attention =====
    rmsnorm_k<<<S_, 256, 0, st>>>(x, wln1, xn1, 1);

    concat_qkv_w<<<(H_ * QKVN_ + 255)/256, 256, 0, st>>>(Wq, Wk, Wv, wqkv);
    gw(xn1, wqkv, qkv, S_, QKVN_, H_, H_, QKVN_, QKVN_, 0,0,0, 1, 1, nullptr);

    rope_k<<<(NH_*S_*HD_ + 255)/256, 256, 0, st>>>(qkv, qr, NH_, QKVN_, 0);
    rope_k<<<(KVH_*S_*HD_ + 255)/256, 256, 0, st>>>(qkv, kr, KVH_, QKVN_, H_);
    transpose_heads_k<<<(KVH_*S_*HD_ + 255)/256, 256, 0, st>>>(qkv, vr, KVH_, QKVN_, H_ + KVH_*HD_);

    {
        dim3 grid(S_/128, S_/128, NH_);
        mmagemm_k<128, false, false, false><<<grid, 256, SM_SCR, st>>>(
            qr, kr, sc, HD_, HD_, HD_, S_,
            (long)S_*HD_, (long)S_*HD_, (long)S_*S_, REP_, nullptr);
    }

    softmax_k<<<dim3(S_, NH_), 256, 0, st>>>(sc, mask);

    {
        dim3 grid(1, S_/128, NH_);
        mmagemm_k<64, true, false, false><<<grid, 256, SM_PV, st>>>(
            sc, vr, aoh, S_, S_, HD_, HD_,
            (long)S_*S_, (long)S_*HD_, (long)S_*HD_, REP_, nullptr);
    }

    merge_heads_k<<<(NH_*S_*HD_ + 255)/256, 256, 0, st>>>(aoh, ao);

    gw(ao, Wo, xn1, S_, H_, H_, H_, H_, H_, 0,0,0, 1, 1, nullptr);
    add_k<<<(S_*H_ + 255)/256, 256, 0, st>>>(x, xn1, hres, (long)S_*H_);

    // ===== MoE =====
    rmsnorm_k<<<S_, 256, 0, st>>>(hres, wln2, xn2, 0);

    sgemm64_k<<<dim3(1, S_/64), 256, 0, st>>>(xn2, Wgate, logits, S_, E_, H_);
    topk_k<<<(S_ + 255)/256, 256, 0, st>>>(logits, topi, coef);
    assign_k<<<E_, 256, 0, st>>>(topi, pos, cnt);

    scatter_k<<<S_*TOPK_, 256, 0, st>>>(xn2, topi, pos, buf);

    gw(buf, Weg, gg, CAP_, ID_, H_, H_, ID_, ID_,
       (long)CAP_*H_, (long)H_*ID_, (long)CAP_*ID_, 1, E_, cnt);
    gw(buf, Weu, uu, CAP_, ID_, H_, H_, ID_, ID_,
       (long)CAP_*H_, (long)H_*ID_, (long)CAP_*ID_, 1, E_, cnt);

    act_expert_k<<<E_ * CAP_, 256, 0, st>>>(gg, uu, cnt);

    gw(gg, Wed, yy, CAP_, H_, ID_, ID_, H_, H_,
       (long)CAP_*ID_, (long)ID_*H_, (long)CAP_*H_, 1, E_, cnt);

    // shared expert
    {
        dim3 grid(ID_/128, S_/128, 1);
        mmagemm_k<128, true, true, true><<<grid, 256, SM_W, st>>>(
            xn2, Wsg, sg, H_, H_, ID_, ID_, 0, 0, 0, 1, nullptr);
        mmagemm_k<128, true, true, true><<<grid, 256, SM_W, st>>>(
            xn2, Wsu, su, H_, H_, ID_, ID_, 0, 0, 0, 1, nullptr);
    }
    { long n = (long)S_*ID_;
      act_k<<<(int)((n + 255)/256), 256, 0, st>>>(sg, su, n); }
    gw(sg, Wsd, shb, S_, H_, ID_, ID_, H_, H_, 0,0,0, 1, 1, nullptr);

    final_k<<<S_, 256, 0, st>>>(hres, shb, yy, topi, pos, coef, out);
}

// round 7
// speedup vs baseline: 6.2919x; 1.1746x over previous
#include <cuda_runtime.h>
#include <cuda_fp16.h>
#include <math.h>
#include <stdint.h>

#define S_    1024
#define H_    1024
#define NH_   16
#define KVH_  4
#define HD_   64
#define REP_  4
#define E_    64
#define TOPK_ 8
#define ID_   1408
#define CAP_  256
#define EPS_  1e-6f
#define QKVN_ (H_ + 2 * KVH_ * HD_)   // 1536

__device__ float g_xn1 [S_ * H_];
__device__ float g_wqkv[H_ * QKVN_];
__device__ float g_qkv [S_ * QKVN_];
__device__ float g_qr  [NH_ * S_ * HD_];
__device__ float g_kr  [KVH_ * S_ * HD_];
__device__ float g_vr  [KVH_ * S_ * HD_];
__device__ float g_sc  [(long)NH_ * S_ * S_];
__device__ float g_aoh [NH_ * S_ * HD_];
__device__ float g_ao  [S_ * H_];
__device__ float g_hres[S_ * H_];
__device__ float g_xn2 [S_ * H_];
__device__ float g_logits[S_ * E_];
__device__ int   g_topi[S_ * TOPK_];
__device__ float g_coef[S_ * TOPK_];
__device__ int   g_pos [S_ * TOPK_];
__device__ int   g_cnt [E_];
__device__ float g_buf [(long)E_ * CAP_ * H_];
__device__ float g_gg  [(long)E_ * CAP_ * ID_];
__device__ float g_uu  [(long)E_ * CAP_ * ID_];
__device__ float g_yy  [(long)E_ * CAP_ * H_];
__device__ float g_sg  [S_ * ID_];
__device__ float g_su  [S_ * ID_];
__device__ float g_shb [S_ * H_];

// ---------- helpers ----------
__device__ __forceinline__ uint32_t smem_u32(const void* p) {
    uint32_t a;
    asm("{ .reg .u64 t; cvta.to.shared.u64 t, %1; cvt.u32.u64 %0, t; }" : "=r"(a) : "l"(p));
    return a;
}
__device__ __forceinline__ uint32_t cvt2h(float lo, float hi) {
    __half2 h = __floats2half2_rn(lo, hi);   // x = lo, y = hi
    return *reinterpret_cast<uint32_t*>(&h);
}
__device__ __forceinline__ void cp16(uint32_t dst, const void* src) {
    asm volatile("cp.async.cg.shared.global [%0], [%1], 16;" :: "r"(dst), "l"(src));
}
__device__ __forceinline__ void cp_commit() { asm volatile("cp.async.commit_group;" ::: "memory"); }
__device__ __forceinline__ void cp_wait(int n) {
    if (n <= 0)      asm volatile("cp.async.wait_group 0;" ::: "memory");
    else if (n == 1) asm volatile("cp.async.wait_group 1;" ::: "memory");
    else             asm volatile("cp.async.wait_group 2;" ::: "memory");
}
__device__ __forceinline__ void mma16816(float* d, const uint32_t* a, const uint32_t* b) {
    asm volatile("mma.sync.aligned.m16n8k16.row.col.f32.f16.f16.f32 "
        "{%0,%1,%2,%3}, {%4,%5,%6,%7}, {%8,%9}, {%0,%1,%2,%3};"
        : "+f"(d[0]), "+f"(d[1]), "+f"(d[2]), "+f"(d[3])
        : "r"(a[0]), "r"(a[1]), "r"(a[2]), "r"(a[3]), "r"(b[0]), "r"(b[1]));
}

// ---------- fp16 mma.sync GEMM (fp32 smem, cvt in fragment load) ----------
// C[M,N] = A[M,K] @ B ; batched by blockIdx.z (strides sA,sB,sC; B index z/bDiv).
// BKMAJ=true : B gmem [K,N] row-major.  BKMAJ=false: B gmem [N,K] row-major (B^T).
// cnt != nullptr: per-batch valid row count; CTAs whose M-tile >= cnt[z] exit.
// M mult of 128, N mult of BN, K mult of 32.
template<int BN, int NST, bool BKMAJ>
__global__ void __launch_bounds__(256, 2) mmagemm_k(
    const float* __restrict__ A, const float* __restrict__ B, float* __restrict__ C,
    int K, int lda, int ldb, int ldc, long sA, long sB, long sC, int bDiv,
    const int* __restrict__ cnt)
{
    constexpr int BM = 128, BK = 32;
    constexpr int LDA  = BK + 8;                 // 40: conflict-free float2 frag loads
    constexpr int LDBK = BN + 4;                 // ≡4 mod 16: conflict-free scalar pairs
    constexpr int A_FL = BM * LDA;
    constexpr int B_FL = BKMAJ ? BK * LDBK : BN * LDA;
    constexpr int STG_FL = A_FL + B_FL;
    constexpr int WGN = BN / 32, WGM = 8 / WGN;
    constexpr int WM  = BM / WGM, MT = WM / 16, NT = 4;

    const int row0 = blockIdx.y * BM;
    if (cnt != nullptr && row0 >= cnt[blockIdx.z]) return;

    extern __shared__ float sm[];
    const int tid = threadIdx.x, wid = tid >> 5, lane = tid & 31;
    const int qrw = lane >> 2, qc = lane & 3;
    A += (long)blockIdx.z * sA;
    B += (long)(blockIdx.z / bDiv) * sB;
    C += (long)blockIdx.z * sC;
    const int col0 = blockIdx.x * BN;
    const int wm0 = (wid / WGN) * WM;
    const int wn0 = (wid % WGN) * 32;
    const int nch = K / BK;

    auto fill = [&](int c) {
        float* As = sm + (c % NST) * STG_FL;
        float* Bs = As + A_FL;
        const int k0 = c * BK;
        const float* Ag = A + (long)row0 * lda + k0;
        #pragma unroll
        for (int i = 0; i < 4; i++) {
            int idx = i * 256 + tid;
            int r = idx >> 3, sg = idx & 7;
            cp16(smem_u32(As + r * LDA + sg * 4), Ag + (long)r * lda + sg * 4);
        }
        if (BKMAJ) {
            const float* Bg = B + (long)k0 * ldb + col0;
            #pragma unroll
            for (int i = 0; i < BN / 32; i++) {
                int idx = i * 256 + tid;
                int r = idx / (BN / 4), sg = idx % (BN / 4);
                cp16(smem_u32(Bs + r * LDBK + sg * 4), Bg + (long)r * ldb + sg * 4);
            }
        } else {
            const float* Bg = B + (long)col0 * ldb + k0;
            #pragma unroll
            for (int i = 0; i < BN / 32; i++) {
                int idx = i * 256 + tid;
                int r = idx >> 3, sg = idx & 7;
                cp16(smem_u32(Bs + r * LDA + sg * 4), Bg + (long)r * ldb + sg * 4);
            }
        }
        cp_commit();
    };

    float acc[MT][NT][4];
    #pragma unroll
    for (int m = 0; m < MT; m++)
        #pragma unroll
        for (int n = 0; n < NT; n++)
            #pragma unroll
            for (int j = 0; j < 4; j++) acc[m][n][j] = 0.f;

    const int PF = NST - 1;
    const int F0 = (nch < PF) ? nch : PF;
    for (int c = 0; c < F0; c++) fill(c);
    int g = F0;

    for (int c = 0; c < nch; c++) {
        cp_wait(g - (c + 1));
        __syncthreads();
        if (c + PF < nch) { fill(c + PF); g++; }

        const float* As = sm + (c % NST) * STG_FL;
        const float* Bs = As + A_FL;
        #pragma unroll
        for (int ks = 0; ks < 2; ks++) {
            const int kk = ks * 16;
            uint32_t af[MT][4], bf[NT][2];
            #pragma unroll
            for (int mt = 0; mt < MT; mt++) {
                const float* ap = As + (wm0 + mt * 16 + qrw) * LDA + kk + 2 * qc;
                float2 v0 = *reinterpret_cast<const float2*>(ap);
                float2 v1 = *reinterpret_cast<const float2*>(ap + 8 * LDA);
                float2 v2 = *reinterpret_cast<const float2*>(ap + 8);
                float2 v3 = *reinterpret_cast<const float2*>(ap + 8 * LDA + 8);
                af[mt][0] = cvt2h(v0.x, v0.y);
                af[mt][1] = cvt2h(v1.x, v1.y);
                af[mt][2] = cvt2h(v2.x, v2.y);
                af[mt][3] = cvt2h(v3.x, v3.y);
            }
            #pragma unroll
            for (int nt = 0; nt < NT; nt++) {
                if (BKMAJ) {
                    const float* bp = Bs + (kk + 2 * qc) * LDBK + wn0 + nt * 8 + qrw;
                    bf[nt][0] = cvt2h(bp[0], bp[LDBK]);
                    bf[nt][1] = cvt2h(bp[8 * LDBK], bp[9 * LDBK]);
                } else {
                    const float* bp = Bs + (wn0 + nt * 8 + qrw) * LDA + kk + 2 * qc;
                    float2 w0 = *reinterpret_cast<const float2*>(bp);
                    float2 w1 = *reinterpret_cast<const float2*>(bp + 8);
                    bf[nt][0] = cvt2h(w0.x, w0.y);
                    bf[nt][1] = cvt2h(w1.x, w1.y);
                }
            }
            #pragma unroll
            for (int mt = 0; mt < MT; mt++)
                #pragma unroll
                for (int nt = 0; nt < NT; nt++)
                    mma16816(acc[mt][nt], af[mt], bf[nt]);
        }
    }

    #pragma unroll
    for (int mt = 0; mt < MT; mt++) {
        const int r = row0 + wm0 + mt * 16 + qrw;
        #pragma unroll
        for (int nt = 0; nt < NT; nt++) {
            const int cc = col0 + wn0 + nt * 8 + qc * 2;
            *reinterpret_cast<float2*>(C + (long)r * ldc + cc) =
                make_float2(acc[mt][nt][0], acc[mt][nt][1]);
            *reinterpret_cast<float2*>(C + (long)(r + 8) * ldc + cc) =
                make_float2(acc[mt][nt][2], acc[mt][nt][3]);
        }
    }
}

// ---------- exact fp32 gemm for gate logits ----------
__global__ void sgemm64_k(const float* __restrict__ A, const float* __restrict__ B,
                          float* __restrict__ C, int M, int N, int K)
{
    const int tid = threadIdx.x;
    const int row0 = blockIdx.y * 64, col0 = blockIdx.x * 64;
    __shared__ float As[16][68];
    __shared__ float Bs[16][68];
    float acc[4][4] = {};
    const int tRow = (tid / 16) * 4, tCol = (tid % 16) * 4;
    const int aRow = tid / 4, aK = (tid % 4) * 4;
    const int bR = tid / 16, bC = (tid % 16) * 4;
    for (int k0 = 0; k0 < K; k0 += 16) {
        {
            int gr = row0 + aRow, gk = k0 + aK;
            float4 v = make_float4(0,0,0,0);
            if (gr < M && gk + 3 < K) v = *reinterpret_cast<const float4*>(A + (long)gr*K + gk);
            As[aK+0][aRow]=v.x; As[aK+1][aRow]=v.y; As[aK+2][aRow]=v.z; As[aK+3][aRow]=v.w;
        }
        {
            int gk = k0 + bR, gn = col0 + bC;
            float4 v = make_float4(0,0,0,0);
            if (gk < K && gn + 3 < N) v = *reinterpret_cast<const float4*>(B + (long)gk*N + gn);
            *reinterpret_cast<float4*>(&Bs[bR][bC]) = v;
        }
        __syncthreads();
        #pragma unroll
        for (int k = 0; k < 16; k++) {
            float rA[4], rB[4];
            #pragma unroll
            for (int m = 0; m < 4; m++) rA[m] = As[k][tRow+m];
            #pragma unroll
            for (int n = 0; n < 4; n++) rB[n] = Bs[k][tCol+n];
            #pragma unroll
            for (int m = 0; m < 4; m++)
                #pragma unroll
                for (int n = 0; n < 4; n++) acc[m][n] += rA[m]*rB[n];
        }
        __syncthreads();
    }
    #pragma unroll
    for (int m = 0; m < 4; m++) {
        int gr = row0 + tRow + m;
        if (gr >= M) continue;
        #pragma unroll
        for (int n = 0; n < 4; n++) {
            int gc = col0 + tCol + n;
            if (gc < N) C[(long)gr*N + gc] = acc[m][n];
        }
    }
}

// ---------- reductions ----------
__device__ __forceinline__ float warpSum(float v) {
    #pragma unroll
    for (int o = 16; o; o >>= 1) v += __shfl_xor_sync(0xffffffffu, v, o);
    return v;
}
__device__ __forceinline__ float warpMax(float v) {
    #pragma unroll
    for (int o = 16; o; o >>= 1) v = fmaxf(v, __shfl_xor_sync(0xffffffffu, v, o));
    return v;
}
__device__ float blockSum(float v) {
    __shared__ float sh[32]; __shared__ float tot;
    int lane = threadIdx.x & 31, wid = threadIdx.x >> 5;
    v = warpSum(v);
    if (lane == 0) sh[wid] = v;
    __syncthreads();
    int nw = (blockDim.x + 31) >> 5;
    float w = (threadIdx.x < nw) ? sh[threadIdx.x] : 0.f;
    if (wid == 0) { w = warpSum(w); if (lane == 0) tot = w; }
    __syncthreads();
    float r = tot; __syncthreads(); return r;
}
__device__ float blockMax(float v) {
    __shared__ float sh[32]; __shared__ float tot;
    int lane = threadIdx.x & 31, wid = threadIdx.x >> 5;
    v = warpMax(v);
    if (lane == 0) sh[wid] = v;
    __syncthreads();
    int nw = (blockDim.x + 31) >> 5;
    float w = (threadIdx.x < nw) ? sh[threadIdx.x] : -1e30f;
    if (wid == 0) { w = warpMax(w); if (lane == 0) tot = w; }
    __syncthreads();
    float r = tot; __syncthreads(); return r;
}

// ---------- small kernels ----------
__global__ void concat_qkv_w(const float* __restrict__ Wq, const float* __restrict__ Wk,
                             const float* __restrict__ Wv, float* __restrict__ W)
{
    int idx = blockIdx.x * blockDim.x + threadIdx.x;
    if (idx >= H_ * QKVN_) return;
    int r = idx / QKVN_, c = idx % QKVN_;
    float v;
    if (c < H_)                 v = Wq[(long)r * H_ + c];
    else if (c < H_ + KVH_*HD_) v = Wk[(long)r * (KVH_*HD_) + (c - H_)];
    else                        v = Wv[(long)r * (KVH_*HD_) + (c - H_ - KVH_*HD_)];
    W[idx] = v;
}

__global__ void rmsnorm_k(const float* __restrict__ x, const float* __restrict__ w,
                          float* __restrict__ y)
{
    int t = blockIdx.x;
    const float* xr = x + (long)t * H_;
    float s = 0.f;
    for (int i = threadIdx.x; i < H_; i += blockDim.x) { float v = xr[i]; s += v * v; }
    s = blockSum(s);
    float inv = rsqrtf(s / (float)H_ + EPS_);
    for (int i = threadIdx.x; i < H_; i += blockDim.x)
        y[(long)t * H_ + i] = xr[i] * inv * w[i];
}

__global__ void rope_k(const float* __restrict__ src, float* __restrict__ dst,
                       int nh, int ld, int off)
{
    int idx = blockIdx.x * blockDim.x + threadIdx.x;
    if (idx >= nh * S_ * HD_) return;
    int d = idx % HD_;
    int s = (idx / HD_) % S_;
    int h = idx / (HD_ * S_);
    const float* p = src + (long)s * ld + off + h * HD_;
    float v  = p[d];
    float pr = (d < HD_/2) ? -p[d + HD_/2] : p[d - HD_/2];
    int i = d & (HD_/2 - 1);
    float inv = expf(-(float)i * (9.210340371976184f / (HD_/2)));
    float ang = (float)s * inv, sn, cs;
    sincosf(ang, &sn, &cs);
    dst[((long)h * S_ + s) * HD_ + d] = v * cs + pr * sn;
}

__global__ void transpose_heads_k(const float* __restrict__ src, float* __restrict__ dst,
                                  int nh, int ld, int off)
{
    int idx = blockIdx.x * blockDim.x + threadIdx.x;
    if (idx >= nh * S_ * HD_) return;
    int d = idx % HD_;
    int s = (idx / HD_) % S_;
    int h = idx / (HD_ * S_);
    dst[((long)h * S_ + s) * HD_ + d] = src[(long)s * ld + off + h * HD_ + d];
}

__global__ void merge_heads_k(const float* __restrict__ src, float* __restrict__ dst)
{
    int idx = blockIdx.x * blockDim.x + threadIdx.x;
    if (idx >= NH_ * S_ * HD_) return;
    int d = idx % HD_;
    int s = (idx / HD_) % S_;
    int h = idx / (HD_ * S_);
    dst[(long)s * H_ + h * HD_ + d] = src[((long)h * S_ + s) * HD_ + d];
}

// single-pass masked softmax: row cached in registers
__global__ void softmax_k(float* __restrict__ sc, const float* __restrict__ mask)
{
    int r = blockIdx.x, h = blockIdx.y;
    float4* row = reinterpret_cast<float4*>(sc + ((long)h * S_ + r) * S_);
    const float4* mr = reinterpret_cast<const float4*>(mask + (long)r * S_);
    int j = threadIdx.x;             // 256 threads x float4 = 1024
    float4 v = row[j], m = mr[j];
    v.x = v.x * 0.125f + m.x;
    v.y = v.y * 0.125f + m.y;
    v.z = v.z * 0.125f + m.z;
    v.w = v.w * 0.125f + m.w;
    float mx = fmaxf(fmaxf(v.x, v.y), fmaxf(v.z, v.w));
    mx = blockMax(mx);
    v.x = expf(v.x - mx); v.y = expf(v.y - mx);
    v.z = expf(v.z - mx); v.w = expf(v.w - mx);
    float sum = v.x + v.y + v.z + v.w;
    sum = blockSum(sum);
    float inv = 1.f / sum;
    v.x *= inv; v.y *= inv; v.z *= inv; v.w *= inv;
    row[j] = v;
}

__global__ void add_k(const float* __restrict__ a, const float* __restrict__ b,
                      float* __restrict__ c, long n)
{
    long i = (long)blockIdx.x * blockDim.x + threadIdx.x;
    if (i < n) c[i] = a[i] + b[i];
}

__global__ void topk_k(const float* __restrict__ logits, int* __restrict__ topi,
                       float* __restrict__ coef)
{
    int t = blockIdx.x * blockDim.x + threadIdx.x;
    if (t >= S_) return;
    const float* lr = logits + (long)t * E_;
    unsigned long long sel = 0ull;
    float tv[TOPK_]; int ti[TOPK_];
    for (int k = 0; k < TOPK_; k++) {
        float best = -1e30f; int bi = 0;
        for (int e = 0; e < E_; e++) {
            if ((sel >> e) & 1ull) continue;
            float v = lr[e];
            if (v > best) { best = v; bi = e; }
        }
        sel |= 1ull << bi;
        tv[k] = best; ti[k] = bi;
    }
    float mx = tv[0], ex[TOPK_], sum = 0.f;
    for (int k = 0; k < TOPK_; k++) { ex[k] = expf(tv[k] - mx); sum += ex[k]; }
    float inv = 1.f / sum;
    for (int k = 0; k < TOPK_; k++) { topi[t*TOPK_+k] = ti[k]; coef[t*TOPK_+k] = ex[k]*inv; }
}

__global__ void assign_k(const int* __restrict__ topi, int* __restrict__ pos,
                         int* __restrict__ cnt)
{
    const int e = blockIdx.x;
    __shared__ int sdata[256];
    int base = 0;
    for (int chunk = 0; chunk < S_ * TOPK_; chunk += 256) {
        int i = chunk + threadIdx.x;
        int p = (topi[i] == e) ? 1 : 0;
        sdata[threadIdx.x] = p;
        __syncthreads();
        #pragma unroll
        for (int off = 1; off < 256; off <<= 1) {
            int v = (threadIdx.x >= off) ? sdata[threadIdx.x - off] : 0;
            __syncthreads();
            sdata[threadIdx.x] += v;
            __syncthreads();
        }
        if (p) pos[i] = base + sdata[threadIdx.x] - 1;
        base += sdata[255];
        __syncthreads();
    }
    if (threadIdx.x == 0) cnt[e] = (base < CAP_) ? base : CAP_;
}

__global__ void scatter_k(const float* __restrict__ xn2, const int* __restrict__ topi,
                          const int* __restrict__ pos, float* __restrict__ buf)
{
    int i = blockIdx.x;
    int p = pos[i];
    if (p >= CAP_) return;
    int e = topi[i];
    int t = i >> 3;
    const float4* src = reinterpret_cast<const float4*>(xn2 + (long)t * H_);
    float4* dst = reinterpret_cast<float4*>(buf + ((long)e * CAP_ + p) * H_);
    dst[threadIdx.x] = src[threadIdx.x];
}

// expert activation: one block per (expert, cap-row); skip rows >= cnt[e]
__global__ void act_expert_k(float* __restrict__ g, const float* __restrict__ u,
                             const int* __restrict__ cnt)
{
    int e = blockIdx.x >> 8, c = blockIdx.x & 255;
    if (c >= cnt[e]) return;
    long base = ((long)e * CAP_ + c) * ID_;
    for (int j = threadIdx.x; j < ID_; j += blockDim.x) {
        float x = g[base + j];
        g[base + j] = (x / (1.f + expf(-x))) * u[base + j];
    }
}

__global__ void act_k(float* __restrict__ g, const float* __restrict__ u, long n)
{
    long i = (long)blockIdx.x * blockDim.x + threadIdx.x;
    if (i < n) {
        float x = g[i];
        g[i] = (x / (1.f + expf(-x))) * u[i];
    }
}

__global__ void final_k(const float* __restrict__ hres, const float* __restrict__ shb,
                        const float* __restrict__ y, const int* __restrict__ topi,
                        const int* __restrict__ pos, const float* __restrict__ coef,
                        float* __restrict__ out)
{
    int t = blockIdx.x, j = threadIdx.x;
    float4 a = reinterpret_cast<const float4*>(hres)[(long)t*256 + j];
    float4 b = reinterpret_cast<const float4*>(shb)[(long)t*256 + j];
    a.x += b.x; a.y += b.y; a.z += b.z; a.w += b.w;
    #pragma unroll
    for (int k = 0; k < TOPK_; k++) {
        int idx = t * TOPK_ + k;
        int p = pos[idx];
        if (p < CAP_) {
            float c = coef[idx];
            float4 v = reinterpret_cast<const float4*>(y)[((long)topi[idx]*CAP_ + p)*256 + j];
            a.x += c*v.x; a.y += c*v.y; a.z += c*v.z; a.w += c*v.w;
        }
    }
    reinterpret_cast<float4*>(out)[(long)t*256 + j] = a;
}

// ---------- host-side smem size (mirror of kernel constexpr) ----------
static int smemBytes(int BN, int NST, bool bkmaj) {
    int A_FL = 128 * 40;
    int B_FL = bkmaj ? 32 * (BN + 4) : BN * 40;
    return NST * (A_FL + B_FL) * 4;
}

extern "C" void kernel_launch(void* const* d_in, const int* in_sizes, int n_in,
                              void* d_out, int out_size)
{
    (void)in_sizes; (void)n_in; (void)out_size;
    cudaStream_t st = 0;

    const int SM_W   = smemBytes(128, 3, true);    // 112,128 B
    const int SM_SCR = smemBytes(128, 2, false);   //  81,920 B
    const int SM_PV  = smemBytes(64,  3, true);    //  87,552 B
    cudaFuncSetAttribute(mmagemm_k<128, 3, true >, cudaFuncAttributeMaxDynamicSharedMemorySize, SM_W);
    cudaFuncSetAttribute(mmagemm_k<128, 2, false>, cudaFuncAttributeMaxDynamicSharedMemorySize, SM_SCR);
    cudaFuncSetAttribute(mmagemm_k<64,  3, true >, cudaFuncAttributeMaxDynamicSharedMemorySize, SM_PV);

    const float* x     = (const float*)d_in[0];
    const float* mask  = (const float*)d_in[1];
    const float* wln1  = (const float*)d_in[2];
    const float* wln2  = (const float*)d_in[3];
    const float* Wq    = (const float*)d_in[4];
    const float* Wk    = (const float*)d_in[5];
    const float* Wv    = (const float*)d_in[6];
    const float* Wo    = (const float*)d_in[7];
    const float* Wgate = (const float*)d_in[8];
    const float* Weg   = (const float*)d_in[9];
    const float* Weu   = (const float*)d_in[10];
    const float* Wed   = (const float*)d_in[11];
    const float* Wsg   = (const float*)d_in[12];
    const float* Wsu   = (const float*)d_in[13];
    const float* Wsd   = (const float*)d_in[14];
    float* out = (float*)d_out;

    void *p;
    #define GET(sym, var) cudaGetSymbolAddress(&p, sym); float* var = (float*)p;
    #define GETI(sym, var) cudaGetSymbolAddress(&p, sym); int* var = (int*)p;
    GET(g_xn1, xn1)  GET(g_wqkv, wqkv) GET(g_qkv, qkv)
    GET(g_qr, qr)    GET(g_kr, kr)     GET(g_vr, vr)     GET(g_sc, sc)
    GET(g_aoh, aoh)  GET(g_ao, ao)     GET(g_hres, hres) GET(g_xn2, xn2)
    GET(g_logits, logits) GET(g_coef, coef)
    GET(g_buf, buf)  GET(g_gg, gg)     GET(g_uu, uu)     GET(g_yy, yy)
    GET(g_sg, sg)    GET(g_su, su)     GET(g_shb, shb)
    GETI(g_topi, topi) GETI(g_pos, pos) GETI(g_cnt, cnt)
    #undef GET
    #undef GETI

    auto gw = [&](const float* A, const float* B, float* C, int M, int N, int K,
                  int lda, int ldb, int ldc, long sA, long sB, long sC, int bDiv,
                  int batch, const int* cc) {
        dim3 grid(N / 128, M / 128, batch);
        mmagemm_k<128, 3, true><<<grid, 256, SM_W, st>>>(
            A, B, C, K, lda, ldb, ldc, sA, sB, sC, bDiv, cc);
    };

    // ===== attention =====
    rmsnorm_k<<<S_, 256, 0, st>>>(x, wln1, xn1);

    concat_qkv_w<<<(H_ * QKVN_ + 255)/256, 256, 0, st>>>(Wq, Wk, Wv, wqkv);
    gw(xn1, wqkv, qkv, S_, QKVN_, H_, H_, QKVN_, QKVN_, 0,0,0, 1, 1, nullptr);

    rope_k<<<(NH_*S_*HD_ + 255)/256, 256, 0, st>>>(qkv, qr, NH_, QKVN_, 0);
    rope_k<<<(KVH_*S_*HD_ + 255)/256, 256, 0, st>>>(qkv, kr, KVH_, QKVN_, H_);
    transpose_heads_k<<<(KVH_*S_*HD_ + 255)/256, 256, 0, st>>>(qkv, vr, KVH_, QKVN_, H_ + KVH_*HD_);

    // scores[h] = qr[h] @ kr[h/4]^T : B = kr ([N,K] row-major), K=64 -> 2 stages
    {
        dim3 grid(S_/128, S_/128, NH_);
        mmagemm_k<128, 2, false><<<grid, 256, SM_SCR, st>>>(
            qr, kr, sc, HD_, HD_, HD_, S_,
            (long)S_*HD_, (long)S_*HD_, (long)S_*S_, REP_, nullptr);
    }

    softmax_k<<<dim3(S_, NH_), 256, 0, st>>>(sc, mask);

    // aoh[h] = probs[h] @ vr[h/4] : B = vr ([K,N]=[S,HD] row-major), N=64
    {
        dim3 grid(1, S_/128, NH_);
        mmagemm_k<64, 3, true><<<grid, 256, SM_PV, st>>>(
            sc, vr, aoh, S_, S_, HD_, HD_,
            (long)S_*S_, (long)S_*HD_, (long)S_*HD_, REP_, nullptr);
    }

    merge_heads_k<<<(NH_*S_*HD_ + 255)/256, 256, 0, st>>>(aoh, ao);

    gw(ao, Wo, xn1, S_, H_, H_, H_, H_, H_, 0,0,0, 1, 1, nullptr);
    add_k<<<(S_*H_ + 255)/256, 256, 0, st>>>(x, xn1, hres, (long)S_*H_);

    // ===== MoE =====
    rmsnorm_k<<<S_, 256, 0, st>>>(hres, wln2, xn2);

    sgemm64_k<<<dim3(1, S_/64), 256, 0, st>>>(xn2, Wgate, logits, S_, E_, H_);
    topk_k<<<(S_ + 255)/256, 256, 0, st>>>(logits, topi, coef);
    assign_k<<<E_, 256, 0, st>>>(topi, pos, cnt);

    scatter_k<<<S_*TOPK_, 256, 0, st>>>(xn2, topi, pos, buf);

    gw(buf, Weg, gg, CAP_, ID_, H_, H_, ID_, ID_,
       (long)CAP_*H_, (long)H_*ID_, (long)CAP_*ID_, 1, E_, cnt);
    gw(buf, Weu, uu, CAP_, ID_, H_, H_, ID_, ID_,
       (long)CAP_*H_, (long)H_*ID_, (long)CAP_*ID_, 1, E_, cnt);

    act_expert_k<<<E_ * CAP_, 256, 0, st>>>(gg, uu, cnt);

    gw(gg, Wed, yy, CAP_, H_, ID_, ID_, H_, H_,
       (long)CAP_*ID_, (long)ID_*H_, (long)CAP_*H_, 1, E_, cnt);

    // shared expert
    gw(xn2, Wsg, sg, S_, ID_, H_, H_, ID_, ID_, 0,0,0, 1, 1, nullptr);
    gw(xn2, Wsu, su, S_, ID_, H_, H_, ID_, ID_, 0,0,0, 1, 1, nullptr);
    { long n = (long)S_*ID_;
      act_k<<<(int)((n + 255)/256), 256, 0, st>>>(sg, su, n); }
    gw(sg, Wsd, shb, S_, H_, ID_, ID_, H_, H_, 0,0,0, 1, 1, nullptr);

    final_k<<<S_, 256, 0, st>>>(hres, shb, yy, topi, pos, coef, out);
}

// round 9
// speedup vs baseline: 6.8690x; 1.0917x over previous
#include <cuda_runtime.h>
#include <cuda_fp16.h>
#include <math.h>
#include <stdint.h>

#define S_    1024
#define H_    1024
#define NH_   16
#define KVH_  4
#define HD_   64
#define REP_  4
#define E_    64
#define TOPK_ 8
#define ID_   1408
#define CAP_  256
#define EPS_  1e-6f
#define QKVN_ (H_ + 2 * KVH_ * HD_)   // 1536

// fp32 scratch
__device__ float g_xn1 [S_ * H_];
__device__ float g_wqkv[H_ * QKVN_];
__device__ float g_qkv [S_ * QKVN_];
__device__ float g_sc  [(long)NH_ * S_ * S_];
__device__ float g_aoh [NH_ * S_ * HD_];
__device__ float g_hres[S_ * H_];
__device__ float g_xn2 [S_ * H_];
__device__ float g_logits[S_ * E_];
__device__ float g_coef[S_ * TOPK_];
__device__ float g_gg  [(long)E_ * CAP_ * ID_];
__device__ float g_uu  [(long)E_ * CAP_ * ID_];
__device__ float g_yy  [(long)E_ * CAP_ * H_];
__device__ float g_sg  [S_ * ID_];
__device__ float g_su  [S_ * ID_];
__device__ float g_shb [S_ * H_];
__device__ int   g_topi[S_ * TOPK_];
__device__ int   g_pos [S_ * TOPK_];
__device__ int   g_cnt [E_];
// fp16 activation scratch (GEMM operands)
__device__ __half h_xn1[S_ * H_];
__device__ __half h_xn2[S_ * H_];
__device__ __half h_qr [NH_ * S_ * HD_];
__device__ __half h_kr [KVH_ * S_ * HD_];
__device__ __half h_vt [KVH_ * HD_ * S_];   // transposed V: [h][d][s]
__device__ __half h_sc [(long)NH_ * S_ * S_];
__device__ __half h_ao [S_ * H_];
__device__ __half h_buf[(long)E_ * CAP_ * H_];
__device__ __half h_gg [(long)E_ * CAP_ * ID_];
__device__ __half h_sg [S_ * ID_];

// ---------- helpers ----------
__device__ __forceinline__ uint32_t smem_u32(const void* p) {
    uint32_t a;
    asm("{ .reg .u64 t; cvta.to.shared.u64 t, %1; cvt.u32.u64 %0, t; }" : "=r"(a) : "l"(p));
    return a;
}
__device__ __forceinline__ uint32_t cvt2h(float lo, float hi) {
    __half2 h = __floats2half2_rn(lo, hi);
    return *reinterpret_cast<uint32_t*>(&h);
}
__device__ __forceinline__ void cp16(uint32_t dst, const void* src) {
    asm volatile("cp.async.cg.shared.global [%0], [%1], 16;" :: "r"(dst), "l"(src));
}
__device__ __forceinline__ void cp_commit() { asm volatile("cp.async.commit_group;" ::: "memory"); }
__device__ __forceinline__ void cp_wait(int n) {
    if (n <= 0)      asm volatile("cp.async.wait_group 0;" ::: "memory");
    else if (n == 1) asm volatile("cp.async.wait_group 1;" ::: "memory");
    else if (n == 2) asm volatile("cp.async.wait_group 2;" ::: "memory");
    else             asm volatile("cp.async.wait_group 3;" ::: "memory");
}
__device__ __forceinline__ void mma16816(float* d, const uint32_t* a, const uint32_t* b) {
    asm volatile("mma.sync.aligned.m16n8k16.row.col.f32.f16.f16.f32 "
        "{%0,%1,%2,%3}, {%4,%5,%6,%7}, {%8,%9}, {%0,%1,%2,%3};"
        : "+f"(d[0]), "+f"(d[1]), "+f"(d[2]), "+f"(d[3])
        : "r"(a[0]), "r"(a[1]), "r"(a[2]), "r"(a[3]), "r"(b[0]), "r"(b[1]));
}

// ---------- fp16 GEMM: A half (gmem+smem), B either fp32 [K,N] (weights, cvt
// in-register) or half [N,K] N-major (activations). C fp32.
// Batched by blockIdx.z. M mult of 128, N mult of BN, K mult of 32.
template<int BN, int NST, bool BHALF>
__global__ void __launch_bounds__(256, 2) hgemm_k(
    const __half* __restrict__ A, const void* __restrict__ Bv, float* __restrict__ C,
    int K, int lda, int ldb, int ldc, long sA, long sB, long sC, int bDiv,
    const int* __restrict__ cnt)
{
    constexpr int BM = 128, BK = 32;
    constexpr int LDA  = 40;                    // halves; conflict-free LDS.32
    constexpr int LDBF = BN + 4;                // floats (fp32 weight tile)
    constexpr int A_BY = BM * LDA * 2;          // 10240 B
    constexpr int B_BY = BHALF ? BN * 40 * 2 : BK * LDBF * 4;
    constexpr int STG_BY = A_BY + B_BY;
    constexpr int WGN = BN / 32, WGM = 8 / WGN;
    constexpr int WM  = BM / WGM, MT = WM / 16, NT = 4;

    const int row0 = blockIdx.y * BM;
    if (cnt != nullptr && row0 >= cnt[blockIdx.z]) return;

    extern __shared__ char sm[];
    const int tid = threadIdx.x, wid = tid >> 5, lane = tid & 31;
    const int qrw = lane >> 2, qc = lane & 3;
    A += (long)blockIdx.z * sA;
    const __half* Bh = BHALF ? (const __half*)Bv + (long)(blockIdx.z / bDiv) * sB : nullptr;
    const float*  Bf = BHALF ? nullptr : (const float*)Bv + (long)(blockIdx.z / bDiv) * sB;
    C += (long)blockIdx.z * sC;
    const int col0 = blockIdx.x * BN;
    const int wm0 = (wid / WGN) * WM;
    const int wn0 = (wid % WGN) * 32;
    const int nch = K / BK;

    auto fill = [&](int c) {
        char* Ss = sm + (c % NST) * STG_BY;
        __half* As = (__half*)Ss;
        const int k0 = c * BK;
        const __half* Ag = A + (long)row0 * lda + k0;
        #pragma unroll
        for (int i = 0; i < 2; i++) {               // 128 rows x 4 x 8 halves = 512 xfers
            int idx = i * 256 + tid;
            int r = idx >> 2, sg = idx & 3;
            cp16(smem_u32(As + r * LDA + sg * 8), Ag + (long)r * lda + sg * 8);
        }
        if (BHALF) {
            __half* Bs = (__half*)(Ss + A_BY);
            const __half* Bg = Bh + (long)col0 * ldb + k0;
            #pragma unroll
            for (int i = 0; i < BN / 64; i++) {     // BN rows x 4 x 8 halves = BN*4 xfers
                int idx = i * 256 + tid;
                int r = idx >> 2, sg = idx & 3;
                cp16(smem_u32(Bs + r * 40 + sg * 8), Bg + (long)r * ldb + sg * 8);
            }
        } else {
            float* Bs = (float*)(Ss + A_BY);
            const float* Bg = Bf + (long)k0 * ldb + col0;
            #pragma unroll
            for (int i = 0; i < BN / 32; i++) {     // 32 rows x BN/4 float4
                int idx = i * 256 + tid;
                int r = idx / (BN / 4), sg = idx % (BN / 4);
                cp16(smem_u32(Bs + r * LDBF + sg * 4), Bg + (long)r * ldb + sg * 4);
            }
        }
        cp_commit();
    };

    float acc[MT][NT][4];
    #pragma unroll
    for (int m = 0; m < MT; m++)
        #pragma unroll
        for (int n = 0; n < NT; n++)
            #pragma unroll
            for (int j = 0; j < 4; j++) acc[m][n][j] = 0.f;

    const int PF = NST - 1;
    const int F0 = (nch < PF) ? nch : PF;
    for (int c = 0; c < F0; c++) fill(c);
    int g = F0;

    for (int c = 0; c < nch; c++) {
        cp_wait(g - (c + 1));
        __syncthreads();
        if (c + PF < nch) { fill(c + PF); g++; }

        const char* Ss = sm + (c % NST) * STG_BY;
        const __half* As = (const __half*)Ss;
        #pragma unroll
        for (int ks = 0; ks < 2; ks++) {
            const int kk = ks * 16;
            uint32_t af[MT][4], bf[NT][2];
            #pragma unroll
            for (int mt = 0; mt < MT; mt++) {
                const __half* ap = As + (wm0 + mt * 16 + qrw) * LDA + kk + 2 * qc;
                af[mt][0] = *(const uint32_t*)ap;
                af[mt][1] = *(const uint32_t*)(ap + 8 * LDA);
                af[mt][2] = *(const uint32_t*)(ap + 8);
                af[mt][3] = *(const uint32_t*)(ap + 8 * LDA + 8);
            }
            #pragma unroll
            for (int nt = 0; nt < NT; nt++) {
                if (BHALF) {
                    const __half* bp = (const __half*)(Ss + A_BY)
                                     + (wn0 + nt * 8 + qrw) * 40 + kk + 2 * qc;
                    bf[nt][0] = *(const uint32_t*)bp;
                    bf[nt][1] = *(const uint32_t*)(bp + 8);
                } else {
                    const float* bp = (const float*)(Ss + A_BY)
                                    + (kk + 2 * qc) * LDBF + wn0 + nt * 8 + qrw;
                    bf[nt][0] = cvt2h(bp[0], bp[LDBF]);
                    bf[nt][1] = cvt2h(bp[8 * LDBF], bp[9 * LDBF]);
                }
            }
            #pragma unroll
            for (int mt = 0; mt < MT; mt++)
                #pragma unroll
                for (int nt = 0; nt < NT; nt++)
                    mma16816(acc[mt][nt], af[mt], bf[nt]);
        }
    }

    #pragma unroll
    for (int mt = 0; mt < MT; mt++) {
        const int r = row0 + wm0 + mt * 16 + qrw;
        #pragma unroll
        for (int nt = 0; nt < NT; nt++) {
            const int cc = col0 + wn0 + nt * 8 + qc * 2;
            *reinterpret_cast<float2*>(C + (long)r * ldc + cc) =
                make_float2(acc[mt][nt][0], acc[mt][nt][1]);
            *reinterpret_cast<float2*>(C + (long)(r + 8) * ldc + cc) =
                make_float2(acc[mt][nt][2], acc[mt][nt][3]);
        }
    }
}

// ---------- exact fp32 gemm for gate logits ----------
__global__ void sgemm64_k(const float* __restrict__ A, const float* __restrict__ B,
                          float* __restrict__ C, int M, int N, int K)
{
    const int tid = threadIdx.x;
    const int row0 = blockIdx.y * 64, col0 = blockIdx.x * 64;
    __shared__ float As[16][68];
    __shared__ float Bs[16][68];
    float acc[4][4] = {};
    const int tRow = (tid / 16) * 4, tCol = (tid % 16) * 4;
    const int aRow = tid / 4, aK = (tid % 4) * 4;
    const int bR = tid / 16, bC = (tid % 16) * 4;
    for (int k0 = 0; k0 < K; k0 += 16) {
        {
            int gr = row0 + aRow, gk = k0 + aK;
            float4 v = make_float4(0,0,0,0);
            if (gr < M && gk + 3 < K) v = *reinterpret_cast<const float4*>(A + (long)gr*K + gk);
            As[aK+0][aRow]=v.x; As[aK+1][aRow]=v.y; As[aK+2][aRow]=v.z; As[aK+3][aRow]=v.w;
        }
        {
            int gk = k0 + bR, gn = col0 + bC;
            float4 v = make_float4(0,0,0,0);
            if (gk < K && gn + 3 < N) v = *reinterpret_cast<const float4*>(B + (long)gk*N + gn);
            *reinterpret_cast<float4*>(&Bs[bR][bC]) = v;
        }
        __syncthreads();
        #pragma unroll
        for (int k = 0; k < 16; k++) {
            float rA[4], rB[4];
            #pragma unroll
            for (int m = 0; m < 4; m++) rA[m] = As[k][tRow+m];
            #pragma unroll
            for (int n = 0; n < 4; n++) rB[n] = Bs[k][tCol+n];
            #pragma unroll
            for (int m = 0; m < 4; m++)
                #pragma unroll
                for (int n = 0; n < 4; n++) acc[m][n] += rA[m]*rB[n];
        }
        __syncthreads();
    }
    #pragma unroll
    for (int m = 0; m < 4; m++) {
        int gr = row0 + tRow + m;
        if (gr >= M) continue;
        #pragma unroll
        for (int n = 0; n < 4; n++) {
            int gc = col0 + tCol + n;
            if (gc < N) C[(long)gr*N + gc] = acc[m][n];
        }
    }
}

// ---------- reductions ----------
__device__ __forceinline__ float warpSum(float v) {
    #pragma unroll
    for (int o = 16; o; o >>= 1) v += __shfl_xor_sync(0xffffffffu, v, o);
    return v;
}
__device__ __forceinline__ float warpMax(float v) {
    #pragma unroll
    for (int o = 16; o; o >>= 1) v = fmaxf(v, __shfl_xor_sync(0xffffffffu, v, o));
    return v;
}
__device__ float blockSum(float v) {
    __shared__ float sh[32]; __shared__ float tot;
    int lane = threadIdx.x & 31, wid = threadIdx.x >> 5;
    v = warpSum(v);
    if (lane == 0) sh[wid] = v;
    __syncthreads();
    int nw = (blockDim.x + 31) >> 5;
    float w = (threadIdx.x < nw) ? sh[threadIdx.x] : 0.f;
    if (wid == 0) { w = warpSum(w); if (lane == 0) tot = w; }
    __syncthreads();
    float r = tot; __syncthreads(); return r;
}
__device__ float blockMax(float v) {
    __shared__ float sh[32]; __shared__ float tot;
    int lane = threadIdx.x & 31, wid = threadIdx.x >> 5;
    v = warpMax(v);
    if (lane == 0) sh[wid] = v;
    __syncthreads();
    int nw = (blockDim.x + 31) >> 5;
    float w = (threadIdx.x < nw) ? sh[threadIdx.x] : -1e30f;
    if (wid == 0) { w = warpMax(w); if (lane == 0) tot = w; }
    __syncthreads();
    float r = tot; __syncthreads(); return r;
}

// ---------- small kernels ----------
__global__ void concat_qkv_w(const float* __restrict__ Wq, const float* __restrict__ Wk,
                             const float* __restrict__ Wv, float* __restrict__ W)
{
    int idx = blockIdx.x * blockDim.x + threadIdx.x;
    if (idx >= H_ * QKVN_) return;
    int r = idx / QKVN_, c = idx % QKVN_;
    float v;
    if (c < H_)                 v = Wq[(long)r * H_ + c];
    else if (c < H_ + KVH_*HD_) v = Wk[(long)r * (KVH_*HD_) + (c - H_)];
    else                        v = Wv[(long)r * (KVH_*HD_) + (c - H_ - KVH_*HD_)];
    W[idx] = v;
}

__global__ void rmsnorm_k(const float* __restrict__ x, const float* __restrict__ w,
                          float* __restrict__ y, __half* __restrict__ yh)
{
    int t = blockIdx.x;
    const float* xr = x + (long)t * H_;
    float s = 0.f;
    for (int i = threadIdx.x; i < H_; i += blockDim.x) { float v = xr[i]; s += v * v; }
    s = blockSum(s);
    float inv = rsqrtf(s / (float)H_ + EPS_);
    for (int i = threadIdx.x; i < H_; i += blockDim.x) {
        float v = xr[i] * inv * w[i];
        if (y)  y[(long)t * H_ + i] = v;
        yh[(long)t * H_ + i] = __float2half_rn(v);
    }
}

__global__ void rope_k(const float* __restrict__ src, __half* __restrict__ dst,
                       int nh, int ld, int off)
{
    int idx = blockIdx.x * blockDim.x + threadIdx.x;
    if (idx >= nh * S_ * HD_) return;
    int d = idx % HD_;
    int s = (idx / HD_) % S_;
    int h = idx / (HD_ * S_);
    const float* p = src + (long)s * ld + off + h * HD_;
    float v  = p[d];
    float pr = (d < HD_/2) ? -p[d + HD_/2] : p[d - HD_/2];
    int i = d & (HD_/2 - 1);
    float inv = expf(-(float)i * (9.210340371976184f / (HD_/2)));
    float ang = (float)s * inv, sn, cs;
    sincosf(ang, &sn, &cs);
    dst[((long)h * S_ + s) * HD_ + d] = __float2half_rn(v * cs + pr * sn);
}

// V transposed: dst[h][d][s] half
__global__ void vtrans_k(const float* __restrict__ src, __half* __restrict__ dst,
                         int ld, int off)
{
    int idx = blockIdx.x * blockDim.x + threadIdx.x;
    if (idx >= KVH_ * S_ * HD_) return;
    int s = idx % S_;
    int d = (idx / S_) % HD_;
    int h = idx / (S_ * HD_);
    dst[idx] = __float2half_rn(src[(long)s * ld + off + h * HD_ + d]);
}

__global__ void merge_heads_k(const float* __restrict__ src, __half* __restrict__ dst)
{
    int idx = blockIdx.x * blockDim.x + threadIdx.x;
    if (idx >= NH_ * S_ * HD_) return;
    int d = idx % HD_;
    int s = (idx / HD_) % S_;
    int h = idx / (HD_ * S_);
    dst[(long)s * H_ + h * HD_ + d] = __float2half_rn(src[((long)h * S_ + s) * HD_ + d]);
}

// single-pass masked softmax: fp32 scores in, half probs out
__global__ void softmax_k(const float* __restrict__ sc, const float* __restrict__ mask,
                          __half* __restrict__ pr)
{
    int r = blockIdx.x, h = blockIdx.y;
    const float4* row = reinterpret_cast<const float4*>(sc + ((long)h * S_ + r) * S_);
    const float4* mr = reinterpret_cast<const float4*>(mask + (long)r * S_);
    int j = threadIdx.x;
    float4 v = row[j], m = mr[j];
    v.x = v.x * 0.125f + m.x;
    v.y = v.y * 0.125f + m.y;
    v.z = v.z * 0.125f + m.z;
    v.w = v.w * 0.125f + m.w;
    float mx = fmaxf(fmaxf(v.x, v.y), fmaxf(v.z, v.w));
    mx = blockMax(mx);
    v.x = expf(v.x - mx); v.y = expf(v.y - mx);
    v.z = expf(v.z - mx); v.w = expf(v.w - mx);
    float sum = v.x + v.y + v.z + v.w;
    sum = blockSum(sum);
    float inv = 1.f / sum;
    __half2 lo = __floats2half2_rn(v.x * inv, v.y * inv);
    __half2 hi = __floats2half2_rn(v.z * inv, v.w * inv);
    uint2 pk = make_uint2(*(uint32_t*)&lo, *(uint32_t*)&hi);
    reinterpret_cast<uint2*>(pr + ((long)h * S_ + r) * S_)[j] = pk;
}

__global__ void add_k(const float* __restrict__ a, const float* __restrict__ b,
                      float* __restrict__ c, long n)
{
    long i = (long)blockIdx.x * blockDim.x + threadIdx.x;
    if (i < n) c[i] = a[i] + b[i];
}

__global__ void topk_k(const float* __restrict__ logits, int* __restrict__ topi,
                       float* __restrict__ coef)
{
    int t = blockIdx.x * blockDim.x + threadIdx.x;
    if (t >= S_) return;
    const float* lr = logits + (long)t * E_;
    unsigned long long sel = 0ull;
    float tv[TOPK_]; int ti[TOPK_];
    for (int k = 0; k < TOPK_; k++) {
        float best = -1e30f; int bi = 0;
        for (int e = 0; e < E_; e++) {
            if ((sel >> e) & 1ull) continue;
            float v = lr[e];
            if (v > best) { best = v; bi = e; }
        }
        sel |= 1ull << bi;
        tv[k] = best; ti[k] = bi;
    }
    float mx = tv[0], ex[TOPK_], sum = 0.f;
    for (int k = 0; k < TOPK_; k++) { ex[k] = expf(tv[k] - mx); sum += ex[k]; }
    float inv = 1.f / sum;
    for (int k = 0; k < TOPK_; k++) { topi[t*TOPK_+k] = ti[k]; coef[t*TOPK_+k] = ex[k]*inv; }
}

__global__ void assign_k(const int* __restrict__ topi, int* __restrict__ pos,
                         int* __restrict__ cnt)
{
    const int e = blockIdx.x;
    __shared__ int sdata[256];
    int base = 0;
    for (int chunk = 0; chunk < S_ * TOPK_; chunk += 256) {
        int i = chunk + threadIdx.x;
        int p = (topi[i] == e) ? 1 : 0;
        sdata[threadIdx.x] = p;
        __syncthreads();
        #pragma unroll
        for (int off = 1; off < 256; off <<= 1) {
            int v = (threadIdx.x >= off) ? sdata[threadIdx.x - off] : 0;
            __syncthreads();
            sdata[threadIdx.x] += v;
            __syncthreads();
        }
        if (p) pos[i] = base + sdata[threadIdx.x] - 1;
        base += sdata[255];
        __syncthreads();
    }
    if (threadIdx.x == 0) cnt[e] = (base < CAP_) ? base : CAP_;
}

__global__ void scatter_k(const float* __restrict__ xn2, const int* __restrict__ topi,
                          const int* __restrict__ pos, __half* __restrict__ buf)
{
    int i = blockIdx.x;
    int p = pos[i];
    if (p >= CAP_) return;
    int e = topi[i];
    int t = i >> 3;
    const float4* src = reinterpret_cast<const float4*>(xn2 + (long)t * H_);
    float4 v = src[threadIdx.x];
    __half2 lo = __floats2half2_rn(v.x, v.y);
    __half2 hi = __floats2half2_rn(v.z, v.w);
    uint2 pk = make_uint2(*(uint32_t*)&lo, *(uint32_t*)&hi);
    reinterpret_cast<uint2*>(buf + ((long)e * CAP_ + p) * H_)[threadIdx.x] = pk;
}

__global__ void act_expert_k(const float* __restrict__ g, const float* __restrict__ u,
                             __half* __restrict__ o, const int* __restrict__ cnt)
{
    int e = blockIdx.x >> 8, c = blockIdx.x & 255;
    if (c >= cnt[e]) return;
    long base = ((long)e * CAP_ + c) * ID_;
    for (int j = threadIdx.x; j < ID_; j += blockDim.x) {
        float x = g[base + j];
        o[base + j] = __float2half_rn((x / (1.f + expf(-x))) * u[base + j]);
    }
}

__global__ void act_k(const float* __restrict__ g, const float* __restrict__ u,
                      __half* __restrict__ o, long n)
{
    long i = (long)blockIdx.x * blockDim.x + threadIdx.x;
    if (i < n) {
        float x = g[i];
        o[i] = __float2half_rn((x / (1.f + expf(-x))) * u[i]);
    }
}

__global__ void final_k(const float* __restrict__ hres, const float* __restrict__ shb,
                        const float* __restrict__ y, const int* __restrict__ topi,
                        const int* __restrict__ pos, const float* __restrict__ coef,
                        float* __restrict__ out)
{
    int t = blockIdx.x, j = threadIdx.x;
    float4 a = reinterpret_cast<const float4*>(hres)[(long)t*256 + j];
    float4 b = reinterpret_cast<const float4*>(shb)[(long)t*256 + j];
    a.x += b.x; a.y += b.y; a.z += b.z; a.w += b.w;
    #pragma unroll
    for (int k = 0; k < TOPK_; k++) {
        int idx = t * TOPK_ + k;
        int p = pos[idx];
        if (p < CAP_) {
            float c = coef[idx];
            float4 v = reinterpret_cast<const float4*>(y)[((long)topi[idx]*CAP_ + p)*256 + j];
            a.x += c*v.x; a.y += c*v.y; a.z += c*v.z; a.w += c*v.w;
        }
    }
    reinterpret_cast<float4*>(out)[(long)t*256 + j] = a;
}

// ---------- host-side smem size (mirror of kernel constexpr) ----------
static int smemB(int BN, int NST, bool bhalf) {
    int A_BY = 128 * 40 * 2;
    int B_BY = bhalf ? BN * 40 * 2 : 32 * (BN + 4) * 4;
    return NST * (A_BY + B_BY);
}

extern "C" void kernel_launch(void* const* d_in, const int* in_sizes, int n_in,
                              void* d_out, int out_size)
{
    (void)in_sizes; (void)n_in; (void)out_size;
    cudaStream_t st = 0;

    const int SM_W   = smemB(128, 4, false);   // 108544
    const int SM_SCR = smemB(128, 2, true);    //  40960
    const int SM_PV  = smemB(64,  4, true);    //  61440
    cudaFuncSetAttribute(hgemm_k<128, 4, false>, cudaFuncAttributeMaxDynamicSharedMemorySize, SM_W);
    cudaFuncSetAttribute(hgemm_k<128, 2, true >, cudaFuncAttributeMaxDynamicSharedMemorySize, SM_SCR);
    cudaFuncSetAttribute(hgemm_k<64,  4, true >, cudaFuncAttributeMaxDynamicSharedMemorySize, SM_PV);

    const float* x     = (const float*)d_in[0];
    const float* mask  = (const float*)d_in[1];
    const float* wln1  = (const float*)d_in[2];
    const float* wln2  = (const float*)d_in[3];
    const float* Wq    = (const float*)d_in[4];
    const float* Wk    = (const float*)d_in[5];
    const float* Wv    = (const float*)d_in[6];
    const float* Wo    = (const float*)d_in[7];
    const float* Wgate = (const float*)d_in[8];
    const float* Weg   = (const float*)d_in[9];
    const float* Weu   = (const float*)d_in[10];
    const float* Wed   = (const float*)d_in[11];
    const float* Wsg   = (const float*)d_in[12];
    const float* Wsu   = (const float*)d_in[13];
    const float* Wsd   = (const float*)d_in[14];
    float* out = (float*)d_out;

    void *p;
    #define GETF(sym, var) cudaGetSymbolAddress(&p, sym); float* var = (float*)p;
    #define GETH(sym, var) cudaGetSymbolAddress(&p, sym); __half* var = (__half*)p;
    #define GETI(sym, var) cudaGetSymbolAddress(&p, sym); int* var = (int*)p;
    GETF(g_xn1, xn1)  GETF(g_wqkv, wqkv) GETF(g_qkv, qkv)  GETF(g_sc, sc)
    GETF(g_aoh, aoh)  GETF(g_hres, hres) GETF(g_xn2, xn2)  GETF(g_logits, logits)
    GETF(g_coef, coef) GETF(g_gg, gg)    GETF(g_uu, uu)    GETF(g_yy, yy)
    GETF(g_sg, sg)    GETF(g_su, su)     GETF(g_shb, shb)
    GETH(h_xn1, hxn1) GETH(h_xn2, hxn2)  GETH(h_qr, hqr)   GETH(h_kr, hkr)
    GETH(h_vt, hvt)   GETH(h_sc, hsc)    GETH(h_ao, hao)   GETH(h_buf, hbuf)
    GETH(h_gg, hgg)   GETH(h_sg, hsg)
    GETI(g_topi, topi) GETI(g_pos, pos)  GETI(g_cnt, cnt)
    #undef GETF
    #undef GETH
    #undef GETI

    auto gw = [&](const __half* A, const float* B, float* C, int M, int N, int K,
                  int lda, int ldb, int ldc, long sA, long sB, long sC, int bDiv,
                  int batch, const int* cc) {
        dim3 grid(N / 128, M / 128, batch);
        hgemm_k<128, 4, false><<<grid, 256, SM_W, st>>>(
            A, B, C, K, lda, ldb, ldc, sA, sB, sC, bDiv, cc);
    };

    // ===== attention =====
    rmsnorm_k<<<S_, 256, 0, st>>>(x, wln1, nullptr, hxn1);

    concat_qkv_w<<<(H_ * QKVN_ + 255)/256, 256, 0, st>>>(Wq, Wk, Wv, wqkv);
    gw(hxn1, wqkv, qkv, S_, QKVN_, H_, H_, QKVN_, QKVN_, 0,0,0, 1, 1, nullptr);

    rope_k<<<(NH_*S_*HD_ + 255)/256, 256, 0, st>>>(qkv, hqr, NH_, QKVN_, 0);
    rope_k<<<(KVH_*S_*HD_ + 255)/256, 256, 0, st>>>(qkv, hkr, KVH_, QKVN_, H_);
    vtrans_k<<<(KVH_*S_*HD_ + 255)/256, 256, 0, st>>>(qkv, hvt, QKVN_, H_ + KVH_*HD_);

    // scores[h] = qr[h] @ kr[h/4]^T : B = kr half [N,K]
    {
        dim3 grid(S_/128, S_/128, NH_);
        hgemm_k<128, 2, true><<<grid, 256, SM_SCR, st>>>(
            hqr, hkr, sc, HD_, HD_, HD_, S_,
            (long)S_*HD_, (long)S_*HD_, (long)S_*S_, REP_, nullptr);
    }

    softmax_k<<<dim3(S_, NH_), 256, 0, st>>>(sc, mask, hsc);

    // aoh[h] = probs[h] @ v[h/4] : B = vt half [N=HD, K=S]
    {
        dim3 grid(1, S_/128, NH_);
        hgemm_k<64, 4, true><<<grid, 256, SM_PV, st>>>(
            hsc, hvt, aoh, S_, S_, S_, HD_,
            (long)S_*S_, (long)HD_*S_, (long)S_*HD_, REP_, nullptr);
    }

    merge_heads_k<<<(NH_*S_*HD_ + 255)/256, 256, 0, st>>>(aoh, hao);

    gw(hao, Wo, xn1, S_, H_, H_, H_, H_, H_, 0,0,0, 1, 1, nullptr);
    add_k<<<(S_*H_ + 255)/256, 256, 0, st>>>(x, xn1, hres, (long)S_*H_);

    // ===== MoE =====
    rmsnorm_k<<<S_, 256, 0, st>>>(hres, wln2, xn2, hxn2);

    sgemm64_k<<<dim3(1, S_/64), 256, 0, st>>>(xn2, Wgate, logits, S_, E_, H_);
    topk_k<<<(S_ + 255)/256, 256, 0, st>>>(logits, topi, coef);
    assign_k<<<E_, 256, 0, st>>>(topi, pos, cnt);

    scatter_k<<<S_*TOPK_, 256, 0, st>>>(xn2, topi, pos, hbuf);

    gw(hbuf, Weg, gg, CAP_, ID_, H_, H_, ID_, ID_,
       (long)CAP_*H_, (long)H_*ID_, (long)CAP_*ID_, 1, E_, cnt);
    gw(hbuf, Weu, uu, CAP_, ID_, H_, H_, ID_, ID_,
       (long)CAP_*H_, (long)H_*ID_, (long)CAP_*ID_, 1, E_, cnt);

    act_expert_k<<<E_ * CAP_, 256, 0, st>>>(gg, uu, hgg, cnt);

    gw(hgg, Wed, yy, CAP_, H_, ID_, ID_, H_, H_,
       (long)CAP_*ID_, (long)ID_*H_, (long)CAP_*H_, 1, E_, cnt);

    // shared expert
    gw(hxn2, Wsg, sg, S_, ID_, H_, H_, ID_, ID_, 0,0,0, 1, 1, nullptr);
    gw(hxn2, Wsu, su, S_, ID_, H_, H_, ID_, ID_, 0,0,0, 1, 1, nullptr);
    { long n = (long)S_*ID_;
      act_k<<<(int)((n + 255)/256), 256, 0, st>>>(sg, su, hsg, n); }
    gw(hsg, Wsd, shb, S_, H_, ID_, ID_, H_, H_, 0,0,0, 1, 1, nullptr);

    final_k<<<S_, 256, 0, st>>>(hres, shb, yy, topi, pos, coef, out);
}

// round 10
// speedup vs baseline: 7.0700x; 1.0293x over previous
#include <cuda_runtime.h>
#include <cuda_fp16.h>
#include <math.h>
#include <stdint.h>

#define S_    1024
#define H_    1024
#define NH_   16
#define KVH_  4
#define HD_   64
#define REP_  4
#define E_    64
#define TOPK_ 8
#define ID_   1408
#define CAP_  256
#define EPS_  1e-6f
#define QKVN_ (H_ + 2 * KVH_ * HD_)   // 1536

// fp32 scratch
__device__ float g_xn1 [S_ * H_];
__device__ float g_wqkv[H_ * QKVN_];
__device__ float g_qkv [S_ * QKVN_];
__device__ float g_sc  [(long)NH_ * S_ * S_];
__device__ float g_hres[S_ * H_];
__device__ float g_xn2 [S_ * H_];
__device__ float g_logits[S_ * E_];
__device__ float g_coef[S_ * TOPK_];
__device__ float g_gg  [(long)E_ * CAP_ * ID_];
__device__ float g_uu  [(long)E_ * CAP_ * ID_];
__device__ float g_yy  [(long)E_ * CAP_ * H_];
__device__ float g_sg  [S_ * ID_];
__device__ float g_su  [S_ * ID_];
__device__ float g_shb [S_ * H_];
__device__ int   g_topi[S_ * TOPK_];
__device__ int   g_pos [S_ * TOPK_];
__device__ int   g_cnt [E_];
__device__ int   g_dummyi;
// fp16 activation scratch
__device__ __half h_xn1[S_ * H_];
__device__ __half h_xn2[S_ * H_];
__device__ __half h_qr [NH_ * S_ * HD_];
__device__ __half h_kr [KVH_ * S_ * HD_];
__device__ __half h_vt [KVH_ * HD_ * S_];   // [h][d][s]
__device__ __half h_sc [(long)NH_ * S_ * S_];
__device__ __half h_ao [S_ * H_];
__device__ __half h_buf[(long)E_ * CAP_ * H_];
__device__ __half h_gg [(long)E_ * CAP_ * ID_];
__device__ __half h_sg [S_ * ID_];

// ---------- helpers ----------
__device__ __forceinline__ uint32_t smem_u32(const void* p) {
    uint32_t a;
    asm("{ .reg .u64 t; cvta.to.shared.u64 t, %1; cvt.u32.u64 %0, t; }" : "=r"(a) : "l"(p));
    return a;
}
__device__ __forceinline__ uint32_t cvt2h(float lo, float hi) {
    __half2 h = __floats2half2_rn(lo, hi);
    return *reinterpret_cast<uint32_t*>(&h);
}
__device__ __forceinline__ void cp16(uint32_t dst, const void* src) {
    asm volatile("cp.async.cg.shared.global [%0], [%1], 16;" :: "r"(dst), "l"(src));
}
__device__ __forceinline__ void cp_commit() { asm volatile("cp.async.commit_group;" ::: "memory"); }
__device__ __forceinline__ void cp_wait(int n) {
    if (n <= 0)      asm volatile("cp.async.wait_group 0;" ::: "memory");
    else if (n == 1) asm volatile("cp.async.wait_group 1;" ::: "memory");
    else if (n == 2) asm volatile("cp.async.wait_group 2;" ::: "memory");
    else             asm volatile("cp.async.wait_group 3;" ::: "memory");
}
__device__ __forceinline__ void mma16816(float* d, const uint32_t* a, const uint32_t* b) {
    asm volatile("mma.sync.aligned.m16n8k16.row.col.f32.f16.f16.f32 "
        "{%0,%1,%2,%3}, {%4,%5,%6,%7}, {%8,%9}, {%0,%1,%2,%3};"
        : "+f"(d[0]), "+f"(d[1]), "+f"(d[2]), "+f"(d[3])
        : "r"(a[0]), "r"(a[1]), "r"(a[2]), "r"(a[3]), "r"(b[0]), "r"(b[1]));
}

// ---------- fp16 GEMM ----------
// A half; B fp32 [K,N] (weights, cvt in-reg) or half [N,K] N-major.
// C fp32, or half when CHALF (ldc/sC in halves).
template<int BN, int NST, bool BHALF, bool CHALF>
__global__ void __launch_bounds__(256, 2) hgemm_k(
    const __half* __restrict__ A, const void* __restrict__ Bv, void* __restrict__ Cv,
    int K, int lda, int ldb, int ldc, long sA, long sB, long sC, int bDiv,
    const int* __restrict__ cnt)
{
    constexpr int BM = 128, BK = 32;
    constexpr int LDA  = 40;
    constexpr int LDBF = BN + 4;
    constexpr int A_BY = BM * LDA * 2;
    constexpr int B_BY = BHALF ? BN * 40 * 2 : BK * LDBF * 4;
    constexpr int STG_BY = A_BY + B_BY;
    constexpr int WGN = BN / 32, WGM = 8 / WGN;
    constexpr int WM  = BM / WGM, MT = WM / 16, NT = 4;

    const int row0 = blockIdx.y * BM;
    if (cnt != nullptr && row0 >= cnt[blockIdx.z]) return;

    extern __shared__ char sm[];
    const int tid = threadIdx.x, wid = tid >> 5, lane = tid & 31;
    const int qrw = lane >> 2, qc = lane & 3;
    A += (long)blockIdx.z * sA;
    const __half* Bh = BHALF ? (const __half*)Bv + (long)(blockIdx.z / bDiv) * sB : nullptr;
    const float*  Bf = BHALF ? nullptr : (const float*)Bv + (long)(blockIdx.z / bDiv) * sB;
    const int col0 = blockIdx.x * BN;
    const int wm0 = (wid / WGN) * WM;
    const int wn0 = (wid % WGN) * 32;
    const int nch = K / BK;

    auto fill = [&](int c) {
        char* Ss = sm + (c % NST) * STG_BY;
        __half* As = (__half*)Ss;
        const int k0 = c * BK;
        const __half* Ag = A + (long)row0 * lda + k0;
        #pragma unroll
        for (int i = 0; i < 2; i++) {
            int idx = i * 256 + tid;
            int r = idx >> 2, sg = idx & 3;
            cp16(smem_u32(As + r * LDA + sg * 8), Ag + (long)r * lda + sg * 8);
        }
        if (BHALF) {
            __half* Bs = (__half*)(Ss + A_BY);
            const __half* Bg = Bh + (long)col0 * ldb + k0;
            #pragma unroll
            for (int i = 0; i < BN / 64; i++) {
                int idx = i * 256 + tid;
                int r = idx >> 2, sg = idx & 3;
                cp16(smem_u32(Bs + r * 40 + sg * 8), Bg + (long)r * ldb + sg * 8);
            }
        } else {
            float* Bs = (float*)(Ss + A_BY);
            const float* Bg = Bf + (long)k0 * ldb + col0;
            #pragma unroll
            for (int i = 0; i < BN / 32; i++) {
                int idx = i * 256 + tid;
                int r = idx / (BN / 4), sg = idx % (BN / 4);
                cp16(smem_u32(Bs + r * LDBF + sg * 4), Bg + (long)r * ldb + sg * 4);
            }
        }
        cp_commit();
    };

    float acc[MT][NT][4];
    #pragma unroll
    for (int m = 0; m < MT; m++)
        #pragma unroll
        for (int n = 0; n < NT; n++)
            #pragma unroll
            for (int j = 0; j < 4; j++) acc[m][n][j] = 0.f;

    const int PF = NST - 1;
    const int F0 = (nch < PF) ? nch : PF;
    for (int c = 0; c < F0; c++) fill(c);
    int g = F0;

    for (int c = 0; c < nch; c++) {
        cp_wait(g - (c + 1));
        __syncthreads();
        if (c + PF < nch) { fill(c + PF); g++; }

        const char* Ss = sm + (c % NST) * STG_BY;
        const __half* As = (const __half*)Ss;
        #pragma unroll
        for (int ks = 0; ks < 2; ks++) {
            const int kk = ks * 16;
            uint32_t af[MT][4], bf[NT][2];
            #pragma unroll
            for (int mt = 0; mt < MT; mt++) {
                const __half* ap = As + (wm0 + mt * 16 + qrw) * LDA + kk + 2 * qc;
                af[mt][0] = *(const uint32_t*)ap;
                af[mt][1] = *(const uint32_t*)(ap + 8 * LDA);
                af[mt][2] = *(const uint32_t*)(ap + 8);
                af[mt][3] = *(const uint32_t*)(ap + 8 * LDA + 8);
            }
            #pragma unroll
            for (int nt = 0; nt < NT; nt++) {
                if (BHALF) {
                    const __half* bp = (const __half*)(Ss + A_BY)
                                     + (wn0 + nt * 8 + qrw) * 40 + kk + 2 * qc;
                    bf[nt][0] = *(const uint32_t*)bp;
                    bf[nt][1] = *(const uint32_t*)(bp + 8);
                } else {
                    const float* bp = (const float*)(Ss + A_BY)
                                    + (kk + 2 * qc) * LDBF + wn0 + nt * 8 + qrw;
                    bf[nt][0] = cvt2h(bp[0], bp[LDBF]);
                    bf[nt][1] = cvt2h(bp[8 * LDBF], bp[9 * LDBF]);
                }
            }
            #pragma unroll
            for (int mt = 0; mt < MT; mt++)
                #pragma unroll
                for (int nt = 0; nt < NT; nt++)
                    mma16816(acc[mt][nt], af[mt], bf[nt]);
        }
    }

    if (CHALF) {
        __half* Ch = (__half*)Cv + (long)blockIdx.z * sC;
        #pragma unroll
        for (int mt = 0; mt < MT; mt++) {
            const int r = row0 + wm0 + mt * 16 + qrw;
            #pragma unroll
            for (int nt = 0; nt < NT; nt++) {
                const int cc = col0 + wn0 + nt * 8 + qc * 2;
                *reinterpret_cast<uint32_t*>(Ch + (long)r * ldc + cc)
                    = cvt2h(acc[mt][nt][0], acc[mt][nt][1]);
                *reinterpret_cast<uint32_t*>(Ch + (long)(r + 8) * ldc + cc)
                    = cvt2h(acc[mt][nt][2], acc[mt][nt][3]);
            }
        }
    } else {
        float* Cf = (float*)Cv + (long)blockIdx.z * sC;
        #pragma unroll
        for (int mt = 0; mt < MT; mt++) {
            const int r = row0 + wm0 + mt * 16 + qrw;
            #pragma unroll
            for (int nt = 0; nt < NT; nt++) {
                const int cc = col0 + wn0 + nt * 8 + qc * 2;
                *reinterpret_cast<float2*>(Cf + (long)r * ldc + cc) =
                    make_float2(acc[mt][nt][0], acc[mt][nt][1]);
                *reinterpret_cast<float2*>(Cf + (long)(r + 8) * ldc + cc) =
                    make_float2(acc[mt][nt][2], acc[mt][nt][3]);
            }
        }
    }
}

// ---------- exact fp32 gemm for gate logits ----------
__global__ void sgemm64_k(const float* __restrict__ A, const float* __restrict__ B,
                          float* __restrict__ C, int M, int N, int K)
{
    const int tid = threadIdx.x;
    const int row0 = blockIdx.y * 64, col0 = blockIdx.x * 64;
    __shared__ float As[16][68];
    __shared__ float Bs[16][68];
    float acc[4][4] = {};
    const int tRow = (tid / 16) * 4, tCol = (tid % 16) * 4;
    const int aRow = tid / 4, aK = (tid % 4) * 4;
    const int bR = tid / 16, bC = (tid % 16) * 4;
    for (int k0 = 0; k0 < K; k0 += 16) {
        {
            int gr = row0 + aRow, gk = k0 + aK;
            float4 v = make_float4(0,0,0,0);
            if (gr < M && gk + 3 < K) v = *reinterpret_cast<const float4*>(A + (long)gr*K + gk);
            As[aK+0][aRow]=v.x; As[aK+1][aRow]=v.y; As[aK+2][aRow]=v.z; As[aK+3][aRow]=v.w;
        }
        {
            int gk = k0 + bR, gn = col0 + bC;
            float4 v = make_float4(0,0,0,0);
            if (gk < K && gn + 3 < N) v = *reinterpret_cast<const float4*>(B + (long)gk*N + gn);
            *reinterpret_cast<float4*>(&Bs[bR][bC]) = v;
        }
        __syncthreads();
        #pragma unroll
        for (int k = 0; k < 16; k++) {
            float rA[4], rB[4];
            #pragma unroll
            for (int m = 0; m < 4; m++) rA[m] = As[k][tRow+m];
            #pragma unroll
            for (int n = 0; n < 4; n++) rB[n] = Bs[k][tCol+n];
            #pragma unroll
            for (int m = 0; m < 4; m++)
                #pragma unroll
                for (int n = 0; n < 4; n++) acc[m][n] += rA[m]*rB[n];
        }
        __syncthreads();
    }
    #pragma unroll
    for (int m = 0; m < 4; m++) {
        int gr = row0 + tRow + m;
        if (gr >= M) continue;
        #pragma unroll
        for (int n = 0; n < 4; n++) {
            int gc = col0 + tCol + n;
            if (gc < N) C[(long)gr*N + gc] = acc[m][n];
        }
    }
}

// ---------- reductions ----------
__device__ __forceinline__ float warpSum(float v) {
    #pragma unroll
    for (int o = 16; o; o >>= 1) v += __shfl_xor_sync(0xffffffffu, v, o);
    return v;
}
__device__ __forceinline__ float warpMax(float v) {
    #pragma unroll
    for (int o = 16; o; o >>= 1) v = fmaxf(v, __shfl_xor_sync(0xffffffffu, v, o));
    return v;
}
__device__ float blockSum(float v) {
    __shared__ float sh[32]; __shared__ float tot;
    int lane = threadIdx.x & 31, wid = threadIdx.x >> 5;
    v = warpSum(v);
    if (lane == 0) sh[wid] = v;
    __syncthreads();
    int nw = (blockDim.x + 31) >> 5;
    float w = (threadIdx.x < nw) ? sh[threadIdx.x] : 0.f;
    if (wid == 0) { w = warpSum(w); if (lane == 0) tot = w; }
    __syncthreads();
    float r = tot; __syncthreads(); return r;
}
__device__ float blockMax(float v) {
    __shared__ float sh[32]; __shared__ float tot;
    int lane = threadIdx.x & 31, wid = threadIdx.x >> 5;
    v = warpMax(v);
    if (lane == 0) sh[wid] = v;
    __syncthreads();
    int nw = (blockDim.x + 31) >> 5;
    float w = (threadIdx.x < nw) ? sh[threadIdx.x] : -1e30f;
    if (wid == 0) { w = warpMax(w); if (lane == 0) tot = w; }
    __syncthreads();
    float r = tot; __syncthreads(); return r;
}

// ---------- small kernels ----------
__global__ void anchor_k(int* p) { if (threadIdx.x == 0) *p = 0; }

__global__ void concat_qkv_w(const float* __restrict__ Wq, const float* __restrict__ Wk,
                             const float* __restrict__ Wv, float* __restrict__ W)
{
    int idx = blockIdx.x * blockDim.x + threadIdx.x;
    if (idx >= H_ * QKVN_) return;
    int r = idx / QKVN_, c = idx % QKVN_;
    float v;
    if (c < H_)                 v = Wq[(long)r * H_ + c];
    else if (c < H_ + KVH_*HD_) v = Wk[(long)r * (KVH_*HD_) + (c - H_)];
    else                        v = Wv[(long)r * (KVH_*HD_) + (c - H_ - KVH_*HD_)];
    W[idx] = v;
}

__global__ void rmsnorm_k(const float* __restrict__ x, const float* __restrict__ w,
                          float* __restrict__ y, __half* __restrict__ yh)
{
    int t = blockIdx.x;
    const float* xr = x + (long)t * H_;
    float s = 0.f;
    for (int i = threadIdx.x; i < H_; i += blockDim.x) { float v = xr[i]; s += v * v; }
    s = blockSum(s);
    float inv = rsqrtf(s / (float)H_ + EPS_);
    for (int i = threadIdx.x; i < H_; i += blockDim.x) {
        float v = xr[i] * inv * w[i];
        if (y)  y[(long)t * H_ + i] = v;
        yh[(long)t * H_ + i] = __float2half_rn(v);
    }
}

// fused: rope(q) + rope(k) + V-transpose, all reading qkv
__global__ void ropeall_k(const float* __restrict__ qkv, __half* __restrict__ hqr,
                          __half* __restrict__ hkr, __half* __restrict__ hvt)
{
    int idx = blockIdx.x * blockDim.x + threadIdx.x;
    if (idx >= 24 * S_ * HD_) return;
    int g = idx / (S_ * HD_);
    int rem = idx - g * (S_ * HD_);
    if (g < 20) {
        int d = rem % HD_, s = rem / HD_;
        int h, off; __half* dst;
        if (g < 16) { h = g;      off = 0;  dst = hqr; }
        else        { h = g - 16; off = H_; dst = hkr; }
        const float* p = qkv + (long)s * QKVN_ + off + h * HD_;
        float v  = p[d];
        float pr = (d < 32) ? -p[d + 32] : p[d - 32];
        int i = d & 31;
        float inv = expf(-(float)i * (9.210340371976184f / 32.f));
        float ang = (float)s * inv, sn, cs;
        sincosf(ang, &sn, &cs);
        dst[((long)h * S_ + s) * HD_ + d] = __float2half_rn(v * cs + pr * sn);
    } else {
        int h = g - 20;
        int s = rem % S_, d = rem / S_;
        hvt[((long)h * HD_ + d) * S_ + s] =
            __float2half_rn(qkv[(long)s * QKVN_ + H_ + KVH_*HD_ + h * HD_ + d]);
    }
}

// single-pass masked softmax: fp32 scores in, half probs out
__global__ void softmax_k(const float* __restrict__ sc, const float* __restrict__ mask,
                          __half* __restrict__ pr)
{
    int r = blockIdx.x, h = blockIdx.y;
    const float4* row = reinterpret_cast<const float4*>(sc + ((long)h * S_ + r) * S_);
    const float4* mr = reinterpret_cast<const float4*>(mask + (long)r * S_);
    int j = threadIdx.x;
    float4 v = row[j], m = mr[j];
    v.x = v.x * 0.125f + m.x;
    v.y = v.y * 0.125f + m.y;
    v.z = v.z * 0.125f + m.z;
    v.w = v.w * 0.125f + m.w;
    float mx = fmaxf(fmaxf(v.x, v.y), fmaxf(v.z, v.w));
    mx = blockMax(mx);
    v.x = expf(v.x - mx); v.y = expf(v.y - mx);
    v.z = expf(v.z - mx); v.w = expf(v.w - mx);
    float sum = v.x + v.y + v.z + v.w;
    sum = blockSum(sum);
    float inv = 1.f / sum;
    uint2 pk = make_uint2(cvt2h(v.x * inv, v.y * inv), cvt2h(v.z * inv, v.w * inv));
    reinterpret_cast<uint2*>(pr + ((long)h * S_ + r) * S_)[j] = pk;
}

__global__ void add_k(const float* __restrict__ a, const float* __restrict__ b,
                      float* __restrict__ c, long n)
{
    long i = (long)blockIdx.x * blockDim.x + threadIdx.x;
    if (i < n) c[i] = a[i] + b[i];
}

// warp-per-token top-k
__global__ void topk_k(const float* __restrict__ logits, int* __restrict__ topi,
                       float* __restrict__ coef)
{
    int t = (blockIdx.x * blockDim.x + threadIdx.x) >> 5;
    int lane = threadIdx.x & 31;
    if (t >= S_) return;
    const float* lr = logits + (long)t * E_;
    float v0 = lr[lane], v1 = lr[lane + 32];
    unsigned long long sel = 0ull;
    float tv[TOPK_]; int ti[TOPK_];
    #pragma unroll
    for (int k = 0; k < TOPK_; k++) {
        float c0 = ((sel >> lane) & 1ull) ? -1e30f : v0;
        float c1 = ((sel >> (lane + 32)) & 1ull) ? -1e30f : v1;
        float bv; int be;
        if (c0 >= c1) { bv = c0; be = lane; } else { bv = c1; be = lane + 32; }
        #pragma unroll
        for (int o = 16; o; o >>= 1) {
            float ov = __shfl_xor_sync(0xffffffffu, bv, o);
            int   oe = __shfl_xor_sync(0xffffffffu, be, o);
            if (ov > bv || (ov == bv && oe < be)) { bv = ov; be = oe; }
        }
        sel |= 1ull << be;
        tv[k] = bv; ti[k] = be;
    }
    if (lane == 0) {
        float mx = tv[0], ex[TOPK_], sum = 0.f;
        #pragma unroll
        for (int k = 0; k < TOPK_; k++) { ex[k] = expf(tv[k] - mx); sum += ex[k]; }
        float inv = 1.f / sum;
        #pragma unroll
        for (int k = 0; k < TOPK_; k++) { topi[t*TOPK_+k] = ti[k]; coef[t*TOPK_+k] = ex[k]*inv; }
    }
}

// ballot-based per-expert occurrence-order assignment
__global__ void assign_k(const int* __restrict__ topi, int* __restrict__ pos,
                         int* __restrict__ cnt)
{
    const int e = blockIdx.x;
    __shared__ int sw[8];
    __shared__ int stot;
    int lane = threadIdx.x & 31, wid = threadIdx.x >> 5;
    int base = 0;
    for (int chunk = 0; chunk < S_ * TOPK_; chunk += 256) {
        int i = chunk + threadIdx.x;
        int p = (topi[i] == e) ? 1 : 0;
        unsigned mask = __ballot_sync(0xffffffffu, p);
        int prefix = __popc(mask & ((1u << lane) - 1u));
        if (lane == 0) sw[wid] = __popc(mask);
        __syncthreads();
        if (threadIdx.x < 8) {
            int c = sw[threadIdx.x];
            int x = c;
            #pragma unroll
            for (int o = 1; o < 8; o <<= 1) {
                int y = __shfl_up_sync(0xffu, x, o);
                if ((int)threadIdx.x >= o) x += y;
            }
            sw[threadIdx.x] = x - c;
            if (threadIdx.x == 7) stot = x;
        }
        __syncthreads();
        if (p) pos[i] = base + sw[wid] + prefix;
        base += stot;
        __syncthreads();
    }
    if (threadIdx.x == 0) cnt[e] = (base < CAP_) ? base : CAP_;
}

__global__ void scatter_k(const __half* __restrict__ hxn2, const int* __restrict__ topi,
                          const int* __restrict__ pos, __half* __restrict__ buf)
{
    int i = blockIdx.x;
    int p = pos[i];
    if (p >= CAP_) return;
    int e = topi[i];
    int t = i >> 3;
    const uint2* src = reinterpret_cast<const uint2*>(hxn2 + (long)t * H_);
    uint2* dst = reinterpret_cast<uint2*>(buf + ((long)e * CAP_ + p) * H_);
    dst[threadIdx.x] = src[threadIdx.x];
}

__global__ void act_expert_k(const float* __restrict__ g, const float* __restrict__ u,
                             __half* __restrict__ o, const int* __restrict__ cnt)
{
    int e = blockIdx.x >> 8, c = blockIdx.x & 255;
    if (c >= cnt[e]) return;
    long base = ((long)e * CAP_ + c) * ID_;
    for (int j = threadIdx.x; j < ID_; j += blockDim.x) {
        float x = g[base + j];
        o[base + j] = __float2half_rn((x / (1.f + expf(-x))) * u[base + j]);
    }
}

__global__ void act_k(const float* __restrict__ g, const float* __restrict__ u,
                      __half* __restrict__ o, long n)
{
    long i = (long)blockIdx.x * blockDim.x + threadIdx.x;
    if (i < n) {
        float x = g[i];
        o[i] = __float2half_rn((x / (1.f + expf(-x))) * u[i]);
    }
}

__global__ void final_k(const float* __restrict__ hres, const float* __restrict__ shb,
                        const float* __restrict__ y, const int* __restrict__ topi,
                        const int* __restrict__ pos, const float* __restrict__ coef,
                        float* __restrict__ out)
{
    int t = blockIdx.x, j = threadIdx.x;
    float4 a = reinterpret_cast<const float4*>(hres)[(long)t*256 + j];
    float4 b = reinterpret_cast<const float4*>(shb)[(long)t*256 + j];
    a.x += b.x; a.y += b.y; a.z += b.z; a.w += b.w;
    #pragma unroll
    for (int k = 0; k < TOPK_; k++) {
        int idx = t * TOPK_ + k;
        int p = pos[idx];
        if (p < CAP_) {
            float c = coef[idx];
            float4 v = reinterpret_cast<const float4*>(y)[((long)topi[idx]*CAP_ + p)*256 + j];
            a.x += c*v.x; a.y += c*v.y; a.z += c*v.z; a.w += c*v.w;
        }
    }
    reinterpret_cast<float4*>(out)[(long)t*256 + j] = a;
}

// ---------- host-side smem size ----------
static int smemB(int BN, int NST, bool bhalf) {
    int A_BY = 128 * 40 * 2;
    int B_BY = bhalf ? BN * 40 * 2 : 32 * (BN + 4) * 4;
    return NST * (A_BY + B_BY);
}

extern "C" void kernel_launch(void* const* d_in, const int* in_sizes, int n_in,
                              void* d_out, int out_size)
{
    (void)in_sizes; (void)n_in; (void)out_size;
    cudaStream_t st = 0;

    const int SM_W   = smemB(128, 4, false);
    const int SM_SCR = smemB(128, 2, true);
    const int SM_PV  = smemB(64,  4, true);
    cudaFuncSetAttribute(hgemm_k<128, 4, false, false>, cudaFuncAttributeMaxDynamicSharedMemorySize, SM_W);
    cudaFuncSetAttribute(hgemm_k<128, 2, true,  false>, cudaFuncAttributeMaxDynamicSharedMemorySize, SM_SCR);
    cudaFuncSetAttribute(hgemm_k<64,  4, true,  true >, cudaFuncAttributeMaxDynamicSharedMemorySize, SM_PV);

    const float* x     = (const float*)d_in[0];
    const float* mask  = (const float*)d_in[1];
    const float* wln1  = (const float*)d_in[2];
    const float* wln2  = (const float*)d_in[3];
    const float* Wq    = (const float*)d_in[4];
    const float* Wk    = (const float*)d_in[5];
    const float* Wv    = (const float*)d_in[6];
    const float* Wo    = (const float*)d_in[7];
    const float* Wgate = (const float*)d_in[8];
    const float* Weg   = (const float*)d_in[9];
    const float* Weu   = (const float*)d_in[10];
    const float* Wed   = (const float*)d_in[11];
    const float* Wsg   = (const float*)d_in[12];
    const float* Wsu   = (const float*)d_in[13];
    const float* Wsd   = (const float*)d_in[14];
    float* out = (float*)d_out;

    void *p;
    #define GETF(sym, var) cudaGetSymbolAddress(&p, sym); float* var = (float*)p;
    #define GETH(sym, var) cudaGetSymbolAddress(&p, sym); __half* var = (__half*)p;
    #define GETI(sym, var) cudaGetSymbolAddress(&p, sym); int* var = (int*)p;
    GETF(g_xn1, xn1)  GETF(g_wqkv, wqkv) GETF(g_qkv, qkv)  GETF(g_sc, sc)
    GETF(g_hres, hres) GETF(g_xn2, xn2)  GETF(g_logits, logits)
    GETF(g_coef, coef) GETF(g_gg, gg)    GETF(g_uu, uu)    GETF(g_yy, yy)
    GETF(g_sg, sg)    GETF(g_su, su)     GETF(g_shb, shb)
    GETH(h_xn1, hxn1) GETH(h_xn2, hxn2)  GETH(h_qr, hqr)   GETH(h_kr, hkr)
    GETH(h_vt, hvt)   GETH(h_sc, hsc)    GETH(h_ao, hao)   GETH(h_buf, hbuf)
    GETH(h_gg, hgg)   GETH(h_sg, hsg)
    GETI(g_topi, topi) GETI(g_pos, pos)  GETI(g_cnt, cnt)  GETI(g_dummyi, dmy)
    #undef GETF
    #undef GETH
    #undef GETI

    auto gw = [&](const __half* A, const float* B, float* C, int M, int N, int K,
                  int lda, int ldb, int ldc, long sA, long sB, long sC, int bDiv,
                  int batch, const int* cc) {
        dim3 grid(N / 128, M / 128, batch);
        hgemm_k<128, 4, false, false><<<grid, 256, SM_W, st>>>(
            A, B, C, K, lda, ldb, ldc, sA, sB, sC, bDiv, cc);
    };

    // profiling anchors: shift ncu -s 5 capture onto the QKV weight GEMM
    anchor_k<<<1, 32, 0, st>>>(dmy);
    anchor_k<<<1, 32, 0, st>>>(dmy);
    anchor_k<<<1, 32, 0, st>>>(dmy);

    // ===== attention =====
    rmsnorm_k<<<S_, 256, 0, st>>>(x, wln1, nullptr, hxn1);
    concat_qkv_w<<<(H_ * QKVN_ + 255)/256, 256, 0, st>>>(Wq, Wk, Wv, wqkv);
    gw(hxn1, wqkv, qkv, S_, QKVN_, H_, H_, QKVN_, QKVN_, 0,0,0, 1, 1, nullptr);   // launch idx 5

    ropeall_k<<<(24*S_*HD_ + 255)/256, 256, 0, st>>>(qkv, hqr, hkr, hvt);

    {
        dim3 grid(S_/128, S_/128, NH_);
        hgemm_k<128, 2, true, false><<<grid, 256, SM_SCR, st>>>(
            hqr, hkr, sc, HD_, HD_, HD_, S_,
            (long)S_*HD_, (long)S_*HD_, (long)S_*S_, REP_, nullptr);
    }

    softmax_k<<<dim3(S_, NH_), 256, 0, st>>>(sc, mask, hsc);

    // PV: writes half directly into [s][h*64+d] layout (C = hao, sC = 64 halves)
    {
        dim3 grid(1, S_/128, NH_);
        hgemm_k<64, 4, true, true><<<grid, 256, SM_PV, st>>>(
            hsc, hvt, hao, S_, S_, S_, H_,
            (long)S_*S_, (long)HD_*S_, 64L, REP_, nullptr);
    }

    gw(hao, Wo, xn1, S_, H_, H_, H_, H_, H_, 0,0,0, 1, 1, nullptr);
    add_k<<<(S_*H_ + 255)/256, 256, 0, st>>>(x, xn1, hres, (long)S_*H_);

    // ===== MoE =====
    rmsnorm_k<<<S_, 256, 0, st>>>(hres, wln2, xn2, hxn2);

    sgemm64_k<<<dim3(1, S_/64), 256, 0, st>>>(xn2, Wgate, logits, S_, E_, H_);
    topk_k<<<(S_*32 + 255)/256, 256, 0, st>>>(logits, topi, coef);
    assign_k<<<E_, 256, 0, st>>>(topi, pos, cnt);

    scatter_k<<<S_*TOPK_, 256, 0, st>>>(hxn2, topi, pos, hbuf);

    gw(hbuf, Weg, gg, CAP_, ID_, H_, H_, ID_, ID_,
       (long)CAP_*H_, (long)H_*ID_, (long)CAP_*ID_, 1, E_, cnt);
    gw(hbuf, Weu, uu, CAP_, ID_, H_, H_, ID_, ID_,
       (long)CAP_*H_, (long)H_*ID_, (long)CAP_*ID_, 1, E_, cnt);

    act_expert_k<<<E_ * CAP_, 256, 0, st>>>(gg, uu, hgg, cnt);

    gw(hgg, Wed, yy, CAP_, H_, ID_, ID_, H_, H_,
       (long)CAP_*ID_, (long)ID_*H_, (long)CAP_*H_, 1, E_, cnt);

    // shared expert
    gw(hxn2, Wsg, sg, S_, ID_, H_, H_, ID_, ID_, 0,0,0, 1, 1, nullptr);
    gw(hxn2, Wsu, su, S_, ID_, H_, H_, ID_, ID_, 0,0,0, 1, 1, nullptr);
    { long n = (long)S_*ID_;
      act_k<<<(int)((n + 255)/256), 256, 0, st>>>(sg, su, hsg, n); }
    gw(hsg, Wsd, shb, S_, H_, ID_, ID_, H_, H_, 0,0,0, 1, 1, nullptr);

    final_k<<<S_, 256, 0, st>>>(hres, shb, yy, topi, pos, coef, out);
}

// round 11
// speedup vs baseline: 7.6556x; 1.0828x over previous
#include <cuda_runtime.h>
#include <cuda_fp16.h>
#include <math.h>
#include <stdint.h>

#define S_    1024
#define H_    1024
#define NH_   16
#define KVH_  4
#define HD_   64
#define REP_  4
#define E_    64
#define TOPK_ 8
#define ID_   1408
#define CAP_  256
#define EPS_  1e-6f
#define QKVN_ (H_ + 2 * KVH_ * HD_)   // 1536

// fp32 scratch
__device__ float g_xn1 [S_ * H_];
__device__ float g_wqkv[H_ * QKVN_];
__device__ float g_qkv [S_ * QKVN_];
__device__ float g_sc  [(long)NH_ * S_ * S_];
__device__ float g_hres[S_ * H_];
__device__ float g_xn2 [S_ * H_];
__device__ float g_logits[S_ * E_];
__device__ float g_coef[S_ * TOPK_];
__device__ float g_shb [S_ * H_];
__device__ int   g_topi[S_ * TOPK_];
__device__ int   g_pos [S_ * TOPK_];
__device__ int   g_cnt [E_];
__device__ int   g_dummyi;
// fp16 activation scratch
__device__ __half h_xn1[S_ * H_];
__device__ __half h_xn2[S_ * H_];
__device__ __half h_qr [NH_ * S_ * HD_];
__device__ __half h_kr [KVH_ * S_ * HD_];
__device__ __half h_vt [KVH_ * HD_ * S_];
__device__ __half h_sc [(long)NH_ * S_ * S_];
__device__ __half h_ao [S_ * H_];
__device__ __half h_buf[(long)E_ * CAP_ * H_];
__device__ __half h_gga[(long)E_ * CAP_ * ID_];
__device__ __half h_uua[(long)E_ * CAP_ * ID_];
__device__ __half h_gg [(long)E_ * CAP_ * ID_];
__device__ __half h_yy [(long)E_ * CAP_ * H_];
__device__ __half h_sga[S_ * ID_];
__device__ __half h_sua[S_ * ID_];
__device__ __half h_sg [S_ * ID_];

// ---------- helpers ----------
__device__ __forceinline__ uint32_t smem_u32(const void* p) {
    uint32_t a;
    asm("{ .reg .u64 t; cvta.to.shared.u64 t, %1; cvt.u32.u64 %0, t; }" : "=r"(a) : "l"(p));
    return a;
}
__device__ __forceinline__ uint32_t cvt2h(float lo, float hi) {
    __half2 h = __floats2half2_rn(lo, hi);
    return *reinterpret_cast<uint32_t*>(&h);
}
__device__ __forceinline__ void cp16(uint32_t dst, const void* src) {
    asm volatile("cp.async.cg.shared.global [%0], [%1], 16;" :: "r"(dst), "l"(src));
}
__device__ __forceinline__ void cp_commit() { asm volatile("cp.async.commit_group;" ::: "memory"); }
__device__ __forceinline__ void cp_wait(int n) {
    if (n <= 0)      asm volatile("cp.async.wait_group 0;" ::: "memory");
    else if (n == 1) asm volatile("cp.async.wait_group 1;" ::: "memory");
    else if (n == 2) asm volatile("cp.async.wait_group 2;" ::: "memory");
    else             asm volatile("cp.async.wait_group 3;" ::: "memory");
}
__device__ __forceinline__ void ldm_x4(uint32_t* r, uint32_t a) {
    asm volatile("ldmatrix.sync.aligned.m8n8.x4.shared.b16 {%0,%1,%2,%3}, [%4];"
        : "=r"(r[0]), "=r"(r[1]), "=r"(r[2]), "=r"(r[3]) : "r"(a));
}
__device__ __forceinline__ void mma16816(float* d, const uint32_t* a, const uint32_t* b) {
    asm volatile("mma.sync.aligned.m16n8k16.row.col.f32.f16.f16.f32 "
        "{%0,%1,%2,%3}, {%4,%5,%6,%7}, {%8,%9}, {%0,%1,%2,%3};"
        : "+f"(d[0]), "+f"(d[1]), "+f"(d[2]), "+f"(d[3])
        : "r"(a[0]), "r"(a[1]), "r"(a[2]), "r"(a[3]), "r"(b[0]), "r"(b[1]));
}

// ---------- fp16 GEMM ----------
// A half (ldmatrix); B fp32 [K,N] (weights, cvt in-reg) or half [N,K] (ldmatrix).
// C fp32 or half (CHALF; ldc/sC in halves).
template<int BN, int NST, bool BHALF, bool CHALF>
__global__ void __launch_bounds__(256, 2) hgemm_k(
    const __half* __restrict__ A, const void* __restrict__ Bv, void* __restrict__ Cv,
    int K, int lda, int ldb, int ldc, long sA, long sB, long sC, int bDiv,
    const int* __restrict__ cnt)
{
    constexpr int BM = 128, BK = 32;
    constexpr int LDA  = 40;                    // halves
    constexpr int LDBF = BN + 4;                // floats (weight tile)
    constexpr int A_BY = BM * LDA * 2;
    constexpr int B_BY = BHALF ? BN * 40 * 2 : BK * LDBF * 4;
    constexpr int STG_BY = A_BY + B_BY;
    constexpr int WGN = BN / 32, WGM = 8 / WGN;
    constexpr int WM  = BM / WGM, MT = WM / 16, NT = 4;

    const int row0 = blockIdx.y * BM;
    if (cnt != nullptr && row0 >= cnt[blockIdx.z]) return;

    extern __shared__ char sm[];
    const uint32_t smb = smem_u32(sm);
    const int tid = threadIdx.x, wid = tid >> 5, lane = tid & 31;
    const int qrw = lane >> 2, qc = lane & 3;
    A += (long)blockIdx.z * sA;
    const __half* Bh = BHALF ? (const __half*)Bv + (long)(blockIdx.z / bDiv) * sB : nullptr;
    const float*  Bf = BHALF ? nullptr : (const float*)Bv + (long)(blockIdx.z / bDiv) * sB;
    const int col0 = blockIdx.x * BN;
    const int wm0 = (wid / WGN) * WM;
    const int wn0 = (wid % WGN) * 32;
    const int nch = K / BK;
    // ldmatrix per-thread byte offsets
    const uint32_t aoff = ((wm0 + (lane & 15)) * LDA + ((lane >> 4) << 3)) * 2;
    const uint32_t boff = ((wn0 + ((lane >> 4) << 3) + (lane & 7)) * 40
                           + (((lane >> 3) & 1) << 3)) * 2;

    auto fill = [&](int c) {
        char* Ss = sm + (c % NST) * STG_BY;
        __half* As = (__half*)Ss;
        const int k0 = c * BK;
        const __half* Ag = A + (long)row0 * lda + k0;
        #pragma unroll
        for (int i = 0; i < 2; i++) {
            int idx = i * 256 + tid;
            int r = idx >> 2, sg = idx & 3;
            cp16(smem_u32(As + r * LDA + sg * 8), Ag + (long)r * lda + sg * 8);
        }
        if (BHALF) {
            __half* Bs = (__half*)(Ss + A_BY);
            const __half* Bg = Bh + (long)col0 * ldb + k0;
            #pragma unroll
            for (int i = 0; i < BN / 64; i++) {
                int idx = i * 256 + tid;
                int r = idx >> 2, sg = idx & 3;
                cp16(smem_u32(Bs + r * 40 + sg * 8), Bg + (long)r * ldb + sg * 8);
            }
        } else {
            float* Bs = (float*)(Ss + A_BY);
            const float* Bg = Bf + (long)k0 * ldb + col0;
            #pragma unroll
            for (int i = 0; i < BN / 32; i++) {
                int idx = i * 256 + tid;
                int r = idx / (BN / 4), sg = idx % (BN / 4);
                cp16(smem_u32(Bs + r * LDBF + sg * 4), Bg + (long)r * ldb + sg * 4);
            }
        }
        cp_commit();
    };

    float acc[MT][NT][4];
    #pragma unroll
    for (int m = 0; m < MT; m++)
        #pragma unroll
        for (int n = 0; n < NT; n++)
            #pragma unroll
            for (int j = 0; j < 4; j++) acc[m][n][j] = 0.f;

    const int PF = NST - 1;
    const int F0 = (nch < PF) ? nch : PF;
    for (int c = 0; c < F0; c++) fill(c);
    int g = F0;

    for (int c = 0; c < nch; c++) {
        cp_wait(g - (c + 1));
        __syncthreads();
        if (c + PF < nch) { fill(c + PF); g++; }

        const uint32_t As_u = smb + (c % NST) * STG_BY;
        const uint32_t Bs_u = As_u + A_BY;
        #pragma unroll
        for (int ks = 0; ks < 2; ks++) {
            const int kk = ks * 16;
            uint32_t af[MT][4], bf[NT][2];
            #pragma unroll
            for (int mt = 0; mt < MT; mt++)
                ldm_x4(af[mt], As_u + aoff + (mt * 16 * LDA + kk) * 2);
            if (BHALF) {
                uint32_t t0[4], t1[4];
                ldm_x4(t0, Bs_u + boff + kk * 2);
                ldm_x4(t1, Bs_u + boff + (16 * 40 + kk) * 2);
                bf[0][0] = t0[0]; bf[0][1] = t0[1];
                bf[1][0] = t0[2]; bf[1][1] = t0[3];
                bf[2][0] = t1[0]; bf[2][1] = t1[1];
                bf[3][0] = t1[2]; bf[3][1] = t1[3];
            } else {
                const float* Bsf = (const float*)(sm + (c % NST) * STG_BY + A_BY);
                #pragma unroll
                for (int nt = 0; nt < NT; nt++) {
                    const float* bp = Bsf + (kk + 2 * qc) * LDBF + wn0 + nt * 8 + qrw;
                    bf[nt][0] = cvt2h(bp[0], bp[LDBF]);
                    bf[nt][1] = cvt2h(bp[8 * LDBF], bp[9 * LDBF]);
                }
            }
            #pragma unroll
            for (int mt = 0; mt < MT; mt++)
                #pragma unroll
                for (int nt = 0; nt < NT; nt++)
                    mma16816(acc[mt][nt], af[mt], bf[nt]);
        }
    }

    if (CHALF) {
        __half* Ch = (__half*)Cv + (long)blockIdx.z * sC;
        #pragma unroll
        for (int mt = 0; mt < MT; mt++) {
            const int r = row0 + wm0 + mt * 16 + qrw;
            #pragma unroll
            for (int nt = 0; nt < NT; nt++) {
                const int cc = col0 + wn0 + nt * 8 + qc * 2;
                *reinterpret_cast<uint32_t*>(Ch + (long)r * ldc + cc)
                    = cvt2h(acc[mt][nt][0], acc[mt][nt][1]);
                *reinterpret_cast<uint32_t*>(Ch + (long)(r + 8) * ldc + cc)
                    = cvt2h(acc[mt][nt][2], acc[mt][nt][3]);
            }
        }
    } else {
        float* Cf = (float*)Cv + (long)blockIdx.z * sC;
        #pragma unroll
        for (int mt = 0; mt < MT; mt++) {
            const int r = row0 + wm0 + mt * 16 + qrw;
            #pragma unroll
            for (int nt = 0; nt < NT; nt++) {
                const int cc = col0 + wn0 + nt * 8 + qc * 2;
                *reinterpret_cast<float2*>(Cf + (long)r * ldc + cc) =
                    make_float2(acc[mt][nt][0], acc[mt][nt][1]);
                *reinterpret_cast<float2*>(Cf + (long)(r + 8) * ldc + cc) =
                    make_float2(acc[mt][nt][2], acc[mt][nt][3]);
            }
        }
    }
}

// ---------- exact fp32 gemm for gate logits ----------
__global__ void sgemm64_k(const float* __restrict__ A, const float* __restrict__ B,
                          float* __restrict__ C, int M, int N, int K)
{
    const int tid = threadIdx.x;
    const int row0 = blockIdx.y * 64, col0 = blockIdx.x * 64;
    __shared__ float As[16][68];
    __shared__ float Bs[16][68];
    float acc[4][4] = {};
    const int tRow = (tid / 16) * 4, tCol = (tid % 16) * 4;
    const int aRow = tid / 4, aK = (tid % 4) * 4;
    const int bR = tid / 16, bC = (tid % 16) * 4;
    for (int k0 = 0; k0 < K; k0 += 16) {
        {
            int gr = row0 + aRow, gk = k0 + aK;
            float4 v = make_float4(0,0,0,0);
            if (gr < M && gk + 3 < K) v = *reinterpret_cast<const float4*>(A + (long)gr*K + gk);
            As[aK+0][aRow]=v.x; As[aK+1][aRow]=v.y; As[aK+2][aRow]=v.z; As[aK+3][aRow]=v.w;
        }
        {
            int gk = k0 + bR, gn = col0 + bC;
            float4 v = make_float4(0,0,0,0);
            if (gk < K && gn + 3 < N) v = *reinterpret_cast<const float4*>(B + (long)gk*N + gn);
            *reinterpret_cast<float4*>(&Bs[bR][bC]) = v;
        }
        __syncthreads();
        #pragma unroll
        for (int k = 0; k < 16; k++) {
            float rA[4], rB[4];
            #pragma unroll
            for (int m = 0; m < 4; m++) rA[m] = As[k][tRow+m];
            #pragma unroll
            for (int n = 0; n < 4; n++) rB[n] = Bs[k][tCol+n];
            #pragma unroll
            for (int m = 0; m < 4; m++)
                #pragma unroll
                for (int n = 0; n < 4; n++) acc[m][n] += rA[m]*rB[n];
        }
        __syncthreads();
    }
    #pragma unroll
    for (int m = 0; m < 4; m++) {
        int gr = row0 + tRow + m;
        if (gr >= M) continue;
        #pragma unroll
        for (int n = 0; n < 4; n++) {
            int gc = col0 + tCol + n;
            if (gc < N) C[(long)gr*N + gc] = acc[m][n];
        }
    }
}

// ---------- reductions ----------
__device__ __forceinline__ float warpSum(float v) {
    #pragma unroll
    for (int o = 16; o; o >>= 1) v += __shfl_xor_sync(0xffffffffu, v, o);
    return v;
}
__device__ __forceinline__ float warpMax(float v) {
    #pragma unroll
    for (int o = 16; o; o >>= 1) v = fmaxf(v, __shfl_xor_sync(0xffffffffu, v, o));
    return v;
}
__device__ float blockSum(float v) {
    __shared__ float sh[32]; __shared__ float tot;
    int lane = threadIdx.x & 31, wid = threadIdx.x >> 5;
    v = warpSum(v);
    if (lane == 0) sh[wid] = v;
    __syncthreads();
    int nw = (blockDim.x + 31) >> 5;
    float w = (threadIdx.x < nw) ? sh[threadIdx.x] : 0.f;
    if (wid == 0) { w = warpSum(w); if (lane == 0) tot = w; }
    __syncthreads();
    float r = tot; __syncthreads(); return r;
}
__device__ float blockMax(float v) {
    __shared__ float sh[32]; __shared__ float tot;
    int lane = threadIdx.x & 31, wid = threadIdx.x >> 5;
    v = warpMax(v);
    if (lane == 0) sh[wid] = v;
    __syncthreads();
    int nw = (blockDim.x + 31) >> 5;
    float w = (threadIdx.x < nw) ? sh[threadIdx.x] : -1e30f;
    if (wid == 0) { w = warpMax(w); if (lane == 0) tot = w; }
    __syncthreads();
    float r = tot; __syncthreads(); return r;
}

// ---------- small kernels ----------
__global__ void anchor_k(int* p) { if (threadIdx.x == 0) *p = 0; }

__global__ void concat_qkv_w(const float* __restrict__ Wq, const float* __restrict__ Wk,
                             const float* __restrict__ Wv, float* __restrict__ W)
{
    int idx = blockIdx.x * blockDim.x + threadIdx.x;
    if (idx >= H_ * QKVN_) return;
    int r = idx / QKVN_, c = idx % QKVN_;
    float v;
    if (c < H_)                 v = Wq[(long)r * H_ + c];
    else if (c < H_ + KVH_*HD_) v = Wk[(long)r * (KVH_*HD_) + (c - H_)];
    else                        v = Wv[(long)r * (KVH_*HD_) + (c - H_ - KVH_*HD_)];
    W[idx] = v;
}

__global__ void rmsnorm_k(const float* __restrict__ x, const float* __restrict__ w,
                          float* __restrict__ y, __half* __restrict__ yh)
{
    int t = blockIdx.x;
    const float* xr = x + (long)t * H_;
    float s = 0.f;
    for (int i = threadIdx.x; i < H_; i += blockDim.x) { float v = xr[i]; s += v * v; }
    s = blockSum(s);
    float inv = rsqrtf(s / (float)H_ + EPS_);
    for (int i = threadIdx.x; i < H_; i += blockDim.x) {
        float v = xr[i] * inv * w[i];
        if (y)  y[(long)t * H_ + i] = v;
        yh[(long)t * H_ + i] = __float2half_rn(v);
    }
}

__global__ void ropeall_k(const float* __restrict__ qkv, __half* __restrict__ hqr,
                          __half* __restrict__ hkr, __half* __restrict__ hvt)
{
    int idx = blockIdx.x * blockDim.x + threadIdx.x;
    if (idx >= 24 * S_ * HD_) return;
    int g = idx / (S_ * HD_);
    int rem = idx - g * (S_ * HD_);
    if (g < 20) {
        int d = rem % HD_, s = rem / HD_;
        int h, off; __half* dst;
        if (g < 16) { h = g;      off = 0;  dst = hqr; }
        else        { h = g - 16; off = H_; dst = hkr; }
        const float* p = qkv + (long)s * QKVN_ + off + h * HD_;
        float v  = p[d];
        float pr = (d < 32) ? -p[d + 32] : p[d - 32];
        int i = d & 31;
        float inv = expf(-(float)i * (9.210340371976184f / 32.f));
        float ang = (float)s * inv, sn, cs;
        sincosf(ang, &sn, &cs);
        dst[((long)h * S_ + s) * HD_ + d] = __float2half_rn(v * cs + pr * sn);
    } else {
        int h = g - 20;
        int s = rem % S_, d = rem / S_;
        hvt[((long)h * HD_ + d) * S_ + s] =
            __float2half_rn(qkv[(long)s * QKVN_ + H_ + KVH_*HD_ + h * HD_ + d]);
    }
}

__global__ void softmax_k(const float* __restrict__ sc, const float* __restrict__ mask,
                          __half* __restrict__ pr)
{
    int r = blockIdx.x, h = blockIdx.y;
    const float4* row = reinterpret_cast<const float4*>(sc + ((long)h * S_ + r) * S_);
    const float4* mr = reinterpret_cast<const float4*>(mask + (long)r * S_);
    int j = threadIdx.x;
    float4 v = row[j], m = mr[j];
    v.x = v.x * 0.125f + m.x;
    v.y = v.y * 0.125f + m.y;
    v.z = v.z * 0.125f + m.z;
    v.w = v.w * 0.125f + m.w;
    float mx = fmaxf(fmaxf(v.x, v.y), fmaxf(v.z, v.w));
    mx = blockMax(mx);
    v.x = expf(v.x - mx); v.y = expf(v.y - mx);
    v.z = expf(v.z - mx); v.w = expf(v.w - mx);
    float sum = v.x + v.y + v.z + v.w;
    sum = blockSum(sum);
    float inv = 1.f / sum;
    uint2 pk = make_uint2(cvt2h(v.x * inv, v.y * inv), cvt2h(v.z * inv, v.w * inv));
    reinterpret_cast<uint2*>(pr + ((long)h * S_ + r) * S_)[j] = pk;
}

__global__ void add_k(const float* __restrict__ a, const float* __restrict__ b,
                      float* __restrict__ c, long n)
{
    long i = (long)blockIdx.x * blockDim.x + threadIdx.x;
    if (i < n) c[i] = a[i] + b[i];
}

__global__ void topk_k(const float* __restrict__ logits, int* __restrict__ topi,
                       float* __restrict__ coef)
{
    int t = (blockIdx.x * blockDim.x + threadIdx.x) >> 5;
    int lane = threadIdx.x & 31;
    if (t >= S_) return;
    const float* lr = logits + (long)t * E_;
    float v0 = lr[lane], v1 = lr[lane + 32];
    unsigned long long sel = 0ull;
    float tv[TOPK_]; int ti[TOPK_];
    #pragma unroll
    for (int k = 0; k < TOPK_; k++) {
        float c0 = ((sel >> lane) & 1ull) ? -1e30f : v0;
        float c1 = ((sel >> (lane + 32)) & 1ull) ? -1e30f : v1;
        float bv; int be;
        if (c0 >= c1) { bv = c0; be = lane; } else { bv = c1; be = lane + 32; }
        #pragma unroll
        for (int o = 16; o; o >>= 1) {
            float ov = __shfl_xor_sync(0xffffffffu, bv, o);
            int   oe = __shfl_xor_sync(0xffffffffu, be, o);
            if (ov > bv || (ov == bv && oe < be)) { bv = ov; be = oe; }
        }
        sel |= 1ull << be;
        tv[k] = bv; ti[k] = be;
    }
    if (lane == 0) {
        float mx = tv[0], ex[TOPK_], sum = 0.f;
        #pragma unroll
        for (int k = 0; k < TOPK_; k++) { ex[k] = expf(tv[k] - mx); sum += ex[k]; }
        float inv = 1.f / sum;
        #pragma unroll
        for (int k = 0; k < TOPK_; k++) { topi[t*TOPK_+k] = ti[k]; coef[t*TOPK_+k] = ex[k]*inv; }
    }
}

__global__ void assign_k(const int* __restrict__ topi, int* __restrict__ pos,
                         int* __restrict__ cnt)
{
    const int e = blockIdx.x;
    __shared__ int sw[8];
    __shared__ int stot;
    int lane = threadIdx.x & 31, wid = threadIdx.x >> 5;
    int base = 0;
    for (int chunk = 0; chunk < S_ * TOPK_; chunk += 256) {
        int i = chunk + threadIdx.x;
        int p = (topi[i] == e) ? 1 : 0;
        unsigned mask = __ballot_sync(0xffffffffu, p);
        int prefix = __popc(mask & ((1u << lane) - 1u));
        if (lane == 0) sw[wid] = __popc(mask);
        __syncthreads();
        if (threadIdx.x < 8) {
            int c = sw[threadIdx.x];
            int x = c;
            #pragma unroll
            for (int o = 1; o < 8; o <<= 1) {
                int y = __shfl_up_sync(0xffu, x, o);
                if ((int)threadIdx.x >= o) x += y;
            }
            sw[threadIdx.x] = x - c;
            if (threadIdx.x == 7) stot = x;
        }
        __syncthreads();
        if (p) pos[i] = base + sw[wid] + prefix;
        base += stot;
        __syncthreads();
    }
    if (threadIdx.x == 0) cnt[e] = (base < CAP_) ? base : CAP_;
}

__global__ void scatter_k(const __half* __restrict__ hxn2, const int* __restrict__ topi,
                          const int* __restrict__ pos, __half* __restrict__ buf)
{
    int i = blockIdx.x;
    int p = pos[i];
    if (p >= CAP_) return;
    int e = topi[i];
    int t = i >> 3;
    const uint2* src = reinterpret_cast<const uint2*>(hxn2 + (long)t * H_);
    uint2* dst = reinterpret_cast<uint2*>(buf + ((long)e * CAP_ + p) * H_);
    dst[threadIdx.x] = src[threadIdx.x];
}

// half in/out expert activation
__global__ void act_expert_k(const __half* __restrict__ ga, const __half* __restrict__ ua,
                             __half* __restrict__ o, const int* __restrict__ cnt)
{
    int e = blockIdx.x >> 8, c = blockIdx.x & 255;
    if (c >= cnt[e]) return;
    long base = ((long)e * CAP_ + c) * ID_;
    const __half2* g2 = reinterpret_cast<const __half2*>(ga + base);
    const __half2* u2 = reinterpret_cast<const __half2*>(ua + base);
    __half2* o2 = reinterpret_cast<__half2*>(o + base);
    for (int j = threadIdx.x; j < ID_ / 2; j += blockDim.x) {
        float2 g = __half22float2(g2[j]);
        float2 u = __half22float2(u2[j]);
        float a = (g.x / (1.f + expf(-g.x))) * u.x;
        float b = (g.y / (1.f + expf(-g.y))) * u.y;
        o2[j] = __floats2half2_rn(a, b);
    }
}

__global__ void act_h_k(const __half* __restrict__ ga, const __half* __restrict__ ua,
                        __half* __restrict__ o, long n2)
{
    long i = (long)blockIdx.x * blockDim.x + threadIdx.x;
    if (i < n2) {
        float2 g = __half22float2(reinterpret_cast<const __half2*>(ga)[i]);
        float2 u = __half22float2(reinterpret_cast<const __half2*>(ua)[i]);
        float a = (g.x / (1.f + expf(-g.x))) * u.x;
        float b = (g.y / (1.f + expf(-g.y))) * u.y;
        reinterpret_cast<__half2*>(o)[i] = __floats2half2_rn(a, b);
    }
}

__global__ void final_k(const float* __restrict__ hres, const float* __restrict__ shb,
                        const __half* __restrict__ yy, const int* __restrict__ topi,
                        const int* __restrict__ pos, const float* __restrict__ coef,
                        float* __restrict__ out)
{
    int t = blockIdx.x, j = threadIdx.x;
    float4 a = reinterpret_cast<const float4*>(hres)[(long)t*256 + j];
    float4 b = reinterpret_cast<const float4*>(shb)[(long)t*256 + j];
    a.x += b.x; a.y += b.y; a.z += b.z; a.w += b.w;
    #pragma unroll
    for (int k = 0; k < TOPK_; k++) {
        int idx = t * TOPK_ + k;
        int p = pos[idx];
        if (p < CAP_) {
            float c = coef[idx];
            uint2 pk = reinterpret_cast<const uint2*>(yy + ((long)topi[idx]*CAP_ + p)*H_)[j];
            float2 f0 = __half22float2(*reinterpret_cast<__half2*>(&pk.x));
            float2 f1 = __half22float2(*reinterpret_cast<__half2*>(&pk.y));
            a.x += c*f0.x; a.y += c*f0.y; a.z += c*f1.x; a.w += c*f1.y;
        }
    }
    reinterpret_cast<float4*>(out)[(long)t*256 + j] = a;
}

// ---------- host-side smem size ----------
static int smemB(int BN, int NST, bool bhalf) {
    int A_BY = 128 * 40 * 2;
    int B_BY = bhalf ? BN * 40 * 2 : 32 * (BN + 4) * 4;
    return NST * (A_BY + B_BY);
}

extern "C" void kernel_launch(void* const* d_in, const int* in_sizes, int n_in,
                              void* d_out, int out_size)
{
    (void)in_sizes; (void)n_in; (void)out_size;
    cudaStream_t st = 0;

    const int SM_W   = smemB(128, 4, false);
    const int SM_SCR = smemB(128, 2, true);
    const int SM_PV  = smemB(64,  4, true);
    cudaFuncSetAttribute(hgemm_k<128, 4, false, false>, cudaFuncAttributeMaxDynamicSharedMemorySize, SM_W);
    cudaFuncSetAttribute(hgemm_k<128, 4, false, true >, cudaFuncAttributeMaxDynamicSharedMemorySize, SM_W);
    cudaFuncSetAttribute(hgemm_k<128, 2, true,  false>, cudaFuncAttributeMaxDynamicSharedMemorySize, SM_SCR);
    cudaFuncSetAttribute(hgemm_k<64,  4, true,  true >, cudaFuncAttributeMaxDynamicSharedMemorySize, SM_PV);

    const float* x     = (const float*)d_in[0];
    const float* mask  = (const float*)d_in[1];
    const float* wln1  = (const float*)d_in[2];
    const float* wln2  = (const float*)d_in[3];
    const float* Wq    = (const float*)d_in[4];
    const float* Wk    = (const float*)d_in[5];
    const float* Wv    = (const float*)d_in[6];
    const float* Wo    = (const float*)d_in[7];
    const float* Wgate = (const float*)d_in[8];
    const float* Weg   = (const float*)d_in[9];
    const float* Weu   = (const float*)d_in[10];
    const float* Wed   = (const float*)d_in[11];
    const float* Wsg   = (const float*)d_in[12];
    const float* Wsu   = (const float*)d_in[13];
    const float* Wsd   = (const float*)d_in[14];
    float* out = (float*)d_out;

    void *p;
    #define GETF(sym, var) cudaGetSymbolAddress(&p, sym); float* var = (float*)p;
    #define GETH(sym, var) cudaGetSymbolAddress(&p, sym); __half* var = (__half*)p;
    #define GETI(sym, var) cudaGetSymbolAddress(&p, sym); int* var = (int*)p;
    GETF(g_xn1, xn1)  GETF(g_wqkv, wqkv) GETF(g_qkv, qkv)  GETF(g_sc, sc)
    GETF(g_hres, hres) GETF(g_xn2, xn2)  GETF(g_logits, logits)
    GETF(g_coef, coef) GETF(g_shb, shb)
    GETH(h_xn1, hxn1) GETH(h_xn2, hxn2)  GETH(h_qr, hqr)   GETH(h_kr, hkr)
    GETH(h_vt, hvt)   GETH(h_sc, hsc)    GETH(h_ao, hao)   GETH(h_buf, hbuf)
    GETH(h_gga, hgga) GETH(h_uua, huua)  GETH(h_gg, hgg)   GETH(h_yy, hyy)
    GETH(h_sga, hsga) GETH(h_sua, hsua)  GETH(h_sg, hsg)
    GETI(g_topi, topi) GETI(g_pos, pos)  GETI(g_cnt, cnt)  GETI(g_dummyi, dmy)
    #undef GETF
    #undef GETH
    #undef GETI

    auto gw = [&](const __half* A, const float* B, float* C, int M, int N, int K,
                  int lda, int ldb, int ldc, long sA, long sB, long sC, int bDiv,
                  int batch, const int* cc) {
        dim3 grid(N / 128, M / 128, batch);
        hgemm_k<128, 4, false, false><<<grid, 256, SM_W, st>>>(
            A, B, C, K, lda, ldb, ldc, sA, sB, sC, bDiv, cc);
    };
    auto gwh = [&](const __half* A, const float* B, __half* C, int M, int N, int K,
                   int lda, int ldb, int ldc, long sA, long sB, long sC, int bDiv,
                   int batch, const int* cc) {
        dim3 grid(N / 128, M / 128, batch);
        hgemm_k<128, 4, false, true><<<grid, 256, SM_W, st>>>(
            A, B, C, K, lda, ldb, ldc, sA, sB, sC, bDiv, cc);
    };

    // ===== attention =====
    rmsnorm_k<<<S_, 256, 0, st>>>(x, wln1, nullptr, hxn1);                       // idx 0
    concat_qkv_w<<<(H_ * QKVN_ + 255)/256, 256, 0, st>>>(Wq, Wk, Wv, wqkv);      // idx 1
    anchor_k<<<1, 32, 0, st>>>(dmy);                                             // idx 2
    gw(hxn1, wqkv, qkv, S_, QKVN_, H_, H_, QKVN_, QKVN_, 0,0,0, 1, 1, nullptr);  // idx 3 (ncu)

    ropeall_k<<<(24*S_*HD_ + 255)/256, 256, 0, st>>>(qkv, hqr, hkr, hvt);

    {
        dim3 grid(S_/128, S_/128, NH_);
        hgemm_k<128, 2, true, false><<<grid, 256, SM_SCR, st>>>(
            hqr, hkr, sc, HD_, HD_, HD_, S_,
            (long)S_*HD_, (long)S_*HD_, (long)S_*S_, REP_, nullptr);
    }

    softmax_k<<<dim3(S_, NH_), 256, 0, st>>>(sc, mask, hsc);

    {
        dim3 grid(1, S_/128, NH_);
        hgemm_k<64, 4, true, true><<<grid, 256, SM_PV, st>>>(
            hsc, hvt, hao, S_, S_, S_, H_,
            (long)S_*S_, (long)HD_*S_, 64L, REP_, nullptr);
    }

    gw(hao, Wo, xn1, S_, H_, H_, H_, H_, H_, 0,0,0, 1, 1, nullptr);
    add_k<<<(S_*H_ + 255)/256, 256, 0, st>>>(x, xn1, hres, (long)S_*H_);

    // ===== MoE =====
    rmsnorm_k<<<S_, 256, 0, st>>>(hres, wln2, xn2, hxn2);

    sgemm64_k<<<dim3(1, S_/64), 256, 0, st>>>(xn2, Wgate, logits, S_, E_, H_);
    topk_k<<<(S_*32 + 255)/256, 256, 0, st>>>(logits, topi, coef);
    assign_k<<<E_, 256, 0, st>>>(topi, pos, cnt);

    scatter_k<<<S_*TOPK_, 256, 0, st>>>(hxn2, topi, pos, hbuf);

    gwh(hbuf, Weg, hgga, CAP_, ID_, H_, H_, ID_, ID_,
        (long)CAP_*H_, (long)H_*ID_, (long)CAP_*ID_, 1, E_, cnt);
    gwh(hbuf, Weu, huua, CAP_, ID_, H_, H_, ID_, ID_,
        (long)CAP_*H_, (long)H_*ID_, (long)CAP_*ID_, 1, E_, cnt);

    act_expert_k<<<E_ * CAP_, 256, 0, st>>>(hgga, huua, hgg, cnt);

    gwh(hgg, Wed, hyy, CAP_, H_, ID_, ID_, H_, H_,
        (long)CAP_*ID_, (long)ID_*H_, (long)CAP_*H_, 1, E_, cnt);

    // shared expert
    gwh(hxn2, Wsg, hsga, S_, ID_, H_, H_, ID_, ID_, 0,0,0, 1, 1, nullptr);
    gwh(hxn2, Wsu, hsua, S_, ID_, H_, H_, ID_, ID_, 0,0,0, 1, 1, nullptr);
    act_h_k<<<(int)(((long)S_*ID_/2 + 255)/256), 256, 0, st>>>(hsga, hsua, hsg, (long)S_*ID_/2);
    gw(hsg, Wsd, shb, S_, H_, ID_, ID_, H_, H_, 0,0,0, 1, 1, nullptr);

    final_k<<<S_, 256, 0, st>>>(hres, shb, hyy, topi, pos, coef, out);
}